// round 12
// baseline (speedup 1.0000x reference)
#include <cuda_runtime.h>
#include <cuda_bf16.h>
#include <cstdint>

#define NN (1024u*1024u)

// scratch (device globals: allocation-free)
__device__ float g_bias[16u*1024u*1024u]; // [h][i][j]
__device__ float g_g [NN];                // gates fp32 [token][dim_inner]
__device__ __nv_bfloat16 g_shi[NN], g_slo[NN];      // single_repr hi/lo [m][k]
__device__ __nv_bfloat16 g_wh[5][NN], g_wl[5][NN];  // W [k][n] hi/lo (natural)
__device__ __nv_bfloat16 g_ohi[NN], g_olo[NN];      // gated attn out hi/lo
__device__ __nv_bfloat16 g_qh[NN], g_ql[NN];        // Q [tok][d_inner] *0.125
__device__ __nv_bfloat16 g_kh[NN], g_kl[NN];        // K [tok][d_inner]
__device__ __nv_bfloat16 g_vh[NN], g_vl[NN];        // V [tok][d_inner]
__device__ __nv_bfloat16 g_wbth[16*128], g_wbtl[16*128]; // (gamma*Wb)^T [h][p]
__device__ float g_binit[16];                            // beta @ Wb

__device__ __forceinline__ unsigned pk2(float a, float b) {
    __nv_bfloat162 t = __floats2bfloat162_rn(a, b);
    return *reinterpret_cast<unsigned*>(&t);
}
__device__ __forceinline__ float lores(float a) {
    return a - __bfloat162float(__float2bfloat16(a));
}
__device__ __forceinline__ unsigned cvta_s(const void* p) {
    return (unsigned)__cvta_generic_to_shared(p);
}

#define MMA_BF16v(c, a, b0, b1) asm volatile( \
    "mma.sync.aligned.m16n8k16.row.col.f32.bf16.bf16.f32 " \
    "{%0,%1,%2,%3},{%4,%5,%6,%7},{%8,%9},{%0,%1,%2,%3};" \
    : "+f"((c)[0]), "+f"((c)[1]), "+f"((c)[2]), "+f"((c)[3]) \
    : "r"((a)[0]), "r"((a)[1]), "r"((a)[2]), "r"((a)[3]), \
      "r"(b0), "r"(b1))
#define LDSM4(R, addr) asm volatile( \
    "ldmatrix.sync.aligned.m8n8.x4.shared.b16 {%0,%1,%2,%3}, [%4];" \
    : "=r"((R)[0]), "=r"((R)[1]), "=r"((R)[2]), "=r"((R)[3]) : "r"(addr))
#define LDSM4T(R, addr) asm volatile( \
    "ldmatrix.sync.aligned.m8n8.x4.trans.shared.b16 {%0,%1,%2,%3}, [%4];" \
    : "=r"((R)[0]), "=r"((R)[1]), "=r"((R)[2]), "=r"((R)[3]) : "r"(addr))
#define CP_ASYNC16(dst, src) asm volatile( \
    "cp.async.cg.shared.global [%0], [%1], 16;" :: "r"(dst), "l"(src) : "memory")
#define CP_COMMIT() asm volatile("cp.async.commit_group;" ::: "memory")
#define CP_WAIT1()  asm volatile("cp.async.wait_group 1;" ::: "memory")
#define CP_WAIT0()  asm volatile("cp.async.wait_group 0;" ::: "memory")

// ---------------------------------------------------------------------------
// One-time prep: (gamma*W_bias)^T as bf16 hi/lo, and beta@W_bias.
// ---------------------------------------------------------------------------
__global__ void bias_setup(const float* __restrict__ gamma,
                           const float* __restrict__ beta,
                           const float* __restrict__ Wb)
{
    int tid = threadIdx.x;
    for (int idx = tid; idx < 2048; idx += 128) {
        int p = idx >> 4, h = idx & 15;
        float w = gamma[p] * Wb[idx];
        __nv_bfloat16 hi = __float2bfloat16(w);
        g_wbth[h * 128 + p] = hi;
        g_wbtl[h * 128 + p] = __float2bfloat16(w - __bfloat162float(hi));
    }
    if (tid < 16) {
        float s = 0.f;
        for (int p = 0; p < 128; p++) s += beta[p] * Wb[p * 16 + tid];
        g_binit[tid] = s;
    }
}

// ---------------------------------------------------------------------------
// Bias kernel: LN (SIMT fp32 stats) + 128->16 projection on tensor cores.
// ---------------------------------------------------------------------------
__global__ __launch_bounds__(256) void bias_kernel(const float* __restrict__ pw)
{
    __shared__ __nv_bfloat16 sXh[64][136], sXl[64][136];
    __shared__ __nv_bfloat16 sWh[16][136], sWl[16][136];
    __shared__ float stage[16][64];
    __shared__ float sbin[16];

    int tid  = threadIdx.x;
    int lane = tid & 31, warp = tid >> 5;
    int i  = blockIdx.y;
    int j0 = blockIdx.x * 64;

    const float4* rowp = (const float4*)(pw
        + ((size_t)i * 1024 + j0 + warp * 8) * 128) + lane;
    float4 x[8];
#pragma unroll
    for (int rr = 0; rr < 8; rr++) x[rr] = rowp[rr * 32];

    for (int idx = tid; idx < 2048; idx += 256) {
        int h = idx >> 7, p = idx & 127;
        sWh[h][p] = g_wbth[idx];
        sWl[h][p] = g_wbtl[idx];
    }
    if (tid < 16) sbin[tid] = g_binit[tid];

#pragma unroll
    for (int rr = 0; rr < 8; rr++) {
        float s  = x[rr].x + x[rr].y + x[rr].z + x[rr].w;
        float ss = x[rr].x*x[rr].x + x[rr].y*x[rr].y
                 + x[rr].z*x[rr].z + x[rr].w*x[rr].w;
#pragma unroll
        for (int off = 16; off >= 1; off >>= 1) {
            s  += __shfl_xor_sync(0xffffffffu, s,  off);
            ss += __shfl_xor_sync(0xffffffffu, ss, off);
        }
        float mu  = s * 0.0078125f;
        float var = ss * 0.0078125f - mu * mu;
        float rs  = rsqrtf(var + 1e-5f);
        float y0 = (x[rr].x - mu) * rs, y1 = (x[rr].y - mu) * rs;
        float y2 = (x[rr].z - mu) * rs, y3 = (x[rr].w - mu) * rs;
        int r = warp * 8 + rr;
        *(uint2*)&sXh[r][lane * 4] = make_uint2(pk2(y0, y1), pk2(y2, y3));
        *(uint2*)&sXl[r][lane * 4] =
            make_uint2(pk2(lores(y0), lores(y1)), pk2(lores(y2), lores(y3)));
    }
    __syncthreads();

    if (warp < 4) {
        int gid  = lane >> 2, tg = lane & 3;
        float acc[2][4] = {};
        int warp_m = warp * 16;
        unsigned aXh = cvta_s(sXh), aXl = cvta_s(sXl);
        unsigned aWh = cvta_s(sWh), aWl = cvta_s(sWl);
        int fr = lane & 15, fc = lane >> 4;
#pragma unroll
        for (int c = 0; c < 8; c++) {
            int kk = c * 16;
            unsigned ah[4], al[4], bh[4], bl[4];
            LDSM4(ah, aXh + ((warp_m + fr) * 136 + kk + fc * 8) * 2);
            LDSM4(al, aXl + ((warp_m + fr) * 136 + kk + fc * 8) * 2);
            LDSM4(bh, aWh + ((fr) * 136 + kk + fc * 8) * 2);
            LDSM4(bl, aWl + ((fr) * 136 + kk + fc * 8) * 2);
            // pass-major: per-acc sequence unchanged (hh -> hl -> lh)
#pragma unroll
            for (int t = 0; t < 2; t++)
                MMA_BF16v(acc[t], ah, bh[t], bh[t + 2]);
#pragma unroll
            for (int t = 0; t < 2; t++)
                MMA_BF16v(acc[t], ah, bl[t], bl[t + 2]);
#pragma unroll
            for (int t = 0; t < 2; t++)
                MMA_BF16v(acc[t], al, bh[t], bh[t + 2]);
        }
#pragma unroll
        for (int t = 0; t < 2; t++) {
            int hc = t * 8 + tg * 2;
            int r  = warp_m + gid;
            stage[hc][r]         = acc[t][0];
            stage[hc + 1][r]     = acc[t][1];
            stage[hc][r + 8]     = acc[t][2];
            stage[hc + 1][r + 8] = acc[t][3];
        }
    }
    __syncthreads();
    size_t obase = (size_t)i * 1024 + j0;
    for (int e = tid; e < 1024; e += 256) {
        int hh = e >> 6, j = e & 63;
        g_bias[(size_t)hh * NN + obase + j] = stage[hh][j] + sbin[hh];
    }
}

// ---------------------------------------------------------------------------
// Convert single_repr + all 5 weights -> bf16 hi/lo.
// ---------------------------------------------------------------------------
__global__ __launch_bounds__(256) void conv_all(
    const float* __restrict__ s0, const float* __restrict__ s1,
    const float* __restrict__ s2, const float* __restrict__ s3,
    const float* __restrict__ s4, const float* __restrict__ s5)
{
    const float* srcs[6] = {s0, s1, s2, s3, s4, s5};
    const float* src = srcs[blockIdx.y];
    __nv_bfloat16 *Dh, *Dl;
    if (blockIdx.y == 0) { Dh = g_shi; Dl = g_slo; }
    else { Dh = g_wh[blockIdx.y - 1]; Dl = g_wl[blockIdx.y - 1]; }

    unsigned i = blockIdx.x * 256u + threadIdx.x;
    float4 v = ((const float4*)src)[i];
    *(unsigned*)(Dh + 4u*i)     = pk2(v.x, v.y);
    *(unsigned*)(Dh + 4u*i + 2) = pk2(v.z, v.w);
    *(unsigned*)(Dl + 4u*i)     = pk2(lores(v.x), lores(v.y));
    *(unsigned*)(Dl + 4u*i + 2) = pk2(lores(v.z), lores(v.w));
}

// ---------------------------------------------------------------------------
// QKVG GEMM: 512 thr, tile 128x256, BK=32, depth-3, pass-major MMA order.
// Grid (4, 8, 4) = 128 CTAs = one full wave.
// ---------------------------------------------------------------------------
__global__ __launch_bounds__(512, 1) void gemm_qkvg(const float* __restrict__ aux)
{
    extern __shared__ __nv_bfloat16 dsm[];
    constexpr unsigned SZB   = 16896u;   // 32 * 264 * 2
    constexpr unsigned BUFSZ = 54272u;

    int widx = blockIdx.z;
    float scale = (widx == 0) ? 0.125f : 1.0f;
    const __nv_bfloat16* gBh = g_wh[widx];
    const __nv_bfloat16* gBl = g_wl[widx];

    int tid  = threadIdx.x;
    int lane = tid & 31, warp = tid >> 5;
    int gid  = lane >> 2, tg = lane & 3;
    int fr = lane & 15, fc8 = (lane >> 4) * 8;
    int vr = (lane >> 4) * 8 + (lane & 7);
    int vc8 = ((lane >> 3) & 1) * 8;
    int warp_m = (warp >> 2) * 32, warp_n = (warp & 3) * 64;
    int m0 = blockIdx.y * 128, n0 = blockIdx.x * 256;
    unsigned sb = cvta_s(dsm);

    int a_row = (tid & 511) >> 2, a_seg = tid & 3;
    int b_row = (tid & 1023) >> 5, b_seg = tid & 31;

    const __nv_bfloat16* pAh = g_shi + (size_t)(m0 + a_row) * 1024 + a_seg * 8;
    const __nv_bfloat16* pAl = g_slo + (size_t)(m0 + a_row) * 1024 + a_seg * 8;
    const __nv_bfloat16* pBh0 = gBh + (size_t)b_row * 1024 + n0 + b_seg * 8;
    const __nv_bfloat16* pBl0 = gBl + (size_t)b_row * 1024 + n0 + b_seg * 8;
    const __nv_bfloat16* pBh1 = pBh0 + 16 * 1024;
    const __nv_bfloat16* pBl1 = pBl0 + 16 * 1024;
    unsigned dA  = a_row * 80u + a_seg * 16u;
    unsigned dB0 = 20480u + b_row * 528u + b_seg * 16u;
    unsigned dB1 = 20480u + (b_row + 16) * 528u + b_seg * 16u;

    auto issue = [&](int ch, int buf) {
        unsigned k0 = ch * 32u;
        size_t kq = ch * 32u * 1024u;
        unsigned bo = sb + buf * BUFSZ;
        CP_ASYNC16(bo + dA,           pAh + k0);
        CP_ASYNC16(bo + dA + 10240u,  pAl + k0);
        CP_ASYNC16(bo + dB0,          pBh0 + kq);
        CP_ASYNC16(bo + dB0 + SZB,    pBl0 + kq);
        CP_ASYNC16(bo + dB1,          pBh1 + kq);
        CP_ASYNC16(bo + dB1 + SZB,    pBl1 + kq);
        CP_COMMIT();
    };

    float acc[2][8][4];
#pragma unroll
    for (int a = 0; a < 2; a++)
#pragma unroll
        for (int b = 0; b < 8; b++)
#pragma unroll
            for (int q = 0; q < 4; q++) acc[a][b][q] = 0.f;

    issue(0, 0);
    issue(1, 1);

    int buf = 0;
#pragma unroll 1
    for (int ch = 0; ch < 32; ch++) {
        if (ch < 31) { CP_WAIT1(); } else { CP_WAIT0(); }
        __syncthreads();
        unsigned base = sb + buf * BUFSZ;
#pragma unroll
        for (int k16 = 0; k16 < 32; k16 += 16) {
            unsigned a_h[2][4], a_l[2][4], b_h[4][4], b_l[4][4];
#pragma unroll
            for (int mt = 0; mt < 2; mt++) {
                unsigned off = base + ((warp_m + mt * 16 + fr) * 40 + k16 + fc8) * 2;
                LDSM4(a_h[mt], off);
                LDSM4(a_l[mt], off + 10240u);
            }
#pragma unroll
            for (int tp = 0; tp < 4; tp++) {
                unsigned off = base + 20480u
                    + ((k16 + vr) * 264 + warp_n + tp * 16 + vc8) * 2;
                LDSM4T(b_h[tp], off);
                LDSM4T(b_l[tp], off + SZB);
            }
            // pass-major: 16 independent MMAs per pass; per-acc order hh->hl->lh
#pragma unroll
            for (int mt = 0; mt < 2; mt++)
#pragma unroll
                for (int tp = 0; tp < 4; tp++)
#pragma unroll
                    for (int u = 0; u < 2; u++)
                        MMA_BF16v(acc[mt][tp * 2 + u], a_h[mt],
                                  b_h[tp][u], b_h[tp][u + 2]);
#pragma unroll
            for (int mt = 0; mt < 2; mt++)
#pragma unroll
                for (int tp = 0; tp < 4; tp++)
#pragma unroll
                    for (int u = 0; u < 2; u++)
                        MMA_BF16v(acc[mt][tp * 2 + u], a_h[mt],
                                  b_l[tp][u], b_l[tp][u + 2]);
#pragma unroll
            for (int mt = 0; mt < 2; mt++)
#pragma unroll
                for (int tp = 0; tp < 4; tp++)
#pragma unroll
                    for (int u = 0; u < 2; u++)
                        MMA_BF16v(acc[mt][tp * 2 + u], a_l[mt],
                                  b_h[tp][u], b_h[tp][u + 2]);
        }
        if (ch + 2 < 32) {
            int nb = buf + 2; if (nb >= 3) nb -= 3;
            issue(ch + 2, nb);
        }
        if (++buf == 3) buf = 0;
    }

    __nv_bfloat16* Dh = (widx == 0) ? g_qh : (widx == 1) ? g_kh : g_vh;
    __nv_bfloat16* Dl = (widx == 0) ? g_ql : (widx == 1) ? g_kl : g_vl;
#pragma unroll
    for (int mt = 0; mt < 2; mt++) {
#pragma unroll
        for (int j = 0; j < 8; j++) {
            int rg = m0 + warp_m + mt * 16 + gid;
            int cg = n0 + warp_n + j * 8 + tg * 2;
            float* a4 = acc[mt][j];
            if (widx == 3) {
                float b0 = aux[cg], b1 = aux[cg + 1];
                float v0 = 1.f / (1.f + __expf(-(a4[0] + b0)));
                float v1 = 1.f / (1.f + __expf(-(a4[1] + b1)));
                float v2 = 1.f / (1.f + __expf(-(a4[2] + b0)));
                float v3 = 1.f / (1.f + __expf(-(a4[3] + b1)));
                *(float2*)&g_g[(size_t)rg * 1024 + cg]       = make_float2(v0, v1);
                *(float2*)&g_g[(size_t)(rg + 8) * 1024 + cg] = make_float2(v2, v3);
            } else {
                float v0 = a4[0] * scale, v1 = a4[1] * scale;
                float v2 = a4[2] * scale, v3 = a4[3] * scale;
                *(unsigned*)&Dh[(size_t)rg * 1024 + cg]       = pk2(v0, v1);
                *(unsigned*)&Dh[(size_t)(rg + 8) * 1024 + cg] = pk2(v2, v3);
                *(unsigned*)&Dl[(size_t)rg * 1024 + cg]       = pk2(lores(v0), lores(v1));
                *(unsigned*)&Dl[(size_t)(rg + 8) * 1024 + cg] =
                    pk2(lores(v2), lores(v3));
            }
        }
    }
}

// ---------------------------------------------------------------------------
// Output GEMM: 256 thr, tile 128x64, BK=32, depth-3, pass-major. Grid (16,8).
// ---------------------------------------------------------------------------
__global__ __launch_bounds__(256) void gemm_out(float* __restrict__ Cext)
{
    extern __shared__ __nv_bfloat16 dsm[];
    constexpr unsigned SZB   = 32u * 72 * 2;          // 4608
    constexpr unsigned BUFSZ = 20480u + 2 * SZB;      // 29696

    const __nv_bfloat16* gBh = g_wh[4];
    const __nv_bfloat16* gBl = g_wl[4];

    int tid  = threadIdx.x;
    int lane = tid & 31, warp = tid >> 5;
    int gid  = lane >> 2, tg = lane & 3;
    int fr = lane & 15, fc8 = (lane >> 4) * 8;
    int vr = (lane >> 4) * 8 + (lane & 7);
    int vc8 = ((lane >> 3) & 1) * 8;
    int warp_m = (warp >> 1) * 32, warp_n = (warp & 1) * 32;
    int m0 = blockIdx.y * 128, n0 = blockIdx.x * 64;
    unsigned sb = cvta_s(dsm);

    auto issue = [&](int ch, int buf) {
        int k0 = ch * 32;
        unsigned bo = sb + buf * BUFSZ;
#pragma unroll
        for (int t = 0; t < 6; t++) {
            int s = tid + t * 256;
            unsigned dst;
            const __nv_bfloat16* src;
            if (s < 1024) {
                int mt = s >> 9, rem = s & 511;
                int row = rem >> 2, seg = rem & 3;
                dst = bo + mt * 10240u + row * 80u + seg * 16u;
                src = (mt ? g_olo : g_ohi) + (size_t)(m0 + row) * 1024 + k0 + seg * 8;
            } else {
                int ss = s - 1024;
                int mt = ss >> 8, rem = ss & 255;
                int row = rem >> 3, seg = rem & 7;
                dst = bo + 20480u + mt * SZB + row * 144u + seg * 16u;
                src = (mt ? gBl : gBh) + (size_t)(k0 + row) * 1024 + n0 + seg * 8;
            }
            CP_ASYNC16(dst, src);
        }
        CP_COMMIT();
    };

    float acc[2][4][4];
#pragma unroll
    for (int a = 0; a < 2; a++)
#pragma unroll
        for (int b = 0; b < 4; b++)
#pragma unroll
            for (int q = 0; q < 4; q++) acc[a][b][q] = 0.f;

    issue(0, 0);
    issue(1, 1);

    int buf = 0;
#pragma unroll 1
    for (int ch = 0; ch < 32; ch++) {
        if (ch < 31) { CP_WAIT1(); } else { CP_WAIT0(); }
        __syncthreads();
        unsigned base = sb + buf * BUFSZ;
#pragma unroll
        for (int k16 = 0; k16 < 32; k16 += 16) {
            unsigned a_h[2][4], a_l[2][4], b_h[2][4], b_l[2][4];
#pragma unroll
            for (int mt = 0; mt < 2; mt++) {
                unsigned off = base + ((warp_m + mt * 16 + fr) * 40 + k16 + fc8) * 2;
                LDSM4(a_h[mt], off);
                LDSM4(a_l[mt], off + 10240u);
            }
#pragma unroll
            for (int tp = 0; tp < 2; tp++) {
                unsigned off = base + 20480u
                    + ((k16 + vr) * 72 + warp_n + tp * 16 + vc8) * 2;
                LDSM4T(b_h[tp], off);
                LDSM4T(b_l[tp], off + SZB);
            }
            // pass-major (8 independent per pass)
#pragma unroll
            for (int mt = 0; mt < 2; mt++)
#pragma unroll
                for (int tp = 0; tp < 2; tp++)
#pragma unroll
                    for (int u = 0; u < 2; u++)
                        MMA_BF16v(acc[mt][tp * 2 + u], a_h[mt],
                                  b_h[tp][u], b_h[tp][u + 2]);
#pragma unroll
            for (int mt = 0; mt < 2; mt++)
#pragma unroll
                for (int tp = 0; tp < 2; tp++)
#pragma unroll
                    for (int u = 0; u < 2; u++)
                        MMA_BF16v(acc[mt][tp * 2 + u], a_h[mt],
                                  b_l[tp][u], b_l[tp][u + 2]);
#pragma unroll
            for (int mt = 0; mt < 2; mt++)
#pragma unroll
                for (int tp = 0; tp < 2; tp++)
#pragma unroll
                    for (int u = 0; u < 2; u++)
                        MMA_BF16v(acc[mt][tp * 2 + u], a_l[mt],
                                  b_h[tp][u], b_h[tp][u + 2]);
        }
        if (ch + 2 < 32) {
            int nb = buf + 2; if (nb >= 3) nb -= 3;
            issue(ch + 2, nb);
        }
        if (++buf == 3) buf = 0;
    }

#pragma unroll
    for (int mt = 0; mt < 2; mt++) {
#pragma unroll
        for (int j = 0; j < 4; j++) {
            int rg = m0 + warp_m + mt * 16 + gid;
            int cg = n0 + warp_n + j * 8 + tg * 2;
            float* a4 = acc[mt][j];
            *(float2*)&Cext[(size_t)rg * 1024 + cg]       = make_float2(a4[0], a4[1]);
            *(float2*)&Cext[(size_t)(rg + 8) * 1024 + cg] = make_float2(a4[2], a4[3]);
        }
    }
}

// ---------------------------------------------------------------------------
// Flash attention, depth-3 K/V pipeline, tp-pair pass-major MMA order.
// 256 thr, 128 queries/CTA. Grid (8, 16).
// ---------------------------------------------------------------------------
__global__ __launch_bounds__(256) void attn_kernel()
{
    extern __shared__ __nv_bfloat16 dsm[];
    int tid  = threadIdx.x;
    int lane = tid & 31, warp = tid >> 5;
    int gid  = lane >> 2, tg = lane & 3;
    int h  = blockIdx.y;
    int q0 = blockIdx.x * 128;
    int warp_m = warp * 16;
    int qrow = q0 + warp_m + gid;
    unsigned sb = cvta_s(dsm);

    int fr = lane & 15, fc8 = (lane >> 4) * 8;
    int vr = (lane >> 4) * 8 + (lane & 7);
    int vc8 = ((lane >> 3) & 1) * 8;

    auto issue_kv = [&](int kb, int buf) {
        int k0 = kb * 64;
        unsigned bo = buf * 36864u;
#pragma unroll
        for (int t = 0; t < 8; t++) {
            int s = tid + t * 256;
            int mt = s >> 9, rem = s & 511;
            int row = rem >> 3, seg = rem & 7;
            unsigned dst = sb + bo + mt * 9216u + row * 144u + seg * 16u;
            const __nv_bfloat16* src;
            if      (mt == 0) src = g_kh + (size_t)(k0 + row) * 1024 + h * 64 + seg * 8;
            else if (mt == 1) src = g_kl + (size_t)(k0 + row) * 1024 + h * 64 + seg * 8;
            else if (mt == 2) src = g_vh + (size_t)(k0 + row) * 1024 + h * 64 + seg * 8;
            else              src = g_vl + (size_t)(k0 + row) * 1024 + h * 64 + seg * 8;
            CP_ASYNC16(dst, src);
        }
        CP_COMMIT();
    };

    unsigned qh[4][4], ql[4][4];
    {
        const __nv_bfloat16* Qh = g_qh + (size_t)qrow * 1024 + h * 64;
        const __nv_bfloat16* Ql = g_ql + (size_t)qrow * 1024 + h * 64;
#pragma unroll
        for (int c = 0; c < 4; c++) {
            int kk = c * 16 + tg * 2;
            qh[c][0] = *(const unsigned*)(Qh + kk);
            qh[c][1] = *(const unsigned*)(Qh + 8 * 1024 + kk);
            qh[c][2] = *(const unsigned*)(Qh + kk + 8);
            qh[c][3] = *(const unsigned*)(Qh + 8 * 1024 + kk + 8);
            ql[c][0] = *(const unsigned*)(Ql + kk);
            ql[c][1] = *(const unsigned*)(Ql + 8 * 1024 + kk);
            ql[c][2] = *(const unsigned*)(Ql + kk + 8);
            ql[c][3] = *(const unsigned*)(Ql + 8 * 1024 + kk + 8);
        }
    }

    float m0 = -1e30f, m1 = -1e30f, l0 = 0.f, l1 = 0.f;
    float O[8][4] = {};

    issue_kv(0, 0);
    issue_kv(1, 1);

    int buf = 0;
#pragma unroll 1
    for (int kb = 0; kb < 16; kb++) {
        if (kb < 15) { CP_WAIT1(); } else { CP_WAIT0(); }
        __syncthreads();
        unsigned base = sb + buf * 36864u;
        int k0 = kb * 64;

        float S[8][4];
        {
            const float* bptr = g_bias + (size_t)h * NN + (size_t)qrow * 1024 + k0;
#pragma unroll
            for (int t = 0; t < 8; t++) {
                float2 b0 = *(const float2*)(bptr + 8 * t + 2 * tg);
                float2 b1 = *(const float2*)(bptr + 8 * 1024 + 8 * t + 2 * tg);
                S[t][0] = b0.x; S[t][1] = b0.y; S[t][2] = b1.x; S[t][3] = b1.y;
            }
        }
        // S += Q K^T  (tp-pairs, pass-major within pair: dep distance 4)
#pragma unroll
        for (int c = 0; c < 4; c++) {
            int kk = c * 16;
#pragma unroll
            for (int tpp = 0; tpp < 4; tpp += 2) {
                unsigned bh[2][4], bl[2][4];
#pragma unroll
                for (int j = 0; j < 2; j++) {
                    unsigned off = base + (((tpp + j) * 16 + fr) * 72 + kk + fc8) * 2;
                    LDSM4(bh[j], off);
                    LDSM4(bl[j], off + 9216u);
                }
#pragma unroll
                for (int j = 0; j < 2; j++)
#pragma unroll
                    for (int u = 0; u < 2; u++)
                        MMA_BF16v(S[(tpp + j) * 2 + u], qh[c],
                                  bh[j][u], bh[j][u + 2]);
#pragma unroll
                for (int j = 0; j < 2; j++)
#pragma unroll
                    for (int u = 0; u < 2; u++)
                        MMA_BF16v(S[(tpp + j) * 2 + u], qh[c],
                                  bl[j][u], bl[j][u + 2]);
#pragma unroll
                for (int j = 0; j < 2; j++)
#pragma unroll
                    for (int u = 0; u < 2; u++)
                        MMA_BF16v(S[(tpp + j) * 2 + u], ql[c],
                                  bh[j][u], bh[j][u + 2]);
            }
        }

        float rm0 = -1e30f, rm1 = -1e30f;
#pragma unroll
        for (int t = 0; t < 8; t++) {
            rm0 = fmaxf(rm0, fmaxf(S[t][0], S[t][1]));
            rm1 = fmaxf(rm1, fmaxf(S[t][2], S[t][3]));
        }
        rm0 = fmaxf(rm0, __shfl_xor_sync(0xffffffffu, rm0, 1));
        rm0 = fmaxf(rm0, __shfl_xor_sync(0xffffffffu, rm0, 2));
        rm1 = fmaxf(rm1, __shfl_xor_sync(0xffffffffu, rm1, 1));
        rm1 = fmaxf(rm1, __shfl_xor_sync(0xffffffffu, rm1, 2));
        float mn0 = fmaxf(m0, rm0), mn1 = fmaxf(m1, rm1);
        float c0 = __expf(m0 - mn0), c1 = __expf(m1 - mn1);
        m0 = mn0; m1 = mn1;
        float ps0 = 0.f, ps1 = 0.f;
#pragma unroll
        for (int t = 0; t < 8; t++) {
            S[t][0] = __expf(S[t][0] - mn0);
            S[t][1] = __expf(S[t][1] - mn0);
            S[t][2] = __expf(S[t][2] - mn1);
            S[t][3] = __expf(S[t][3] - mn1);
            ps0 += S[t][0] + S[t][1];
            ps1 += S[t][2] + S[t][3];
        }
        ps0 += __shfl_xor_sync(0xffffffffu, ps0, 1);
        ps0 += __shfl_xor_sync(0xffffffffu, ps0, 2);
        ps1 += __shfl_xor_sync(0xffffffffu, ps1, 1);
        ps1 += __shfl_xor_sync(0xffffffffu, ps1, 2);
        l0 = l0 * c0 + ps0;
        l1 = l1 * c1 + ps1;
#pragma unroll
        for (int t = 0; t < 8; t++) {
            O[t][0] *= c0; O[t][1] *= c0; O[t][2] *= c1; O[t][3] *= c1;
        }

        unsigned ph[4][4], pl[4][4];
#pragma unroll
        for (int c = 0; c < 4; c++) {
            int t0 = 2 * c, t1 = 2 * c + 1;
            ph[c][0] = pk2(S[t0][0], S[t0][1]);
            ph[c][1] = pk2(S[t0][2], S[t0][3]);
            ph[c][2] = pk2(S[t1][0], S[t1][1]);
            ph[c][3] = pk2(S[t1][2], S[t1][3]);
            pl[c][0] = pk2(lores(S[t0][0]), lores(S[t0][1]));
            pl[c][1] = pk2(lores(S[t0][2]), lores(S[t0][3]));
            pl[c][2] = pk2(lores(S[t1][0]), lores(S[t1][1]));
            pl[c][3] = pk2(lores(S[t1][2]), lores(S[t1][3]));
        }

        // O += P V  (tp-pairs, pass-major within pair)
#pragma unroll
        for (int c = 0; c < 4; c++) {
#pragma unroll
            for (int tpp = 0; tpp < 4; tpp += 2) {
                unsigned bh[2][4], bl[2][4];
#pragma unroll
                for (int j = 0; j < 2; j++) {
                    unsigned off = base + 18432u
                        + ((c * 16 + vr) * 72 + (tpp + j) * 16 + vc8) * 2;
                    LDSM4T(bh[j], off);
                    LDSM4T(bl[j], off + 9216u);
                }
#pragma unroll
                for (int j = 0; j < 2; j++)
#pragma unroll
                    for (int u = 0; u < 2; u++)
                        MMA_BF16v(O[(tpp + j) * 2 + u], ph[c],
                                  bh[j][u], bh[j][u + 2]);
#pragma unroll
                for (int j = 0; j < 2; j++)
#pragma unroll
                    for (int u = 0; u < 2; u++)
                        MMA_BF16v(O[(tpp + j) * 2 + u], ph[c],
                                  bl[j][u], bl[j][u + 2]);
#pragma unroll
                for (int j = 0; j < 2; j++)
#pragma unroll
                    for (int u = 0; u < 2; u++)
                        MMA_BF16v(O[(tpp + j) * 2 + u], pl[c],
                                  bh[j][u], bh[j][u + 2]);
            }
        }
        if (kb + 2 < 16) {
            int nb = buf + 2; if (nb >= 3) nb -= 3;
            issue_kv(kb + 2, nb);
        }
        if (++buf == 3) buf = 0;
    }

    float inv0 = 1.f / l0, inv1 = 1.f / l1;
#pragma unroll
    for (int t = 0; t < 8; t++) {
        int col = h * 64 + 8 * t + 2 * tg;
        size_t o0 = (size_t)qrow * 1024 + col;
        size_t o1 = o0 + 8 * 1024;
        float2 gg0 = *(const float2*)(g_g + o0);
        float2 gg1 = *(const float2*)(g_g + o1);
        float v0 = O[t][0] * inv0 * gg0.x;
        float v1 = O[t][1] * inv0 * gg0.y;
        float v2 = O[t][2] * inv1 * gg1.x;
        float v3 = O[t][3] * inv1 * gg1.y;
        *(unsigned*)(g_ohi + o0) = pk2(v0, v1);
        *(unsigned*)(g_ohi + o1) = pk2(v2, v3);
        *(unsigned*)(g_olo + o0) = pk2(lores(v0), lores(v1));
        *(unsigned*)(g_olo + o1) = pk2(lores(v2), lores(v3));
    }
}

// ---------------------------------------------------------------------------
extern "C" void kernel_launch(void* const* d_in, const int* in_sizes, int n_in,
                              void* d_out, int out_size)
{
    const float* single = (const float*)d_in[0];
    const float* pw     = (const float*)d_in[1];
    const float* gamma  = (const float*)d_in[2];
    const float* beta   = (const float*)d_in[3];
    const float* Wb     = (const float*)d_in[4];
    const float* Wq     = (const float*)d_in[5];
    const float* Wk     = (const float*)d_in[6];
    const float* Wv     = (const float*)d_in[7];
    const float* Wg     = (const float*)d_in[8];
    const float* bg     = (const float*)d_in[9];
    const float* Wo     = (const float*)d_in[10];
    float* out = (float*)d_out;

    const int QKVG_SMEM = 3 * 54272;   // 162816
    const int OUT_SMEM  = 3 * 29696;   // 89088
    const int ATTN_SMEM = 3 * 36864;   // 110592
    cudaFuncSetAttribute(gemm_qkvg,
        cudaFuncAttributeMaxDynamicSharedMemorySize, QKVG_SMEM);
    cudaFuncSetAttribute(gemm_out,
        cudaFuncAttributeMaxDynamicSharedMemorySize, OUT_SMEM);
    cudaFuncSetAttribute(attn_kernel,
        cudaFuncAttributeMaxDynamicSharedMemorySize, ATTN_SMEM);

    bias_setup<<<1, 128>>>(gamma, beta, Wb);
    dim3 bgrid(16, 1024);
    bias_kernel<<<bgrid, 256>>>(pw);

    dim3 cgrid(1024, 6);
    conv_all<<<cgrid, 256>>>(single, Wq, Wk, Wv, Wg, Wo);

    dim3 ggrid(4, 8, 4);   // 128 CTAs
    gemm_qkvg<<<ggrid, 512, QKVG_SMEM>>>(bg);

    dim3 agrid(8, 16);
    attn_kernel<<<agrid, 256, ATTN_SMEM>>>();

    dim3 ogrid(16, 8);     // 128 CTAs
    gemm_out<<<ogrid, 256, OUT_SMEM>>>(out);
}

// round 13
// speedup vs baseline: 1.4874x; 1.4874x over previous
#include <cuda_runtime.h>
#include <cuda_bf16.h>
#include <cstdint>

#define NN (1024u*1024u)

// scratch (device globals: allocation-free)
__device__ float g_bias[16u*1024u*1024u]; // [h][i][j]
__device__ float g_g [NN];                // gates fp32 [token][dim_inner]
__device__ __nv_bfloat16 g_shi[NN], g_slo[NN];      // single_repr hi/lo [m][k]
__device__ __nv_bfloat16 g_wh[5][NN], g_wl[5][NN];  // W [k][n] hi/lo (natural)
__device__ __nv_bfloat16 g_ohi[NN], g_olo[NN];      // gated attn out hi/lo
__device__ __nv_bfloat16 g_qh[NN], g_ql[NN];        // Q [tok][d_inner] *0.125
__device__ __nv_bfloat16 g_kh[NN], g_kl[NN];        // K [tok][d_inner]
__device__ __nv_bfloat16 g_vh[NN], g_vl[NN];        // V [tok][d_inner]
__device__ __nv_bfloat16 g_wbth[16*128], g_wbtl[16*128]; // (gamma*Wb)^T [h][p]
__device__ float g_binit[16];                            // beta @ Wb

__device__ __forceinline__ unsigned pk2(float a, float b) {
    __nv_bfloat162 t = __floats2bfloat162_rn(a, b);
    return *reinterpret_cast<unsigned*>(&t);
}
__device__ __forceinline__ float lores(float a) {
    return a - __bfloat162float(__float2bfloat16(a));
}
__device__ __forceinline__ unsigned cvta_s(const void* p) {
    return (unsigned)__cvta_generic_to_shared(p);
}

#define MMA_BF16v(c, a, b0, b1) asm volatile( \
    "mma.sync.aligned.m16n8k16.row.col.f32.bf16.bf16.f32 " \
    "{%0,%1,%2,%3},{%4,%5,%6,%7},{%8,%9},{%0,%1,%2,%3};" \
    : "+f"((c)[0]), "+f"((c)[1]), "+f"((c)[2]), "+f"((c)[3]) \
    : "r"((a)[0]), "r"((a)[1]), "r"((a)[2]), "r"((a)[3]), \
      "r"(b0), "r"(b1))
#define LDSM4(R, addr) asm volatile( \
    "ldmatrix.sync.aligned.m8n8.x4.shared.b16 {%0,%1,%2,%3}, [%4];" \
    : "=r"((R)[0]), "=r"((R)[1]), "=r"((R)[2]), "=r"((R)[3]) : "r"(addr))
#define LDSM4T(R, addr) asm volatile( \
    "ldmatrix.sync.aligned.m8n8.x4.trans.shared.b16 {%0,%1,%2,%3}, [%4];" \
    : "=r"((R)[0]), "=r"((R)[1]), "=r"((R)[2]), "=r"((R)[3]) : "r"(addr))
#define CP_ASYNC16(dst, src) asm volatile( \
    "cp.async.cg.shared.global [%0], [%1], 16;" :: "r"(dst), "l"(src) : "memory")
#define CP_COMMIT() asm volatile("cp.async.commit_group;" ::: "memory")
#define CP_WAIT1()  asm volatile("cp.async.wait_group 1;" ::: "memory")
#define CP_WAIT0()  asm volatile("cp.async.wait_group 0;" ::: "memory")

// ---------------------------------------------------------------------------
// One-time prep: (gamma*W_bias)^T as bf16 hi/lo, and beta@W_bias.
// ---------------------------------------------------------------------------
__global__ void bias_setup(const float* __restrict__ gamma,
                           const float* __restrict__ beta,
                           const float* __restrict__ Wb)
{
    int tid = threadIdx.x;
    for (int idx = tid; idx < 2048; idx += 128) {
        int p = idx >> 4, h = idx & 15;
        float w = gamma[p] * Wb[idx];
        __nv_bfloat16 hi = __float2bfloat16(w);
        g_wbth[h * 128 + p] = hi;
        g_wbtl[h * 128 + p] = __float2bfloat16(w - __bfloat162float(hi));
    }
    if (tid < 16) {
        float s = 0.f;
        for (int p = 0; p < 128; p++) s += beta[p] * Wb[p * 16 + tid];
        g_binit[tid] = s;
    }
}

// ---------------------------------------------------------------------------
// Bias kernel: LN (SIMT fp32 stats) + 128->16 projection on tensor cores.
// ---------------------------------------------------------------------------
__global__ __launch_bounds__(256) void bias_kernel(const float* __restrict__ pw)
{
    __shared__ __nv_bfloat16 sXh[64][136], sXl[64][136];
    __shared__ __nv_bfloat16 sWh[16][136], sWl[16][136];
    __shared__ float stage[16][64];
    __shared__ float sbin[16];

    int tid  = threadIdx.x;
    int lane = tid & 31, warp = tid >> 5;
    int i  = blockIdx.y;
    int j0 = blockIdx.x * 64;

    const float4* rowp = (const float4*)(pw
        + ((size_t)i * 1024 + j0 + warp * 8) * 128) + lane;
    float4 x[8];
#pragma unroll
    for (int rr = 0; rr < 8; rr++) x[rr] = rowp[rr * 32];

    for (int idx = tid; idx < 2048; idx += 256) {
        int h = idx >> 7, p = idx & 127;
        sWh[h][p] = g_wbth[idx];
        sWl[h][p] = g_wbtl[idx];
    }
    if (tid < 16) sbin[tid] = g_binit[tid];

#pragma unroll
    for (int rr = 0; rr < 8; rr++) {
        float s  = x[rr].x + x[rr].y + x[rr].z + x[rr].w;
        float ss = x[rr].x*x[rr].x + x[rr].y*x[rr].y
                 + x[rr].z*x[rr].z + x[rr].w*x[rr].w;
#pragma unroll
        for (int off = 16; off >= 1; off >>= 1) {
            s  += __shfl_xor_sync(0xffffffffu, s,  off);
            ss += __shfl_xor_sync(0xffffffffu, ss, off);
        }
        float mu  = s * 0.0078125f;
        float var = ss * 0.0078125f - mu * mu;
        float rs  = rsqrtf(var + 1e-5f);
        float y0 = (x[rr].x - mu) * rs, y1 = (x[rr].y - mu) * rs;
        float y2 = (x[rr].z - mu) * rs, y3 = (x[rr].w - mu) * rs;
        int r = warp * 8 + rr;
        *(uint2*)&sXh[r][lane * 4] = make_uint2(pk2(y0, y1), pk2(y2, y3));
        *(uint2*)&sXl[r][lane * 4] =
            make_uint2(pk2(lores(y0), lores(y1)), pk2(lores(y2), lores(y3)));
    }
    __syncthreads();

    if (warp < 4) {
        int gid  = lane >> 2, tg = lane & 3;
        float acc[2][4] = {};
        int warp_m = warp * 16;
        unsigned aXh = cvta_s(sXh), aXl = cvta_s(sXl);
        unsigned aWh = cvta_s(sWh), aWl = cvta_s(sWl);
        int fr = lane & 15, fc = lane >> 4;
#pragma unroll
        for (int c = 0; c < 8; c++) {
            int kk = c * 16;
            unsigned ah[4], al[4], bh[4], bl[4];
            LDSM4(ah, aXh + ((warp_m + fr) * 136 + kk + fc * 8) * 2);
            LDSM4(al, aXl + ((warp_m + fr) * 136 + kk + fc * 8) * 2);
            LDSM4(bh, aWh + ((fr) * 136 + kk + fc * 8) * 2);
            LDSM4(bl, aWl + ((fr) * 136 + kk + fc * 8) * 2);
            // pass-major: per-acc sequence unchanged (hh -> hl -> lh)
#pragma unroll
            for (int t = 0; t < 2; t++)
                MMA_BF16v(acc[t], ah, bh[t], bh[t + 2]);
#pragma unroll
            for (int t = 0; t < 2; t++)
                MMA_BF16v(acc[t], ah, bl[t], bl[t + 2]);
#pragma unroll
            for (int t = 0; t < 2; t++)
                MMA_BF16v(acc[t], al, bh[t], bh[t + 2]);
        }
#pragma unroll
        for (int t = 0; t < 2; t++) {
            int hc = t * 8 + tg * 2;
            int r  = warp_m + gid;
            stage[hc][r]         = acc[t][0];
            stage[hc + 1][r]     = acc[t][1];
            stage[hc][r + 8]     = acc[t][2];
            stage[hc + 1][r + 8] = acc[t][3];
        }
    }
    __syncthreads();
    size_t obase = (size_t)i * 1024 + j0;
    for (int e = tid; e < 1024; e += 256) {
        int hh = e >> 6, j = e & 63;
        g_bias[(size_t)hh * NN + obase + j] = stage[hh][j] + sbin[hh];
    }
}

// ---------------------------------------------------------------------------
// Convert single_repr + all 5 weights -> bf16 hi/lo.
// ---------------------------------------------------------------------------
__global__ __launch_bounds__(256) void conv_all(
    const float* __restrict__ s0, const float* __restrict__ s1,
    const float* __restrict__ s2, const float* __restrict__ s3,
    const float* __restrict__ s4, const float* __restrict__ s5)
{
    const float* srcs[6] = {s0, s1, s2, s3, s4, s5};
    const float* src = srcs[blockIdx.y];
    __nv_bfloat16 *Dh, *Dl;
    if (blockIdx.y == 0) { Dh = g_shi; Dl = g_slo; }
    else { Dh = g_wh[blockIdx.y - 1]; Dl = g_wl[blockIdx.y - 1]; }

    unsigned i = blockIdx.x * 256u + threadIdx.x;
    float4 v = ((const float4*)src)[i];
    *(unsigned*)(Dh + 4u*i)     = pk2(v.x, v.y);
    *(unsigned*)(Dh + 4u*i + 2) = pk2(v.z, v.w);
    *(unsigned*)(Dl + 4u*i)     = pk2(lores(v.x), lores(v.y));
    *(unsigned*)(Dl + 4u*i + 2) = pk2(lores(v.z), lores(v.w));
}

// ---------------------------------------------------------------------------
// QKVG GEMM: 512 thr, tile 128x256, BK=32, depth-3, pass-major MMA order.
// Grid (4, 8, 4) = 128 CTAs = one full wave.
// ---------------------------------------------------------------------------
__global__ __launch_bounds__(512, 1) void gemm_qkvg(const float* __restrict__ aux)
{
    extern __shared__ __nv_bfloat16 dsm[];
    constexpr unsigned SZB   = 16896u;   // 32 * 264 * 2
    constexpr unsigned BUFSZ = 54272u;

    int widx = blockIdx.z;
    float scale = (widx == 0) ? 0.125f : 1.0f;
    const __nv_bfloat16* gBh = g_wh[widx];
    const __nv_bfloat16* gBl = g_wl[widx];

    int tid  = threadIdx.x;
    int lane = tid & 31, warp = tid >> 5;
    int gid  = lane >> 2, tg = lane & 3;
    int fr = lane & 15, fc8 = (lane >> 4) * 8;
    int vr = (lane >> 4) * 8 + (lane & 7);
    int vc8 = ((lane >> 3) & 1) * 8;
    int warp_m = (warp >> 2) * 32, warp_n = (warp & 3) * 64;
    int m0 = blockIdx.y * 128, n0 = blockIdx.x * 256;
    unsigned sb = cvta_s(dsm);

    int a_row = (tid & 511) >> 2, a_seg = tid & 3;
    int b_row = (tid & 1023) >> 5, b_seg = tid & 31;

    const __nv_bfloat16* pAh = g_shi + (size_t)(m0 + a_row) * 1024 + a_seg * 8;
    const __nv_bfloat16* pAl = g_slo + (size_t)(m0 + a_row) * 1024 + a_seg * 8;
    const __nv_bfloat16* pBh0 = gBh + (size_t)b_row * 1024 + n0 + b_seg * 8;
    const __nv_bfloat16* pBl0 = gBl + (size_t)b_row * 1024 + n0 + b_seg * 8;
    const __nv_bfloat16* pBh1 = pBh0 + 16 * 1024;
    const __nv_bfloat16* pBl1 = pBl0 + 16 * 1024;
    unsigned dA  = a_row * 80u + a_seg * 16u;
    unsigned dB0 = 20480u + b_row * 528u + b_seg * 16u;
    unsigned dB1 = 20480u + (b_row + 16) * 528u + b_seg * 16u;

    auto issue = [&](int ch, int buf) {
        unsigned k0 = ch * 32u;
        size_t kq = ch * 32u * 1024u;
        unsigned bo = sb + buf * BUFSZ;
        CP_ASYNC16(bo + dA,           pAh + k0);
        CP_ASYNC16(bo + dA + 10240u,  pAl + k0);
        CP_ASYNC16(bo + dB0,          pBh0 + kq);
        CP_ASYNC16(bo + dB0 + SZB,    pBl0 + kq);
        CP_ASYNC16(bo + dB1,          pBh1 + kq);
        CP_ASYNC16(bo + dB1 + SZB,    pBl1 + kq);
        CP_COMMIT();
    };

    float acc[2][8][4];
#pragma unroll
    for (int a = 0; a < 2; a++)
#pragma unroll
        for (int b = 0; b < 8; b++)
#pragma unroll
            for (int q = 0; q < 4; q++) acc[a][b][q] = 0.f;

    issue(0, 0);
    issue(1, 1);

    int buf = 0;
#pragma unroll 1
    for (int ch = 0; ch < 32; ch++) {
        if (ch < 31) { CP_WAIT1(); } else { CP_WAIT0(); }
        __syncthreads();
        unsigned base = sb + buf * BUFSZ;
#pragma unroll
        for (int k16 = 0; k16 < 32; k16 += 16) {
            unsigned a_h[2][4], a_l[2][4], b_h[4][4], b_l[4][4];
#pragma unroll
            for (int mt = 0; mt < 2; mt++) {
                unsigned off = base + ((warp_m + mt * 16 + fr) * 40 + k16 + fc8) * 2;
                LDSM4(a_h[mt], off);
                LDSM4(a_l[mt], off + 10240u);
            }
#pragma unroll
            for (int tp = 0; tp < 4; tp++) {
                unsigned off = base + 20480u
                    + ((k16 + vr) * 264 + warp_n + tp * 16 + vc8) * 2;
                LDSM4T(b_h[tp], off);
                LDSM4T(b_l[tp], off + SZB);
            }
            // pass-major: 16 independent MMAs per pass; per-acc order hh->hl->lh
#pragma unroll
            for (int mt = 0; mt < 2; mt++)
#pragma unroll
                for (int tp = 0; tp < 4; tp++)
#pragma unroll
                    for (int u = 0; u < 2; u++)
                        MMA_BF16v(acc[mt][tp * 2 + u], a_h[mt],
                                  b_h[tp][u], b_h[tp][u + 2]);
#pragma unroll
            for (int mt = 0; mt < 2; mt++)
#pragma unroll
                for (int tp = 0; tp < 4; tp++)
#pragma unroll
                    for (int u = 0; u < 2; u++)
                        MMA_BF16v(acc[mt][tp * 2 + u], a_h[mt],
                                  b_l[tp][u], b_l[tp][u + 2]);
#pragma unroll
            for (int mt = 0; mt < 2; mt++)
#pragma unroll
                for (int tp = 0; tp < 4; tp++)
#pragma unroll
                    for (int u = 0; u < 2; u++)
                        MMA_BF16v(acc[mt][tp * 2 + u], a_l[mt],
                                  b_h[tp][u], b_h[tp][u + 2]);
        }
        if (ch + 2 < 32) {
            int nb = buf + 2; if (nb >= 3) nb -= 3;
            issue(ch + 2, nb);
        }
        if (++buf == 3) buf = 0;
    }

    __nv_bfloat16* Dh = (widx == 0) ? g_qh : (widx == 1) ? g_kh : g_vh;
    __nv_bfloat16* Dl = (widx == 0) ? g_ql : (widx == 1) ? g_kl : g_vl;
#pragma unroll
    for (int mt = 0; mt < 2; mt++) {
#pragma unroll
        for (int j = 0; j < 8; j++) {
            int rg = m0 + warp_m + mt * 16 + gid;
            int cg = n0 + warp_n + j * 8 + tg * 2;
            float* a4 = acc[mt][j];
            if (widx == 3) {
                float b0 = aux[cg], b1 = aux[cg + 1];
                float v0 = 1.f / (1.f + __expf(-(a4[0] + b0)));
                float v1 = 1.f / (1.f + __expf(-(a4[1] + b1)));
                float v2 = 1.f / (1.f + __expf(-(a4[2] + b0)));
                float v3 = 1.f / (1.f + __expf(-(a4[3] + b1)));
                *(float2*)&g_g[(size_t)rg * 1024 + cg]       = make_float2(v0, v1);
                *(float2*)&g_g[(size_t)(rg + 8) * 1024 + cg] = make_float2(v2, v3);
            } else {
                float v0 = a4[0] * scale, v1 = a4[1] * scale;
                float v2 = a4[2] * scale, v3 = a4[3] * scale;
                *(unsigned*)&Dh[(size_t)rg * 1024 + cg]       = pk2(v0, v1);
                *(unsigned*)&Dh[(size_t)(rg + 8) * 1024 + cg] = pk2(v2, v3);
                *(unsigned*)&Dl[(size_t)rg * 1024 + cg]       = pk2(lores(v0), lores(v1));
                *(unsigned*)&Dl[(size_t)(rg + 8) * 1024 + cg] =
                    pk2(lores(v2), lores(v3));
            }
        }
    }
}

// ---------------------------------------------------------------------------
// Output GEMM: 256 thr, tile 128x64, BK=32, depth-3, pass-major. Grid (16,8).
// ---------------------------------------------------------------------------
__global__ __launch_bounds__(256) void gemm_out(float* __restrict__ Cext)
{
    extern __shared__ __nv_bfloat16 dsm[];
    constexpr unsigned SZB   = 32u * 72 * 2;          // 4608
    constexpr unsigned BUFSZ = 20480u + 2 * SZB;      // 29696

    const __nv_bfloat16* gBh = g_wh[4];
    const __nv_bfloat16* gBl = g_wl[4];

    int tid  = threadIdx.x;
    int lane = tid & 31, warp = tid >> 5;
    int gid  = lane >> 2, tg = lane & 3;
    int fr = lane & 15, fc8 = (lane >> 4) * 8;
    int vr = (lane >> 4) * 8 + (lane & 7);
    int vc8 = ((lane >> 3) & 1) * 8;
    int warp_m = (warp >> 1) * 32, warp_n = (warp & 1) * 32;
    int m0 = blockIdx.y * 128, n0 = blockIdx.x * 64;
    unsigned sb = cvta_s(dsm);

    auto issue = [&](int ch, int buf) {
        int k0 = ch * 32;
        unsigned bo = sb + buf * BUFSZ;
#pragma unroll
        for (int t = 0; t < 6; t++) {
            int s = tid + t * 256;
            unsigned dst;
            const __nv_bfloat16* src;
            if (s < 1024) {
                int mt = s >> 9, rem = s & 511;
                int row = rem >> 2, seg = rem & 3;
                dst = bo + mt * 10240u + row * 80u + seg * 16u;
                src = (mt ? g_olo : g_ohi) + (size_t)(m0 + row) * 1024 + k0 + seg * 8;
            } else {
                int ss = s - 1024;
                int mt = ss >> 8, rem = ss & 255;
                int row = rem >> 3, seg = rem & 7;
                dst = bo + 20480u + mt * SZB + row * 144u + seg * 16u;
                src = (mt ? gBl : gBh) + (size_t)(k0 + row) * 1024 + n0 + seg * 8;
            }
            CP_ASYNC16(dst, src);
        }
        CP_COMMIT();
    };

    float acc[2][4][4];
#pragma unroll
    for (int a = 0; a < 2; a++)
#pragma unroll
        for (int b = 0; b < 4; b++)
#pragma unroll
            for (int q = 0; q < 4; q++) acc[a][b][q] = 0.f;

    issue(0, 0);
    issue(1, 1);

    int buf = 0;
#pragma unroll 1
    for (int ch = 0; ch < 32; ch++) {
        if (ch < 31) { CP_WAIT1(); } else { CP_WAIT0(); }
        __syncthreads();
        unsigned base = sb + buf * BUFSZ;
#pragma unroll
        for (int k16 = 0; k16 < 32; k16 += 16) {
            unsigned a_h[2][4], a_l[2][4], b_h[2][4], b_l[2][4];
#pragma unroll
            for (int mt = 0; mt < 2; mt++) {
                unsigned off = base + ((warp_m + mt * 16 + fr) * 40 + k16 + fc8) * 2;
                LDSM4(a_h[mt], off);
                LDSM4(a_l[mt], off + 10240u);
            }
#pragma unroll
            for (int tp = 0; tp < 2; tp++) {
                unsigned off = base + 20480u
                    + ((k16 + vr) * 72 + warp_n + tp * 16 + vc8) * 2;
                LDSM4T(b_h[tp], off);
                LDSM4T(b_l[tp], off + SZB);
            }
            // pass-major (8 independent per pass)
#pragma unroll
            for (int mt = 0; mt < 2; mt++)
#pragma unroll
                for (int tp = 0; tp < 2; tp++)
#pragma unroll
                    for (int u = 0; u < 2; u++)
                        MMA_BF16v(acc[mt][tp * 2 + u], a_h[mt],
                                  b_h[tp][u], b_h[tp][u + 2]);
#pragma unroll
            for (int mt = 0; mt < 2; mt++)
#pragma unroll
                for (int tp = 0; tp < 2; tp++)
#pragma unroll
                    for (int u = 0; u < 2; u++)
                        MMA_BF16v(acc[mt][tp * 2 + u], a_h[mt],
                                  b_l[tp][u], b_l[tp][u + 2]);
#pragma unroll
            for (int mt = 0; mt < 2; mt++)
#pragma unroll
                for (int tp = 0; tp < 2; tp++)
#pragma unroll
                    for (int u = 0; u < 2; u++)
                        MMA_BF16v(acc[mt][tp * 2 + u], a_l[mt],
                                  b_h[tp][u], b_h[tp][u + 2]);
        }
        if (ch + 2 < 32) {
            int nb = buf + 2; if (nb >= 3) nb -= 3;
            issue(ch + 2, nb);
        }
        if (++buf == 3) buf = 0;
    }

#pragma unroll
    for (int mt = 0; mt < 2; mt++) {
#pragma unroll
        for (int j = 0; j < 4; j++) {
            int rg = m0 + warp_m + mt * 16 + gid;
            int cg = n0 + warp_n + j * 8 + tg * 2;
            float* a4 = acc[mt][j];
            *(float2*)&Cext[(size_t)rg * 1024 + cg]       = make_float2(a4[0], a4[1]);
            *(float2*)&Cext[(size_t)(rg + 8) * 1024 + cg] = make_float2(a4[2], a4[3]);
        }
    }
}

// ---------------------------------------------------------------------------
// Flash attention, depth-3 K/V pipeline, tp-pair pass-major MMA order.
// 256 thr, 128 queries/CTA. Grid (8, 16).
// ---------------------------------------------------------------------------
__global__ __launch_bounds__(256) void attn_kernel()
{
    extern __shared__ __nv_bfloat16 dsm[];
    int tid  = threadIdx.x;
    int lane = tid & 31, warp = tid >> 5;
    int gid  = lane >> 2, tg = lane & 3;
    int h  = blockIdx.y;
    int q0 = blockIdx.x * 128;
    int warp_m = warp * 16;
    int qrow = q0 + warp_m + gid;
    unsigned sb = cvta_s(dsm);

    int fr = lane & 15, fc8 = (lane >> 4) * 8;
    int vr = (lane >> 4) * 8 + (lane & 7);
    int vc8 = ((lane >> 3) & 1) * 8;

    auto issue_kv = [&](int kb, int buf) {
        int k0 = kb * 64;
        unsigned bo = buf * 36864u;
#pragma unroll
        for (int t = 0; t < 8; t++) {
            int s = tid + t * 256;
            int mt = s >> 9, rem = s & 511;
            int row = rem >> 3, seg = rem & 7;
            unsigned dst = sb + bo + mt * 9216u + row * 144u + seg * 16u;
            const __nv_bfloat16* src;
            if      (mt == 0) src = g_kh + (size_t)(k0 + row) * 1024 + h * 64 + seg * 8;
            else if (mt == 1) src = g_kl + (size_t)(k0 + row) * 1024 + h * 64 + seg * 8;
            else if (mt == 2) src = g_vh + (size_t)(k0 + row) * 1024 + h * 64 + seg * 8;
            else              src = g_vl + (size_t)(k0 + row) * 1024 + h * 64 + seg * 8;
            CP_ASYNC16(dst, src);
        }
        CP_COMMIT();
    };

    unsigned qh[4][4], ql[4][4];
    {
        const __nv_bfloat16* Qh = g_qh + (size_t)qrow * 1024 + h * 64;
        const __nv_bfloat16* Ql = g_ql + (size_t)qrow * 1024 + h * 64;
#pragma unroll
        for (int c = 0; c < 4; c++) {
            int kk = c * 16 + tg * 2;
            qh[c][0] = *(const unsigned*)(Qh + kk);
            qh[c][1] = *(const unsigned*)(Qh + 8 * 1024 + kk);
            qh[c][2] = *(const unsigned*)(Qh + kk + 8);
            qh[c][3] = *(const unsigned*)(Qh + 8 * 1024 + kk + 8);
            ql[c][0] = *(const unsigned*)(Ql + kk);
            ql[c][1] = *(const unsigned*)(Ql + 8 * 1024 + kk);
            ql[c][2] = *(const unsigned*)(Ql + kk + 8);
            ql[c][3] = *(const unsigned*)(Ql + 8 * 1024 + kk + 8);
        }
    }

    float m0 = -1e30f, m1 = -1e30f, l0 = 0.f, l1 = 0.f;
    float O[8][4] = {};

    issue_kv(0, 0);
    issue_kv(1, 1);

    int buf = 0;
#pragma unroll 1
    for (int kb = 0; kb < 16; kb++) {
        if (kb < 15) { CP_WAIT1(); } else { CP_WAIT0(); }
        __syncthreads();
        unsigned base = sb + buf * 36864u;
        int k0 = kb * 64;

        float S[8][4];
        {
            const float* bptr = g_bias + (size_t)h * NN + (size_t)qrow * 1024 + k0;
#pragma unroll
            for (int t = 0; t < 8; t++) {
                float2 b0 = *(const float2*)(bptr + 8 * t + 2 * tg);
                float2 b1 = *(const float2*)(bptr + 8 * 1024 + 8 * t + 2 * tg);
                S[t][0] = b0.x; S[t][1] = b0.y; S[t][2] = b1.x; S[t][3] = b1.y;
            }
        }
        // S += Q K^T  (tp-pairs, pass-major within pair: dep distance 4)
#pragma unroll
        for (int c = 0; c < 4; c++) {
            int kk = c * 16;
#pragma unroll
            for (int tpp = 0; tpp < 4; tpp += 2) {
                unsigned bh[2][4], bl[2][4];
#pragma unroll
                for (int j = 0; j < 2; j++) {
                    unsigned off = base + (((tpp + j) * 16 + fr) * 72 + kk + fc8) * 2;
                    LDSM4(bh[j], off);
                    LDSM4(bl[j], off + 9216u);
                }
#pragma unroll
                for (int j = 0; j < 2; j++)
#pragma unroll
                    for (int u = 0; u < 2; u++)
                        MMA_BF16v(S[(tpp + j) * 2 + u], qh[c],
                                  bh[j][u], bh[j][u + 2]);
#pragma unroll
                for (int j = 0; j < 2; j++)
#pragma unroll
                    for (int u = 0; u < 2; u++)
                        MMA_BF16v(S[(tpp + j) * 2 + u], qh[c],
                                  bl[j][u], bl[j][u + 2]);
#pragma unroll
                for (int j = 0; j < 2; j++)
#pragma unroll
                    for (int u = 0; u < 2; u++)
                        MMA_BF16v(S[(tpp + j) * 2 + u], ql[c],
                                  bh[j][u], bh[j][u + 2]);
            }
        }

        float rm0 = -1e30f, rm1 = -1e30f;
#pragma unroll
        for (int t = 0; t < 8; t++) {
            rm0 = fmaxf(rm0, fmaxf(S[t][0], S[t][1]));
            rm1 = fmaxf(rm1, fmaxf(S[t][2], S[t][3]));
        }
        rm0 = fmaxf(rm0, __shfl_xor_sync(0xffffffffu, rm0, 1));
        rm0 = fmaxf(rm0, __shfl_xor_sync(0xffffffffu, rm0, 2));
        rm1 = fmaxf(rm1, __shfl_xor_sync(0xffffffffu, rm1, 1));
        rm1 = fmaxf(rm1, __shfl_xor_sync(0xffffffffu, rm1, 2));
        float mn0 = fmaxf(m0, rm0), mn1 = fmaxf(m1, rm1);
        float c0 = __expf(m0 - mn0), c1 = __expf(m1 - mn1);
        m0 = mn0; m1 = mn1;
        float ps0 = 0.f, ps1 = 0.f;
#pragma unroll
        for (int t = 0; t < 8; t++) {
            S[t][0] = __expf(S[t][0] - mn0);
            S[t][1] = __expf(S[t][1] - mn0);
            S[t][2] = __expf(S[t][2] - mn1);
            S[t][3] = __expf(S[t][3] - mn1);
            ps0 += S[t][0] + S[t][1];
            ps1 += S[t][2] + S[t][3];
        }
        ps0 += __shfl_xor_sync(0xffffffffu, ps0, 1);
        ps0 += __shfl_xor_sync(0xffffffffu, ps0, 2);
        ps1 += __shfl_xor_sync(0xffffffffu, ps1, 1);
        ps1 += __shfl_xor_sync(0xffffffffu, ps1, 2);
        l0 = l0 * c0 + ps0;
        l1 = l1 * c1 + ps1;
#pragma unroll
        for (int t = 0; t < 8; t++) {
            O[t][0] *= c0; O[t][1] *= c0; O[t][2] *= c1; O[t][3] *= c1;
        }

        unsigned ph[4][4], pl[4][4];
#pragma unroll
        for (int c = 0; c < 4; c++) {
            int t0 = 2 * c, t1 = 2 * c + 1;
            ph[c][0] = pk2(S[t0][0], S[t0][1]);
            ph[c][1] = pk2(S[t0][2], S[t0][3]);
            ph[c][2] = pk2(S[t1][0], S[t1][1]);
            ph[c][3] = pk2(S[t1][2], S[t1][3]);
            pl[c][0] = pk2(lores(S[t0][0]), lores(S[t0][1]));
            pl[c][1] = pk2(lores(S[t0][2]), lores(S[t0][3]));
            pl[c][2] = pk2(lores(S[t1][0]), lores(S[t1][1]));
            pl[c][3] = pk2(lores(S[t1][2]), lores(S[t1][3]));
        }

        // O += P V  (tp-pairs, pass-major within pair)
#pragma unroll
        for (int c = 0; c < 4; c++) {
#pragma unroll
            for (int tpp = 0; tpp < 4; tpp += 2) {
                unsigned bh[2][4], bl[2][4];
#pragma unroll
                for (int j = 0; j < 2; j++) {
                    unsigned off = base + 18432u
                        + ((c * 16 + vr) * 72 + (tpp + j) * 16 + vc8) * 2;
                    LDSM4T(bh[j], off);
                    LDSM4T(bl[j], off + 9216u);
                }
#pragma unroll
                for (int j = 0; j < 2; j++)
#pragma unroll
                    for (int u = 0; u < 2; u++)
                        MMA_BF16v(O[(tpp + j) * 2 + u], ph[c],
                                  bh[j][u], bh[j][u + 2]);
#pragma unroll
                for (int j = 0; j < 2; j++)
#pragma unroll
                    for (int u = 0; u < 2; u++)
                        MMA_BF16v(O[(tpp + j) * 2 + u], ph[c],
                                  bl[j][u], bl[j][u + 2]);
#pragma unroll
                for (int j = 0; j < 2; j++)
#pragma unroll
                    for (int u = 0; u < 2; u++)
                        MMA_BF16v(O[(tpp + j) * 2 + u], pl[c],
                                  bh[j][u], bh[j][u + 2]);
            }
        }
        if (kb + 2 < 16) {
            int nb = buf + 2; if (nb >= 3) nb -= 3;
            issue_kv(kb + 2, nb);
        }
        if (++buf == 3) buf = 0;
    }

    float inv0 = 1.f / l0, inv1 = 1.f / l1;
#pragma unroll
    for (int t = 0; t < 8; t++) {
        int col = h * 64 + 8 * t + 2 * tg;
        size_t o0 = (size_t)qrow * 1024 + col;
        size_t o1 = o0 + 8 * 1024;
        float2 gg0 = *(const float2*)(g_g + o0);
        float2 gg1 = *(const float2*)(g_g + o1);
        float v0 = O[t][0] * inv0 * gg0.x;
        float v1 = O[t][1] * inv0 * gg0.y;
        float v2 = O[t][2] * inv1 * gg1.x;
        float v3 = O[t][3] * inv1 * gg1.y;
        *(unsigned*)(g_ohi + o0) = pk2(v0, v1);
        *(unsigned*)(g_ohi + o1) = pk2(v2, v3);
        *(unsigned*)(g_olo + o0) = pk2(lores(v0), lores(v1));
        *(unsigned*)(g_olo + o1) = pk2(lores(v2), lores(v3));
    }
}

// ---------------------------------------------------------------------------
extern "C" void kernel_launch(void* const* d_in, const int* in_sizes, int n_in,
                              void* d_out, int out_size)
{
    const float* single = (const float*)d_in[0];
    const float* pw     = (const float*)d_in[1];
    const float* gamma  = (const float*)d_in[2];
    const float* beta   = (const float*)d_in[3];
    const float* Wb     = (const float*)d_in[4];
    const float* Wq     = (const float*)d_in[5];
    const float* Wk     = (const float*)d_in[6];
    const float* Wv     = (const float*)d_in[7];
    const float* Wg     = (const float*)d_in[8];
    const float* bg     = (const float*)d_in[9];
    const float* Wo     = (const float*)d_in[10];
    float* out = (float*)d_out;

    const int QKVG_SMEM = 3 * 54272;   // 162816
    const int OUT_SMEM  = 3 * 29696;   // 89088
    const int ATTN_SMEM = 3 * 36864;   // 110592
    cudaFuncSetAttribute(gemm_qkvg,
        cudaFuncAttributeMaxDynamicSharedMemorySize, QKVG_SMEM);
    cudaFuncSetAttribute(gemm_out,
        cudaFuncAttributeMaxDynamicSharedMemorySize, OUT_SMEM);
    cudaFuncSetAttribute(attn_kernel,
        cudaFuncAttributeMaxDynamicSharedMemorySize, ATTN_SMEM);

    bias_setup<<<1, 128>>>(gamma, beta, Wb);
    dim3 bgrid(16, 1024);
    bias_kernel<<<bgrid, 256>>>(pw);

    dim3 cgrid(1024, 6);
    conv_all<<<cgrid, 256>>>(single, Wq, Wk, Wv, Wg, Wo);

    dim3 ggrid(4, 8, 4);   // 128 CTAs
    gemm_qkvg<<<ggrid, 512, QKVG_SMEM>>>(bg);

    dim3 agrid(8, 16);
    attn_kernel<<<agrid, 256, ATTN_SMEM>>>();

    dim3 ogrid(16, 8);     // 128 CTAs
    gemm_out<<<ogrid, 256, OUT_SMEM>>>(out);
}

// round 14
// speedup vs baseline: 1.4966x; 1.0062x over previous
#include <cuda_runtime.h>
#include <cuda_bf16.h>
#include <cstdint>

#define NN (1024u*1024u)

// scratch (device globals: allocation-free)
__device__ float g_bias[16u*1024u*1024u]; // [h][i][j]
__device__ float g_g [NN];                // gates fp32 [token][dim_inner]
__device__ __nv_bfloat16 g_shi[NN], g_slo[NN];      // single_repr hi/lo [m][k]
__device__ __nv_bfloat16 g_wh[5][NN], g_wl[5][NN];  // W [k][n] hi/lo (natural)
__device__ __nv_bfloat16 g_ohi[NN], g_olo[NN];      // gated attn out hi/lo
__device__ __nv_bfloat16 g_qh[NN], g_ql[NN];        // Q [tok][d_inner] *0.125
__device__ __nv_bfloat16 g_kh[NN], g_kl[NN];        // K [tok][d_inner]
__device__ __nv_bfloat16 g_vh[NN], g_vl[NN];        // V [tok][d_inner]
__device__ __nv_bfloat16 g_wbth[16*128], g_wbtl[16*128]; // (gamma*Wb)^T [h][p]
__device__ float g_binit[16];                            // beta @ Wb

__device__ __forceinline__ unsigned pk2(float a, float b) {
    __nv_bfloat162 t = __floats2bfloat162_rn(a, b);
    return *reinterpret_cast<unsigned*>(&t);
}
__device__ __forceinline__ float lores(float a) {
    return a - __bfloat162float(__float2bfloat16(a));
}
__device__ __forceinline__ unsigned cvta_s(const void* p) {
    return (unsigned)__cvta_generic_to_shared(p);
}

#define MMA_BF16v(c, a, b0, b1) asm volatile( \
    "mma.sync.aligned.m16n8k16.row.col.f32.bf16.bf16.f32 " \
    "{%0,%1,%2,%3},{%4,%5,%6,%7},{%8,%9},{%0,%1,%2,%3};" \
    : "+f"((c)[0]), "+f"((c)[1]), "+f"((c)[2]), "+f"((c)[3]) \
    : "r"((a)[0]), "r"((a)[1]), "r"((a)[2]), "r"((a)[3]), \
      "r"(b0), "r"(b1))
#define LDSM4(R, addr) asm volatile( \
    "ldmatrix.sync.aligned.m8n8.x4.shared.b16 {%0,%1,%2,%3}, [%4];" \
    : "=r"((R)[0]), "=r"((R)[1]), "=r"((R)[2]), "=r"((R)[3]) : "r"(addr))
#define LDSM4T(R, addr) asm volatile( \
    "ldmatrix.sync.aligned.m8n8.x4.trans.shared.b16 {%0,%1,%2,%3}, [%4];" \
    : "=r"((R)[0]), "=r"((R)[1]), "=r"((R)[2]), "=r"((R)[3]) : "r"(addr))
#define CP_ASYNC16(dst, src) asm volatile( \
    "cp.async.cg.shared.global [%0], [%1], 16;" :: "r"(dst), "l"(src) : "memory")
#define CP_COMMIT() asm volatile("cp.async.commit_group;" ::: "memory")
#define CP_WAIT1()  asm volatile("cp.async.wait_group 1;" ::: "memory")
#define CP_WAIT0()  asm volatile("cp.async.wait_group 0;" ::: "memory")

// ---------------------------------------------------------------------------
// One-time prep: (gamma*W_bias)^T as bf16 hi/lo, and beta@W_bias.
// ---------------------------------------------------------------------------
__global__ void bias_setup(const float* __restrict__ gamma,
                           const float* __restrict__ beta,
                           const float* __restrict__ Wb)
{
    int tid = threadIdx.x;
    for (int idx = tid; idx < 2048; idx += 128) {
        int p = idx >> 4, h = idx & 15;
        float w = gamma[p] * Wb[idx];
        __nv_bfloat16 hi = __float2bfloat16(w);
        g_wbth[h * 128 + p] = hi;
        g_wbtl[h * 128 + p] = __float2bfloat16(w - __bfloat162float(hi));
    }
    if (tid < 16) {
        float s = 0.f;
        for (int p = 0; p < 128; p++) s += beta[p] * Wb[p * 16 + tid];
        g_binit[tid] = s;
    }
}

// ---------------------------------------------------------------------------
// Bias kernel: LN (SIMT fp32 stats) + 128->16 projection on tensor cores.
// ---------------------------------------------------------------------------
__global__ __launch_bounds__(256) void bias_kernel(const float* __restrict__ pw)
{
    __shared__ __nv_bfloat16 sXh[64][136], sXl[64][136];
    __shared__ __nv_bfloat16 sWh[16][136], sWl[16][136];
    __shared__ float stage[16][64];
    __shared__ float sbin[16];

    int tid  = threadIdx.x;
    int lane = tid & 31, warp = tid >> 5;
    int i  = blockIdx.y;
    int j0 = blockIdx.x * 64;

    const float4* rowp = (const float4*)(pw
        + ((size_t)i * 1024 + j0 + warp * 8) * 128) + lane;
    float4 x[8];
#pragma unroll
    for (int rr = 0; rr < 8; rr++) x[rr] = rowp[rr * 32];

    for (int idx = tid; idx < 2048; idx += 256) {
        int h = idx >> 7, p = idx & 127;
        sWh[h][p] = g_wbth[idx];
        sWl[h][p] = g_wbtl[idx];
    }
    if (tid < 16) sbin[tid] = g_binit[tid];

#pragma unroll
    for (int rr = 0; rr < 8; rr++) {
        float s  = x[rr].x + x[rr].y + x[rr].z + x[rr].w;
        float ss = x[rr].x*x[rr].x + x[rr].y*x[rr].y
                 + x[rr].z*x[rr].z + x[rr].w*x[rr].w;
#pragma unroll
        for (int off = 16; off >= 1; off >>= 1) {
            s  += __shfl_xor_sync(0xffffffffu, s,  off);
            ss += __shfl_xor_sync(0xffffffffu, ss, off);
        }
        float mu  = s * 0.0078125f;
        float var = ss * 0.0078125f - mu * mu;
        float rs  = rsqrtf(var + 1e-5f);
        float y0 = (x[rr].x - mu) * rs, y1 = (x[rr].y - mu) * rs;
        float y2 = (x[rr].z - mu) * rs, y3 = (x[rr].w - mu) * rs;
        int r = warp * 8 + rr;
        *(uint2*)&sXh[r][lane * 4] = make_uint2(pk2(y0, y1), pk2(y2, y3));
        *(uint2*)&sXl[r][lane * 4] =
            make_uint2(pk2(lores(y0), lores(y1)), pk2(lores(y2), lores(y3)));
    }
    __syncthreads();

    if (warp < 4) {
        int gid  = lane >> 2, tg = lane & 3;
        float acc[2][4] = {};
        int warp_m = warp * 16;
        unsigned aXh = cvta_s(sXh), aXl = cvta_s(sXl);
        unsigned aWh = cvta_s(sWh), aWl = cvta_s(sWl);
        int fr = lane & 15, fc = lane >> 4;
#pragma unroll
        for (int c = 0; c < 8; c++) {
            int kk = c * 16;
            unsigned ah[4], al[4], bh[4], bl[4];
            LDSM4(ah, aXh + ((warp_m + fr) * 136 + kk + fc * 8) * 2);
            LDSM4(al, aXl + ((warp_m + fr) * 136 + kk + fc * 8) * 2);
            LDSM4(bh, aWh + ((fr) * 136 + kk + fc * 8) * 2);
            LDSM4(bl, aWl + ((fr) * 136 + kk + fc * 8) * 2);
            // pass-major: per-acc sequence unchanged (hh -> hl -> lh)
#pragma unroll
            for (int t = 0; t < 2; t++)
                MMA_BF16v(acc[t], ah, bh[t], bh[t + 2]);
#pragma unroll
            for (int t = 0; t < 2; t++)
                MMA_BF16v(acc[t], ah, bl[t], bl[t + 2]);
#pragma unroll
            for (int t = 0; t < 2; t++)
                MMA_BF16v(acc[t], al, bh[t], bh[t + 2]);
        }
#pragma unroll
        for (int t = 0; t < 2; t++) {
            int hc = t * 8 + tg * 2;
            int r  = warp_m + gid;
            stage[hc][r]         = acc[t][0];
            stage[hc + 1][r]     = acc[t][1];
            stage[hc][r + 8]     = acc[t][2];
            stage[hc + 1][r + 8] = acc[t][3];
        }
    }
    __syncthreads();
    size_t obase = (size_t)i * 1024 + j0;
    for (int e = tid; e < 1024; e += 256) {
        int hh = e >> 6, j = e & 63;
        g_bias[(size_t)hh * NN + obase + j] = stage[hh][j] + sbin[hh];
    }
}

// ---------------------------------------------------------------------------
// Convert single_repr + all 5 weights -> bf16 hi/lo.
// ---------------------------------------------------------------------------
__global__ __launch_bounds__(256) void conv_all(
    const float* __restrict__ s0, const float* __restrict__ s1,
    const float* __restrict__ s2, const float* __restrict__ s3,
    const float* __restrict__ s4, const float* __restrict__ s5)
{
    const float* srcs[6] = {s0, s1, s2, s3, s4, s5};
    const float* src = srcs[blockIdx.y];
    __nv_bfloat16 *Dh, *Dl;
    if (blockIdx.y == 0) { Dh = g_shi; Dl = g_slo; }
    else { Dh = g_wh[blockIdx.y - 1]; Dl = g_wl[blockIdx.y - 1]; }

    unsigned i = blockIdx.x * 256u + threadIdx.x;
    float4 v = ((const float4*)src)[i];
    *(unsigned*)(Dh + 4u*i)     = pk2(v.x, v.y);
    *(unsigned*)(Dh + 4u*i + 2) = pk2(v.z, v.w);
    *(unsigned*)(Dl + 4u*i)     = pk2(lores(v.x), lores(v.y));
    *(unsigned*)(Dl + 4u*i + 2) = pk2(lores(v.z), lores(v.w));
}

// ---------------------------------------------------------------------------
// QKVG GEMM: 512 thr, tile 128x256, BK=32, depth-3, pass-major MMA order.
// Grid (4, 8, 4) = 128 CTAs = one full wave.
// ---------------------------------------------------------------------------
__global__ __launch_bounds__(512, 1) void gemm_qkvg(const float* __restrict__ aux)
{
    extern __shared__ __nv_bfloat16 dsm[];
    constexpr unsigned SZB   = 16896u;   // 32 * 264 * 2
    constexpr unsigned BUFSZ = 54272u;

    int widx = blockIdx.z;
    float scale = (widx == 0) ? 0.125f : 1.0f;
    const __nv_bfloat16* gBh = g_wh[widx];
    const __nv_bfloat16* gBl = g_wl[widx];

    int tid  = threadIdx.x;
    int lane = tid & 31, warp = tid >> 5;
    int gid  = lane >> 2, tg = lane & 3;
    int fr = lane & 15, fc8 = (lane >> 4) * 8;
    int vr = (lane >> 4) * 8 + (lane & 7);
    int vc8 = ((lane >> 3) & 1) * 8;
    int warp_m = (warp >> 2) * 32, warp_n = (warp & 3) * 64;
    int m0 = blockIdx.y * 128, n0 = blockIdx.x * 256;
    unsigned sb = cvta_s(dsm);

    int a_row = (tid & 511) >> 2, a_seg = tid & 3;
    int b_row = (tid & 1023) >> 5, b_seg = tid & 31;

    const __nv_bfloat16* pAh = g_shi + (size_t)(m0 + a_row) * 1024 + a_seg * 8;
    const __nv_bfloat16* pAl = g_slo + (size_t)(m0 + a_row) * 1024 + a_seg * 8;
    const __nv_bfloat16* pBh0 = gBh + (size_t)b_row * 1024 + n0 + b_seg * 8;
    const __nv_bfloat16* pBl0 = gBl + (size_t)b_row * 1024 + n0 + b_seg * 8;
    const __nv_bfloat16* pBh1 = pBh0 + 16 * 1024;
    const __nv_bfloat16* pBl1 = pBl0 + 16 * 1024;
    unsigned dA  = a_row * 80u + a_seg * 16u;
    unsigned dB0 = 20480u + b_row * 528u + b_seg * 16u;
    unsigned dB1 = 20480u + (b_row + 16) * 528u + b_seg * 16u;

    auto issue = [&](int ch, int buf) {
        unsigned k0 = ch * 32u;
        size_t kq = ch * 32u * 1024u;
        unsigned bo = sb + buf * BUFSZ;
        CP_ASYNC16(bo + dA,           pAh + k0);
        CP_ASYNC16(bo + dA + 10240u,  pAl + k0);
        CP_ASYNC16(bo + dB0,          pBh0 + kq);
        CP_ASYNC16(bo + dB0 + SZB,    pBl0 + kq);
        CP_ASYNC16(bo + dB1,          pBh1 + kq);
        CP_ASYNC16(bo + dB1 + SZB,    pBl1 + kq);
        CP_COMMIT();
    };

    float acc[2][8][4];
#pragma unroll
    for (int a = 0; a < 2; a++)
#pragma unroll
        for (int b = 0; b < 8; b++)
#pragma unroll
            for (int q = 0; q < 4; q++) acc[a][b][q] = 0.f;

    issue(0, 0);
    issue(1, 1);

    int buf = 0;
#pragma unroll 1
    for (int ch = 0; ch < 32; ch++) {
        if (ch < 31) { CP_WAIT1(); } else { CP_WAIT0(); }
        __syncthreads();
        unsigned base = sb + buf * BUFSZ;
#pragma unroll
        for (int k16 = 0; k16 < 32; k16 += 16) {
            unsigned a_h[2][4], a_l[2][4], b_h[4][4], b_l[4][4];
#pragma unroll
            for (int mt = 0; mt < 2; mt++) {
                unsigned off = base + ((warp_m + mt * 16 + fr) * 40 + k16 + fc8) * 2;
                LDSM4(a_h[mt], off);
                LDSM4(a_l[mt], off + 10240u);
            }
#pragma unroll
            for (int tp = 0; tp < 4; tp++) {
                unsigned off = base + 20480u
                    + ((k16 + vr) * 264 + warp_n + tp * 16 + vc8) * 2;
                LDSM4T(b_h[tp], off);
                LDSM4T(b_l[tp], off + SZB);
            }
            // pass-major: 16 independent MMAs per pass; per-acc order hh->hl->lh
#pragma unroll
            for (int mt = 0; mt < 2; mt++)
#pragma unroll
                for (int tp = 0; tp < 4; tp++)
#pragma unroll
                    for (int u = 0; u < 2; u++)
                        MMA_BF16v(acc[mt][tp * 2 + u], a_h[mt],
                                  b_h[tp][u], b_h[tp][u + 2]);
#pragma unroll
            for (int mt = 0; mt < 2; mt++)
#pragma unroll
                for (int tp = 0; tp < 4; tp++)
#pragma unroll
                    for (int u = 0; u < 2; u++)
                        MMA_BF16v(acc[mt][tp * 2 + u], a_h[mt],
                                  b_l[tp][u], b_l[tp][u + 2]);
#pragma unroll
            for (int mt = 0; mt < 2; mt++)
#pragma unroll
                for (int tp = 0; tp < 4; tp++)
#pragma unroll
                    for (int u = 0; u < 2; u++)
                        MMA_BF16v(acc[mt][tp * 2 + u], a_l[mt],
                                  b_h[tp][u], b_h[tp][u + 2]);
        }
        if (ch + 2 < 32) {
            int nb = buf + 2; if (nb >= 3) nb -= 3;
            issue(ch + 2, nb);
        }
        if (++buf == 3) buf = 0;
    }

    __nv_bfloat16* Dh = (widx == 0) ? g_qh : (widx == 1) ? g_kh : g_vh;
    __nv_bfloat16* Dl = (widx == 0) ? g_ql : (widx == 1) ? g_kl : g_vl;
#pragma unroll
    for (int mt = 0; mt < 2; mt++) {
#pragma unroll
        for (int j = 0; j < 8; j++) {
            int rg = m0 + warp_m + mt * 16 + gid;
            int cg = n0 + warp_n + j * 8 + tg * 2;
            float* a4 = acc[mt][j];
            if (widx == 3) {
                float b0 = aux[cg], b1 = aux[cg + 1];
                float v0 = 1.f / (1.f + __expf(-(a4[0] + b0)));
                float v1 = 1.f / (1.f + __expf(-(a4[1] + b1)));
                float v2 = 1.f / (1.f + __expf(-(a4[2] + b0)));
                float v3 = 1.f / (1.f + __expf(-(a4[3] + b1)));
                *(float2*)&g_g[(size_t)rg * 1024 + cg]       = make_float2(v0, v1);
                *(float2*)&g_g[(size_t)(rg + 8) * 1024 + cg] = make_float2(v2, v3);
            } else {
                float v0 = a4[0] * scale, v1 = a4[1] * scale;
                float v2 = a4[2] * scale, v3 = a4[3] * scale;
                *(unsigned*)&Dh[(size_t)rg * 1024 + cg]       = pk2(v0, v1);
                *(unsigned*)&Dh[(size_t)(rg + 8) * 1024 + cg] = pk2(v2, v3);
                *(unsigned*)&Dl[(size_t)rg * 1024 + cg]       = pk2(lores(v0), lores(v1));
                *(unsigned*)&Dl[(size_t)(rg + 8) * 1024 + cg] =
                    pk2(lores(v2), lores(v3));
            }
        }
    }
}

// ---------------------------------------------------------------------------
// Output GEMM: 256 thr, tile 128x64, BK=32, depth-3, pass-major. Grid (16,8).
// ---------------------------------------------------------------------------
__global__ __launch_bounds__(256) void gemm_out(float* __restrict__ Cext)
{
    extern __shared__ __nv_bfloat16 dsm[];
    constexpr unsigned SZB   = 32u * 72 * 2;          // 4608
    constexpr unsigned BUFSZ = 20480u + 2 * SZB;      // 29696

    const __nv_bfloat16* gBh = g_wh[4];
    const __nv_bfloat16* gBl = g_wl[4];

    int tid  = threadIdx.x;
    int lane = tid & 31, warp = tid >> 5;
    int gid  = lane >> 2, tg = lane & 3;
    int fr = lane & 15, fc8 = (lane >> 4) * 8;
    int vr = (lane >> 4) * 8 + (lane & 7);
    int vc8 = ((lane >> 3) & 1) * 8;
    int warp_m = (warp >> 1) * 32, warp_n = (warp & 1) * 32;
    int m0 = blockIdx.y * 128, n0 = blockIdx.x * 64;
    unsigned sb = cvta_s(dsm);

    auto issue = [&](int ch, int buf) {
        int k0 = ch * 32;
        unsigned bo = sb + buf * BUFSZ;
#pragma unroll
        for (int t = 0; t < 6; t++) {
            int s = tid + t * 256;
            unsigned dst;
            const __nv_bfloat16* src;
            if (s < 1024) {
                int mt = s >> 9, rem = s & 511;
                int row = rem >> 2, seg = rem & 3;
                dst = bo + mt * 10240u + row * 80u + seg * 16u;
                src = (mt ? g_olo : g_ohi) + (size_t)(m0 + row) * 1024 + k0 + seg * 8;
            } else {
                int ss = s - 1024;
                int mt = ss >> 8, rem = ss & 255;
                int row = rem >> 3, seg = rem & 7;
                dst = bo + 20480u + mt * SZB + row * 144u + seg * 16u;
                src = (mt ? gBl : gBh) + (size_t)(k0 + row) * 1024 + n0 + seg * 8;
            }
            CP_ASYNC16(dst, src);
        }
        CP_COMMIT();
    };

    float acc[2][4][4];
#pragma unroll
    for (int a = 0; a < 2; a++)
#pragma unroll
        for (int b = 0; b < 4; b++)
#pragma unroll
            for (int q = 0; q < 4; q++) acc[a][b][q] = 0.f;

    issue(0, 0);
    issue(1, 1);

    int buf = 0;
#pragma unroll 1
    for (int ch = 0; ch < 32; ch++) {
        if (ch < 31) { CP_WAIT1(); } else { CP_WAIT0(); }
        __syncthreads();
        unsigned base = sb + buf * BUFSZ;
#pragma unroll
        for (int k16 = 0; k16 < 32; k16 += 16) {
            unsigned a_h[2][4], a_l[2][4], b_h[2][4], b_l[2][4];
#pragma unroll
            for (int mt = 0; mt < 2; mt++) {
                unsigned off = base + ((warp_m + mt * 16 + fr) * 40 + k16 + fc8) * 2;
                LDSM4(a_h[mt], off);
                LDSM4(a_l[mt], off + 10240u);
            }
#pragma unroll
            for (int tp = 0; tp < 2; tp++) {
                unsigned off = base + 20480u
                    + ((k16 + vr) * 72 + warp_n + tp * 16 + vc8) * 2;
                LDSM4T(b_h[tp], off);
                LDSM4T(b_l[tp], off + SZB);
            }
            // pass-major (8 independent per pass)
#pragma unroll
            for (int mt = 0; mt < 2; mt++)
#pragma unroll
                for (int tp = 0; tp < 2; tp++)
#pragma unroll
                    for (int u = 0; u < 2; u++)
                        MMA_BF16v(acc[mt][tp * 2 + u], a_h[mt],
                                  b_h[tp][u], b_h[tp][u + 2]);
#pragma unroll
            for (int mt = 0; mt < 2; mt++)
#pragma unroll
                for (int tp = 0; tp < 2; tp++)
#pragma unroll
                    for (int u = 0; u < 2; u++)
                        MMA_BF16v(acc[mt][tp * 2 + u], a_h[mt],
                                  b_l[tp][u], b_l[tp][u + 2]);
#pragma unroll
            for (int mt = 0; mt < 2; mt++)
#pragma unroll
                for (int tp = 0; tp < 2; tp++)
#pragma unroll
                    for (int u = 0; u < 2; u++)
                        MMA_BF16v(acc[mt][tp * 2 + u], a_l[mt],
                                  b_h[tp][u], b_h[tp][u + 2]);
        }
        if (ch + 2 < 32) {
            int nb = buf + 2; if (nb >= 3) nb -= 3;
            issue(ch + 2, nb);
        }
        if (++buf == 3) buf = 0;
    }

#pragma unroll
    for (int mt = 0; mt < 2; mt++) {
#pragma unroll
        for (int j = 0; j < 4; j++) {
            int rg = m0 + warp_m + mt * 16 + gid;
            int cg = n0 + warp_n + j * 8 + tg * 2;
            float* a4 = acc[mt][j];
            *(float2*)&Cext[(size_t)rg * 1024 + cg]       = make_float2(a4[0], a4[1]);
            *(float2*)&Cext[(size_t)(rg + 8) * 1024 + cg] = make_float2(a4[2], a4[3]);
        }
    }
}

// ---------------------------------------------------------------------------
// Flash attention, depth-3 K/V pipeline, tp-pair pass-major MMA order.
// 256 thr, 128 queries/CTA. Grid (8, 16).
// ---------------------------------------------------------------------------
__global__ __launch_bounds__(256) void attn_kernel()
{
    extern __shared__ __nv_bfloat16 dsm[];
    int tid  = threadIdx.x;
    int lane = tid & 31, warp = tid >> 5;
    int gid  = lane >> 2, tg = lane & 3;
    int h  = blockIdx.y;
    int q0 = blockIdx.x * 128;
    int warp_m = warp * 16;
    int qrow = q0 + warp_m + gid;
    unsigned sb = cvta_s(dsm);

    int fr = lane & 15, fc8 = (lane >> 4) * 8;
    int vr = (lane >> 4) * 8 + (lane & 7);
    int vc8 = ((lane >> 3) & 1) * 8;

    auto issue_kv = [&](int kb, int buf) {
        int k0 = kb * 64;
        unsigned bo = buf * 36864u;
#pragma unroll
        for (int t = 0; t < 8; t++) {
            int s = tid + t * 256;
            int mt = s >> 9, rem = s & 511;
            int row = rem >> 3, seg = rem & 7;
            unsigned dst = sb + bo + mt * 9216u + row * 144u + seg * 16u;
            const __nv_bfloat16* src;
            if      (mt == 0) src = g_kh + (size_t)(k0 + row) * 1024 + h * 64 + seg * 8;
            else if (mt == 1) src = g_kl + (size_t)(k0 + row) * 1024 + h * 64 + seg * 8;
            else if (mt == 2) src = g_vh + (size_t)(k0 + row) * 1024 + h * 64 + seg * 8;
            else              src = g_vl + (size_t)(k0 + row) * 1024 + h * 64 + seg * 8;
            CP_ASYNC16(dst, src);
        }
        CP_COMMIT();
    };

    unsigned qh[4][4], ql[4][4];
    {
        const __nv_bfloat16* Qh = g_qh + (size_t)qrow * 1024 + h * 64;
        const __nv_bfloat16* Ql = g_ql + (size_t)qrow * 1024 + h * 64;
#pragma unroll
        for (int c = 0; c < 4; c++) {
            int kk = c * 16 + tg * 2;
            qh[c][0] = *(const unsigned*)(Qh + kk);
            qh[c][1] = *(const unsigned*)(Qh + 8 * 1024 + kk);
            qh[c][2] = *(const unsigned*)(Qh + kk + 8);
            qh[c][3] = *(const unsigned*)(Qh + 8 * 1024 + kk + 8);
            ql[c][0] = *(const unsigned*)(Ql + kk);
            ql[c][1] = *(const unsigned*)(Ql + 8 * 1024 + kk);
            ql[c][2] = *(const unsigned*)(Ql + kk + 8);
            ql[c][3] = *(const unsigned*)(Ql + 8 * 1024 + kk + 8);
        }
    }

    float m0 = -1e30f, m1 = -1e30f, l0 = 0.f, l1 = 0.f;
    float O[8][4] = {};

    issue_kv(0, 0);
    issue_kv(1, 1);

    int buf = 0;
#pragma unroll 1
    for (int kb = 0; kb < 16; kb++) {
        if (kb < 15) { CP_WAIT1(); } else { CP_WAIT0(); }
        __syncthreads();
        unsigned base = sb + buf * 36864u;
        int k0 = kb * 64;

        float S[8][4];
        {
            const float* bptr = g_bias + (size_t)h * NN + (size_t)qrow * 1024 + k0;
#pragma unroll
            for (int t = 0; t < 8; t++) {
                float2 b0 = *(const float2*)(bptr + 8 * t + 2 * tg);
                float2 b1 = *(const float2*)(bptr + 8 * 1024 + 8 * t + 2 * tg);
                S[t][0] = b0.x; S[t][1] = b0.y; S[t][2] = b1.x; S[t][3] = b1.y;
            }
        }
        // S += Q K^T  (tp-pairs, pass-major within pair: dep distance 4)
#pragma unroll
        for (int c = 0; c < 4; c++) {
            int kk = c * 16;
#pragma unroll
            for (int tpp = 0; tpp < 4; tpp += 2) {
                unsigned bh[2][4], bl[2][4];
#pragma unroll
                for (int j = 0; j < 2; j++) {
                    unsigned off = base + (((tpp + j) * 16 + fr) * 72 + kk + fc8) * 2;
                    LDSM4(bh[j], off);
                    LDSM4(bl[j], off + 9216u);
                }
#pragma unroll
                for (int j = 0; j < 2; j++)
#pragma unroll
                    for (int u = 0; u < 2; u++)
                        MMA_BF16v(S[(tpp + j) * 2 + u], qh[c],
                                  bh[j][u], bh[j][u + 2]);
#pragma unroll
                for (int j = 0; j < 2; j++)
#pragma unroll
                    for (int u = 0; u < 2; u++)
                        MMA_BF16v(S[(tpp + j) * 2 + u], qh[c],
                                  bl[j][u], bl[j][u + 2]);
#pragma unroll
                for (int j = 0; j < 2; j++)
#pragma unroll
                    for (int u = 0; u < 2; u++)
                        MMA_BF16v(S[(tpp + j) * 2 + u], ql[c],
                                  bh[j][u], bh[j][u + 2]);
            }
        }

        float rm0 = -1e30f, rm1 = -1e30f;
#pragma unroll
        for (int t = 0; t < 8; t++) {
            rm0 = fmaxf(rm0, fmaxf(S[t][0], S[t][1]));
            rm1 = fmaxf(rm1, fmaxf(S[t][2], S[t][3]));
        }
        rm0 = fmaxf(rm0, __shfl_xor_sync(0xffffffffu, rm0, 1));
        rm0 = fmaxf(rm0, __shfl_xor_sync(0xffffffffu, rm0, 2));
        rm1 = fmaxf(rm1, __shfl_xor_sync(0xffffffffu, rm1, 1));
        rm1 = fmaxf(rm1, __shfl_xor_sync(0xffffffffu, rm1, 2));
        float mn0 = fmaxf(m0, rm0), mn1 = fmaxf(m1, rm1);
        float c0 = __expf(m0 - mn0), c1 = __expf(m1 - mn1);
        m0 = mn0; m1 = mn1;
        float ps0 = 0.f, ps1 = 0.f;
#pragma unroll
        for (int t = 0; t < 8; t++) {
            S[t][0] = __expf(S[t][0] - mn0);
            S[t][1] = __expf(S[t][1] - mn0);
            S[t][2] = __expf(S[t][2] - mn1);
            S[t][3] = __expf(S[t][3] - mn1);
            ps0 += S[t][0] + S[t][1];
            ps1 += S[t][2] + S[t][3];
        }
        ps0 += __shfl_xor_sync(0xffffffffu, ps0, 1);
        ps0 += __shfl_xor_sync(0xffffffffu, ps0, 2);
        ps1 += __shfl_xor_sync(0xffffffffu, ps1, 1);
        ps1 += __shfl_xor_sync(0xffffffffu, ps1, 2);
        l0 = l0 * c0 + ps0;
        l1 = l1 * c1 + ps1;
#pragma unroll
        for (int t = 0; t < 8; t++) {
            O[t][0] *= c0; O[t][1] *= c0; O[t][2] *= c1; O[t][3] *= c1;
        }

        unsigned ph[4][4], pl[4][4];
#pragma unroll
        for (int c = 0; c < 4; c++) {
            int t0 = 2 * c, t1 = 2 * c + 1;
            ph[c][0] = pk2(S[t0][0], S[t0][1]);
            ph[c][1] = pk2(S[t0][2], S[t0][3]);
            ph[c][2] = pk2(S[t1][0], S[t1][1]);
            ph[c][3] = pk2(S[t1][2], S[t1][3]);
            pl[c][0] = pk2(lores(S[t0][0]), lores(S[t0][1]));
            pl[c][1] = pk2(lores(S[t0][2]), lores(S[t0][3]));
            pl[c][2] = pk2(lores(S[t1][0]), lores(S[t1][1]));
            pl[c][3] = pk2(lores(S[t1][2]), lores(S[t1][3]));
        }

        // O += P V  (tp-pairs, pass-major within pair)
#pragma unroll
        for (int c = 0; c < 4; c++) {
#pragma unroll
            for (int tpp = 0; tpp < 4; tpp += 2) {
                unsigned bh[2][4], bl[2][4];
#pragma unroll
                for (int j = 0; j < 2; j++) {
                    unsigned off = base + 18432u
                        + ((c * 16 + vr) * 72 + (tpp + j) * 16 + vc8) * 2;
                    LDSM4T(bh[j], off);
                    LDSM4T(bl[j], off + 9216u);
                }
#pragma unroll
                for (int j = 0; j < 2; j++)
#pragma unroll
                    for (int u = 0; u < 2; u++)
                        MMA_BF16v(O[(tpp + j) * 2 + u], ph[c],
                                  bh[j][u], bh[j][u + 2]);
#pragma unroll
                for (int j = 0; j < 2; j++)
#pragma unroll
                    for (int u = 0; u < 2; u++)
                        MMA_BF16v(O[(tpp + j) * 2 + u], ph[c],
                                  bl[j][u], bl[j][u + 2]);
#pragma unroll
                for (int j = 0; j < 2; j++)
#pragma unroll
                    for (int u = 0; u < 2; u++)
                        MMA_BF16v(O[(tpp + j) * 2 + u], pl[c],
                                  bh[j][u], bh[j][u + 2]);
            }
        }
        if (kb + 2 < 16) {
            int nb = buf + 2; if (nb >= 3) nb -= 3;
            issue_kv(kb + 2, nb);
        }
        if (++buf == 3) buf = 0;
    }

    float inv0 = 1.f / l0, inv1 = 1.f / l1;
#pragma unroll
    for (int t = 0; t < 8; t++) {
        int col = h * 64 + 8 * t + 2 * tg;
        size_t o0 = (size_t)qrow * 1024 + col;
        size_t o1 = o0 + 8 * 1024;
        float2 gg0 = *(const float2*)(g_g + o0);
        float2 gg1 = *(const float2*)(g_g + o1);
        float v0 = O[t][0] * inv0 * gg0.x;
        float v1 = O[t][1] * inv0 * gg0.y;
        float v2 = O[t][2] * inv1 * gg1.x;
        float v3 = O[t][3] * inv1 * gg1.y;
        *(unsigned*)(g_ohi + o0) = pk2(v0, v1);
        *(unsigned*)(g_ohi + o1) = pk2(v2, v3);
        *(unsigned*)(g_olo + o0) = pk2(lores(v0), lores(v1));
        *(unsigned*)(g_olo + o1) = pk2(lores(v2), lores(v3));
    }
}

// ---------------------------------------------------------------------------
extern "C" void kernel_launch(void* const* d_in, const int* in_sizes, int n_in,
                              void* d_out, int out_size)
{
    const float* single = (const float*)d_in[0];
    const float* pw     = (const float*)d_in[1];
    const float* gamma  = (const float*)d_in[2];
    const float* beta   = (const float*)d_in[3];
    const float* Wb     = (const float*)d_in[4];
    const float* Wq     = (const float*)d_in[5];
    const float* Wk     = (const float*)d_in[6];
    const float* Wv     = (const float*)d_in[7];
    const float* Wg     = (const float*)d_in[8];
    const float* bg     = (const float*)d_in[9];
    const float* Wo     = (const float*)d_in[10];
    float* out = (float*)d_out;

    const int QKVG_SMEM = 3 * 54272;   // 162816
    const int OUT_SMEM  = 3 * 29696;   // 89088
    const int ATTN_SMEM = 3 * 36864;   // 110592
    cudaFuncSetAttribute(gemm_qkvg,
        cudaFuncAttributeMaxDynamicSharedMemorySize, QKVG_SMEM);
    cudaFuncSetAttribute(gemm_out,
        cudaFuncAttributeMaxDynamicSharedMemorySize, OUT_SMEM);
    cudaFuncSetAttribute(attn_kernel,
        cudaFuncAttributeMaxDynamicSharedMemorySize, ATTN_SMEM);

    bias_setup<<<1, 128>>>(gamma, beta, Wb);
    dim3 bgrid(16, 1024);
    bias_kernel<<<bgrid, 256>>>(pw);

    dim3 cgrid(1024, 6);
    conv_all<<<cgrid, 256>>>(single, Wq, Wk, Wv, Wg, Wo);

    dim3 ggrid(4, 8, 4);   // 128 CTAs
    gemm_qkvg<<<ggrid, 512, QKVG_SMEM>>>(bg);

    dim3 agrid(8, 16);
    attn_kernel<<<agrid, 256, ATTN_SMEM>>>();

    dim3 ogrid(16, 8);     // 128 CTAs
    gemm_out<<<ogrid, 256, OUT_SMEM>>>(out);
}

// round 15
// speedup vs baseline: 1.6408x; 1.0964x over previous
#include <cuda_runtime.h>
#include <cuda_bf16.h>
#include <cuda_fp16.h>
#include <cstdint>

#define NN (1024u*1024u)

// scratch (device globals: allocation-free)
__device__ float g_bias[16u*1024u*1024u]; // [h][i][j]
__device__ float g_g [NN];                // gates fp32 [token][dim_inner]
__device__ __half g_sh[NN];               // single_repr fp16 (hi only) [m][k]
__device__ __half g_wfh[5][NN], g_wfl[5][NN]; // W [k][n] fp16 hi/lo (natural)
__device__ __half g_oh[NN];               // gated attn out fp16 (hi only)
__device__ __nv_bfloat16 g_qh[NN], g_ql[NN];  // Q bf16 hi/lo [tok][d] *0.125
__device__ __nv_bfloat16 g_kh[NN], g_kl[NN];  // K bf16 hi/lo
__device__ __nv_bfloat16 g_vh[NN], g_vl[NN];  // V bf16 hi/lo
__device__ __nv_bfloat16 g_wbth[16*128], g_wbtl[16*128]; // (gamma*Wb)^T [h][p]
__device__ float g_binit[16];                            // beta @ Wb

__device__ __forceinline__ unsigned pk2(float a, float b) {
    __nv_bfloat162 t = __floats2bfloat162_rn(a, b);
    return *reinterpret_cast<unsigned*>(&t);
}
__device__ __forceinline__ float lores(float a) {
    return a - __bfloat162float(__float2bfloat16(a));
}
__device__ __forceinline__ unsigned pkh2(float a, float b) {
    __half2 t = __floats2half2_rn(a, b);
    return *reinterpret_cast<unsigned*>(&t);
}
__device__ __forceinline__ float loresh(float a) {
    return a - __half2float(__float2half_rn(a));
}
__device__ __forceinline__ unsigned cvta_s(const void* p) {
    return (unsigned)__cvta_generic_to_shared(p);
}

#define MMA_BF16v(c, a, b0, b1) asm volatile( \
    "mma.sync.aligned.m16n8k16.row.col.f32.bf16.bf16.f32 " \
    "{%0,%1,%2,%3},{%4,%5,%6,%7},{%8,%9},{%0,%1,%2,%3};" \
    : "+f"((c)[0]), "+f"((c)[1]), "+f"((c)[2]), "+f"((c)[3]) \
    : "r"((a)[0]), "r"((a)[1]), "r"((a)[2]), "r"((a)[3]), \
      "r"(b0), "r"(b1))
#define MMA_F16v(c, a, b0, b1) asm volatile( \
    "mma.sync.aligned.m16n8k16.row.col.f32.f16.f16.f32 " \
    "{%0,%1,%2,%3},{%4,%5,%6,%7},{%8,%9},{%0,%1,%2,%3};" \
    : "+f"((c)[0]), "+f"((c)[1]), "+f"((c)[2]), "+f"((c)[3]) \
    : "r"((a)[0]), "r"((a)[1]), "r"((a)[2]), "r"((a)[3]), \
      "r"(b0), "r"(b1))
#define LDSM4(R, addr) asm volatile( \
    "ldmatrix.sync.aligned.m8n8.x4.shared.b16 {%0,%1,%2,%3}, [%4];" \
    : "=r"((R)[0]), "=r"((R)[1]), "=r"((R)[2]), "=r"((R)[3]) : "r"(addr))
#define LDSM4T(R, addr) asm volatile( \
    "ldmatrix.sync.aligned.m8n8.x4.trans.shared.b16 {%0,%1,%2,%3}, [%4];" \
    : "=r"((R)[0]), "=r"((R)[1]), "=r"((R)[2]), "=r"((R)[3]) : "r"(addr))
#define CP_ASYNC16(dst, src) asm volatile( \
    "cp.async.cg.shared.global [%0], [%1], 16;" :: "r"(dst), "l"(src) : "memory")
#define CP_COMMIT() asm volatile("cp.async.commit_group;" ::: "memory")
#define CP_WAIT1()  asm volatile("cp.async.wait_group 1;" ::: "memory")
#define CP_WAIT0()  asm volatile("cp.async.wait_group 0;" ::: "memory")

// ---------------------------------------------------------------------------
// One-time prep: (gamma*W_bias)^T as bf16 hi/lo, and beta@W_bias.
// ---------------------------------------------------------------------------
__global__ void bias_setup(const float* __restrict__ gamma,
                           const float* __restrict__ beta,
                           const float* __restrict__ Wb)
{
    int tid = threadIdx.x;
    for (int idx = tid; idx < 2048; idx += 128) {
        int p = idx >> 4, h = idx & 15;
        float w = gamma[p] * Wb[idx];
        __nv_bfloat16 hi = __float2bfloat16(w);
        g_wbth[h * 128 + p] = hi;
        g_wbtl[h * 128 + p] = __float2bfloat16(w - __bfloat162float(hi));
    }
    if (tid < 16) {
        float s = 0.f;
        for (int p = 0; p < 128; p++) s += beta[p] * Wb[p * 16 + tid];
        g_binit[tid] = s;
    }
}

// ---------------------------------------------------------------------------
// Bias kernel: LN (SIMT fp32 stats) + 128->16 projection on tensor cores.
// (unchanged numerics: bf16 3-pass)
// ---------------------------------------------------------------------------
__global__ __launch_bounds__(256) void bias_kernel(const float* __restrict__ pw)
{
    __shared__ __nv_bfloat16 sXh[64][136], sXl[64][136];
    __shared__ __nv_bfloat16 sWh[16][136], sWl[16][136];
    __shared__ float stage[16][64];
    __shared__ float sbin[16];

    int tid  = threadIdx.x;
    int lane = tid & 31, warp = tid >> 5;
    int i  = blockIdx.y;
    int j0 = blockIdx.x * 64;

    const float4* rowp = (const float4*)(pw
        + ((size_t)i * 1024 + j0 + warp * 8) * 128) + lane;
    float4 x[8];
#pragma unroll
    for (int rr = 0; rr < 8; rr++) x[rr] = rowp[rr * 32];

    for (int idx = tid; idx < 2048; idx += 256) {
        int h = idx >> 7, p = idx & 127;
        sWh[h][p] = g_wbth[idx];
        sWl[h][p] = g_wbtl[idx];
    }
    if (tid < 16) sbin[tid] = g_binit[tid];

#pragma unroll
    for (int rr = 0; rr < 8; rr++) {
        float s  = x[rr].x + x[rr].y + x[rr].z + x[rr].w;
        float ss = x[rr].x*x[rr].x + x[rr].y*x[rr].y
                 + x[rr].z*x[rr].z + x[rr].w*x[rr].w;
#pragma unroll
        for (int off = 16; off >= 1; off >>= 1) {
            s  += __shfl_xor_sync(0xffffffffu, s,  off);
            ss += __shfl_xor_sync(0xffffffffu, ss, off);
        }
        float mu  = s * 0.0078125f;
        float var = ss * 0.0078125f - mu * mu;
        float rs  = rsqrtf(var + 1e-5f);
        float y0 = (x[rr].x - mu) * rs, y1 = (x[rr].y - mu) * rs;
        float y2 = (x[rr].z - mu) * rs, y3 = (x[rr].w - mu) * rs;
        int r = warp * 8 + rr;
        *(uint2*)&sXh[r][lane * 4] = make_uint2(pk2(y0, y1), pk2(y2, y3));
        *(uint2*)&sXl[r][lane * 4] =
            make_uint2(pk2(lores(y0), lores(y1)), pk2(lores(y2), lores(y3)));
    }
    __syncthreads();

    if (warp < 4) {
        int gid  = lane >> 2, tg = lane & 3;
        float acc[2][4] = {};
        int warp_m = warp * 16;
        unsigned aXh = cvta_s(sXh), aXl = cvta_s(sXl);
        unsigned aWh = cvta_s(sWh), aWl = cvta_s(sWl);
        int fr = lane & 15, fc = lane >> 4;
#pragma unroll
        for (int c = 0; c < 8; c++) {
            int kk = c * 16;
            unsigned ah[4], al[4], bh[4], bl[4];
            LDSM4(ah, aXh + ((warp_m + fr) * 136 + kk + fc * 8) * 2);
            LDSM4(al, aXl + ((warp_m + fr) * 136 + kk + fc * 8) * 2);
            LDSM4(bh, aWh + ((fr) * 136 + kk + fc * 8) * 2);
            LDSM4(bl, aWl + ((fr) * 136 + kk + fc * 8) * 2);
#pragma unroll
            for (int t = 0; t < 2; t++)
                MMA_BF16v(acc[t], ah, bh[t], bh[t + 2]);
#pragma unroll
            for (int t = 0; t < 2; t++)
                MMA_BF16v(acc[t], ah, bl[t], bl[t + 2]);
#pragma unroll
            for (int t = 0; t < 2; t++)
                MMA_BF16v(acc[t], al, bh[t], bh[t + 2]);
        }
#pragma unroll
        for (int t = 0; t < 2; t++) {
            int hc = t * 8 + tg * 2;
            int r  = warp_m + gid;
            stage[hc][r]         = acc[t][0];
            stage[hc + 1][r]     = acc[t][1];
            stage[hc][r + 8]     = acc[t][2];
            stage[hc + 1][r + 8] = acc[t][3];
        }
    }
    __syncthreads();
    size_t obase = (size_t)i * 1024 + j0;
    for (int e = tid; e < 1024; e += 256) {
        int hh = e >> 6, j = e & 63;
        g_bias[(size_t)hh * NN + obase + j] = stage[hh][j] + sbin[hh];
    }
}

// ---------------------------------------------------------------------------
// Convert: single -> fp16 hi only; weights -> fp16 hi/lo.
// ---------------------------------------------------------------------------
__global__ __launch_bounds__(256) void conv_all(
    const float* __restrict__ s0, const float* __restrict__ s1,
    const float* __restrict__ s2, const float* __restrict__ s3,
    const float* __restrict__ s4, const float* __restrict__ s5)
{
    const float* srcs[6] = {s0, s1, s2, s3, s4, s5};
    const float* src = srcs[blockIdx.y];
    unsigned i = blockIdx.x * 256u + threadIdx.x;
    float4 v = ((const float4*)src)[i];
    if (blockIdx.y == 0) {
        *(unsigned*)(g_sh + 4u*i)     = pkh2(v.x, v.y);
        *(unsigned*)(g_sh + 4u*i + 2) = pkh2(v.z, v.w);
    } else {
        __half* Dh = g_wfh[blockIdx.y - 1];
        __half* Dl = g_wfl[blockIdx.y - 1];
        *(unsigned*)(Dh + 4u*i)     = pkh2(v.x, v.y);
        *(unsigned*)(Dh + 4u*i + 2) = pkh2(v.z, v.w);
        *(unsigned*)(Dl + 4u*i)     = pkh2(loresh(v.x), loresh(v.y));
        *(unsigned*)(Dl + 4u*i + 2) = pkh2(loresh(v.z), loresh(v.w));
    }
}

// ---------------------------------------------------------------------------
// QKVG GEMM: fp16 2-pass (A=hi only, B=hi+lo). 512 thr, tile 128x256, BK=32,
// depth-3 pipeline, one barrier/chunk. Grid (4, 8, 4) = 128 CTAs.
// smem/buf: A 10240 | Bh 16896 | Bl 16896 = 44032; x3 = 132096.
// ---------------------------------------------------------------------------
__global__ __launch_bounds__(512, 1) void gemm_qkvg(const float* __restrict__ aux)
{
    extern __shared__ __half dsm[];
    constexpr unsigned SZB   = 16896u;   // 32 * 264 * 2
    constexpr unsigned BUFSZ = 44032u;

    int widx = blockIdx.z;
    float scale = (widx == 0) ? 0.125f : 1.0f;
    const __half* gBh = g_wfh[widx];
    const __half* gBl = g_wfl[widx];

    int tid  = threadIdx.x;
    int lane = tid & 31, warp = tid >> 5;
    int gid  = lane >> 2, tg = lane & 3;
    int fr = lane & 15, fc8 = (lane >> 4) * 8;
    int vr = (lane >> 4) * 8 + (lane & 7);
    int vc8 = ((lane >> 3) & 1) * 8;
    int warp_m = (warp >> 2) * 32, warp_n = (warp & 3) * 64;
    int m0 = blockIdx.y * 128, n0 = blockIdx.x * 256;
    unsigned sb = cvta_s(dsm);

    int a_row = (tid & 511) >> 2, a_seg = tid & 3;
    int b_row = (tid & 1023) >> 5, b_seg = tid & 31;

    const __half* pA   = g_sh + (size_t)(m0 + a_row) * 1024 + a_seg * 8;
    const __half* pBh0 = gBh + (size_t)b_row * 1024 + n0 + b_seg * 8;
    const __half* pBl0 = gBl + (size_t)b_row * 1024 + n0 + b_seg * 8;
    const __half* pBh1 = pBh0 + 16 * 1024;
    const __half* pBl1 = pBl0 + 16 * 1024;
    unsigned dA  = a_row * 80u + a_seg * 16u;
    unsigned dB0 = 10240u + b_row * 528u + b_seg * 16u;
    unsigned dB1 = 10240u + (b_row + 16) * 528u + b_seg * 16u;

    auto issue = [&](int ch, int buf) {
        unsigned k0 = ch * 32u;
        size_t kq = ch * 32u * 1024u;
        unsigned bo = sb + buf * BUFSZ;
        CP_ASYNC16(bo + dA,        pA + k0);
        CP_ASYNC16(bo + dB0,       pBh0 + kq);
        CP_ASYNC16(bo + dB0 + SZB, pBl0 + kq);
        CP_ASYNC16(bo + dB1,       pBh1 + kq);
        CP_ASYNC16(bo + dB1 + SZB, pBl1 + kq);
        CP_COMMIT();
    };

    float acc[2][8][4];
#pragma unroll
    for (int a = 0; a < 2; a++)
#pragma unroll
        for (int b = 0; b < 8; b++)
#pragma unroll
            for (int q = 0; q < 4; q++) acc[a][b][q] = 0.f;

    issue(0, 0);
    issue(1, 1);

    int buf = 0;
#pragma unroll 1
    for (int ch = 0; ch < 32; ch++) {
        if (ch < 31) { CP_WAIT1(); } else { CP_WAIT0(); }
        __syncthreads();
        unsigned base = sb + buf * BUFSZ;
#pragma unroll
        for (int k16 = 0; k16 < 32; k16 += 16) {
            unsigned a_h[2][4], b_h[4][4], b_l[4][4];
#pragma unroll
            for (int mt = 0; mt < 2; mt++) {
                unsigned off = base + ((warp_m + mt * 16 + fr) * 40 + k16 + fc8) * 2;
                LDSM4(a_h[mt], off);
            }
#pragma unroll
            for (int tp = 0; tp < 4; tp++) {
                unsigned off = base + 10240u
                    + ((k16 + vr) * 264 + warp_n + tp * 16 + vc8) * 2;
                LDSM4T(b_h[tp], off);
                LDSM4T(b_l[tp], off + SZB);
            }
            // 2-pass fp16: per-acc order hh -> hl
#pragma unroll
            for (int mt = 0; mt < 2; mt++)
#pragma unroll
                for (int tp = 0; tp < 4; tp++)
#pragma unroll
                    for (int u = 0; u < 2; u++)
                        MMA_F16v(acc[mt][tp * 2 + u], a_h[mt],
                                 b_h[tp][u], b_h[tp][u + 2]);
#pragma unroll
            for (int mt = 0; mt < 2; mt++)
#pragma unroll
                for (int tp = 0; tp < 4; tp++)
#pragma unroll
                    for (int u = 0; u < 2; u++)
                        MMA_F16v(acc[mt][tp * 2 + u], a_h[mt],
                                 b_l[tp][u], b_l[tp][u + 2]);
        }
        if (ch + 2 < 32) {
            int nb = buf + 2; if (nb >= 3) nb -= 3;
            issue(ch + 2, nb);
        }
        if (++buf == 3) buf = 0;
    }

    __nv_bfloat16* Dh = (widx == 0) ? g_qh : (widx == 1) ? g_kh : g_vh;
    __nv_bfloat16* Dl = (widx == 0) ? g_ql : (widx == 1) ? g_kl : g_vl;
#pragma unroll
    for (int mt = 0; mt < 2; mt++) {
#pragma unroll
        for (int j = 0; j < 8; j++) {
            int rg = m0 + warp_m + mt * 16 + gid;
            int cg = n0 + warp_n + j * 8 + tg * 2;
            float* a4 = acc[mt][j];
            if (widx == 3) {
                float b0 = aux[cg], b1 = aux[cg + 1];
                float v0 = 1.f / (1.f + __expf(-(a4[0] + b0)));
                float v1 = 1.f / (1.f + __expf(-(a4[1] + b1)));
                float v2 = 1.f / (1.f + __expf(-(a4[2] + b0)));
                float v3 = 1.f / (1.f + __expf(-(a4[3] + b1)));
                *(float2*)&g_g[(size_t)rg * 1024 + cg]       = make_float2(v0, v1);
                *(float2*)&g_g[(size_t)(rg + 8) * 1024 + cg] = make_float2(v2, v3);
            } else {
                float v0 = a4[0] * scale, v1 = a4[1] * scale;
                float v2 = a4[2] * scale, v3 = a4[3] * scale;
                *(unsigned*)&Dh[(size_t)rg * 1024 + cg]       = pk2(v0, v1);
                *(unsigned*)&Dh[(size_t)(rg + 8) * 1024 + cg] = pk2(v2, v3);
                *(unsigned*)&Dl[(size_t)rg * 1024 + cg]       = pk2(lores(v0), lores(v1));
                *(unsigned*)&Dl[(size_t)(rg + 8) * 1024 + cg] =
                    pk2(lores(v2), lores(v3));
            }
        }
    }
}

// ---------------------------------------------------------------------------
// Output GEMM: fp16 2-pass (A=g_oh hi only, B=Wo hi+lo). 256 thr, 128x64 tile,
// BK=32, depth-3. Grid (16,8)=128.
// smem/buf: A 10240 | Bh 4608 | Bl 4608 = 19456; x3 = 58368.
// ---------------------------------------------------------------------------
__global__ __launch_bounds__(256) void gemm_out(float* __restrict__ Cext)
{
    extern __shared__ __half dsm[];
    constexpr unsigned SZB   = 32u * 72 * 2;          // 4608
    constexpr unsigned BUFSZ = 10240u + 2 * SZB;      // 19456

    const __half* gBh = g_wfh[4];
    const __half* gBl = g_wfl[4];

    int tid  = threadIdx.x;
    int lane = tid & 31, warp = tid >> 5;
    int gid  = lane >> 2, tg = lane & 3;
    int fr = lane & 15, fc8 = (lane >> 4) * 8;
    int vr = (lane >> 4) * 8 + (lane & 7);
    int vc8 = ((lane >> 3) & 1) * 8;
    int warp_m = (warp >> 1) * 32, warp_n = (warp & 1) * 32;
    int m0 = blockIdx.y * 128, n0 = blockIdx.x * 64;
    unsigned sb = cvta_s(dsm);

    auto issue = [&](int ch, int buf) {
        int k0 = ch * 32;
        unsigned bo = sb + buf * BUFSZ;
#pragma unroll
        for (int t = 0; t < 4; t++) {
            int s = tid + t * 256;
            unsigned dst;
            const __half* src;
            if (s < 512) {
                int row = s >> 2, seg = s & 3;
                dst = bo + row * 80u + seg * 16u;
                src = g_oh + (size_t)(m0 + row) * 1024 + k0 + seg * 8;
            } else {
                int ss = s - 512;                 // 0..511
                int mt = ss >> 8, rem = ss & 255;
                int row = rem >> 3, seg = rem & 7;
                dst = bo + 10240u + mt * SZB + row * 144u + seg * 16u;
                src = (mt ? gBl : gBh) + (size_t)(k0 + row) * 1024 + n0 + seg * 8;
            }
            CP_ASYNC16(dst, src);
        }
        CP_COMMIT();
    };

    float acc[2][4][4];
#pragma unroll
    for (int a = 0; a < 2; a++)
#pragma unroll
        for (int b = 0; b < 4; b++)
#pragma unroll
            for (int q = 0; q < 4; q++) acc[a][b][q] = 0.f;

    issue(0, 0);
    issue(1, 1);

    int buf = 0;
#pragma unroll 1
    for (int ch = 0; ch < 32; ch++) {
        if (ch < 31) { CP_WAIT1(); } else { CP_WAIT0(); }
        __syncthreads();
        unsigned base = sb + buf * BUFSZ;
#pragma unroll
        for (int k16 = 0; k16 < 32; k16 += 16) {
            unsigned a_h[2][4], b_h[2][4], b_l[2][4];
#pragma unroll
            for (int mt = 0; mt < 2; mt++) {
                unsigned off = base + ((warp_m + mt * 16 + fr) * 40 + k16 + fc8) * 2;
                LDSM4(a_h[mt], off);
            }
#pragma unroll
            for (int tp = 0; tp < 2; tp++) {
                unsigned off = base + 10240u
                    + ((k16 + vr) * 72 + warp_n + tp * 16 + vc8) * 2;
                LDSM4T(b_h[tp], off);
                LDSM4T(b_l[tp], off + SZB);
            }
#pragma unroll
            for (int mt = 0; mt < 2; mt++)
#pragma unroll
                for (int tp = 0; tp < 2; tp++)
#pragma unroll
                    for (int u = 0; u < 2; u++)
                        MMA_F16v(acc[mt][tp * 2 + u], a_h[mt],
                                 b_h[tp][u], b_h[tp][u + 2]);
#pragma unroll
            for (int mt = 0; mt < 2; mt++)
#pragma unroll
                for (int tp = 0; tp < 2; tp++)
#pragma unroll
                    for (int u = 0; u < 2; u++)
                        MMA_F16v(acc[mt][tp * 2 + u], a_h[mt],
                                 b_l[tp][u], b_l[tp][u + 2]);
        }
        if (ch + 2 < 32) {
            int nb = buf + 2; if (nb >= 3) nb -= 3;
            issue(ch + 2, nb);
        }
        if (++buf == 3) buf = 0;
    }

#pragma unroll
    for (int mt = 0; mt < 2; mt++) {
#pragma unroll
        for (int j = 0; j < 4; j++) {
            int rg = m0 + warp_m + mt * 16 + gid;
            int cg = n0 + warp_n + j * 8 + tg * 2;
            float* a4 = acc[mt][j];
            *(float2*)&Cext[(size_t)rg * 1024 + cg]       = make_float2(a4[0], a4[1]);
            *(float2*)&Cext[(size_t)(rg + 8) * 1024 + cg] = make_float2(a4[2], a4[3]);
        }
    }
}

// ---------------------------------------------------------------------------
// Flash attention, depth-3 K/V pipeline, bf16 3-pass (numerics unchanged).
// Epilogue now writes fp16 hi only (g_oh) for the output GEMM.
// 256 thr, 128 queries/CTA. Grid (8, 16).
// ---------------------------------------------------------------------------
__global__ __launch_bounds__(256) void attn_kernel()
{
    extern __shared__ __nv_bfloat16 dsmb[];
    int tid  = threadIdx.x;
    int lane = tid & 31, warp = tid >> 5;
    int gid  = lane >> 2, tg = lane & 3;
    int h  = blockIdx.y;
    int q0 = blockIdx.x * 128;
    int warp_m = warp * 16;
    int qrow = q0 + warp_m + gid;
    unsigned sb = cvta_s(dsmb);

    int fr = lane & 15, fc8 = (lane >> 4) * 8;
    int vr = (lane >> 4) * 8 + (lane & 7);
    int vc8 = ((lane >> 3) & 1) * 8;

    auto issue_kv = [&](int kb, int buf) {
        int k0 = kb * 64;
        unsigned bo = buf * 36864u;
#pragma unroll
        for (int t = 0; t < 8; t++) {
            int s = tid + t * 256;
            int mt = s >> 9, rem = s & 511;
            int row = rem >> 3, seg = rem & 7;
            unsigned dst = sb + bo + mt * 9216u + row * 144u + seg * 16u;
            const __nv_bfloat16* src;
            if      (mt == 0) src = g_kh + (size_t)(k0 + row) * 1024 + h * 64 + seg * 8;
            else if (mt == 1) src = g_kl + (size_t)(k0 + row) * 1024 + h * 64 + seg * 8;
            else if (mt == 2) src = g_vh + (size_t)(k0 + row) * 1024 + h * 64 + seg * 8;
            else              src = g_vl + (size_t)(k0 + row) * 1024 + h * 64 + seg * 8;
            CP_ASYNC16(dst, src);
        }
        CP_COMMIT();
    };

    unsigned qh[4][4], ql[4][4];
    {
        const __nv_bfloat16* Qh = g_qh + (size_t)qrow * 1024 + h * 64;
        const __nv_bfloat16* Ql = g_ql + (size_t)qrow * 1024 + h * 64;
#pragma unroll
        for (int c = 0; c < 4; c++) {
            int kk = c * 16 + tg * 2;
            qh[c][0] = *(const unsigned*)(Qh + kk);
            qh[c][1] = *(const unsigned*)(Qh + 8 * 1024 + kk);
            qh[c][2] = *(const unsigned*)(Qh + kk + 8);
            qh[c][3] = *(const unsigned*)(Qh + 8 * 1024 + kk + 8);
            ql[c][0] = *(const unsigned*)(Ql + kk);
            ql[c][1] = *(const unsigned*)(Ql + 8 * 1024 + kk);
            ql[c][2] = *(const unsigned*)(Ql + kk + 8);
            ql[c][3] = *(const unsigned*)(Ql + 8 * 1024 + kk + 8);
        }
    }

    float m0 = -1e30f, m1 = -1e30f, l0 = 0.f, l1 = 0.f;
    float O[8][4] = {};

    issue_kv(0, 0);
    issue_kv(1, 1);

    int buf = 0;
#pragma unroll 1
    for (int kb = 0; kb < 16; kb++) {
        if (kb < 15) { CP_WAIT1(); } else { CP_WAIT0(); }
        __syncthreads();
        unsigned base = sb + buf * 36864u;
        int k0 = kb * 64;

        float S[8][4];
        {
            const float* bptr = g_bias + (size_t)h * NN + (size_t)qrow * 1024 + k0;
#pragma unroll
            for (int t = 0; t < 8; t++) {
                float2 b0 = *(const float2*)(bptr + 8 * t + 2 * tg);
                float2 b1 = *(const float2*)(bptr + 8 * 1024 + 8 * t + 2 * tg);
                S[t][0] = b0.x; S[t][1] = b0.y; S[t][2] = b1.x; S[t][3] = b1.y;
            }
        }
#pragma unroll
        for (int c = 0; c < 4; c++) {
            int kk = c * 16;
#pragma unroll
            for (int tpp = 0; tpp < 4; tpp += 2) {
                unsigned bh[2][4], bl[2][4];
#pragma unroll
                for (int j = 0; j < 2; j++) {
                    unsigned off = base + (((tpp + j) * 16 + fr) * 72 + kk + fc8) * 2;
                    LDSM4(bh[j], off);
                    LDSM4(bl[j], off + 9216u);
                }
#pragma unroll
                for (int j = 0; j < 2; j++)
#pragma unroll
                    for (int u = 0; u < 2; u++)
                        MMA_BF16v(S[(tpp + j) * 2 + u], qh[c],
                                  bh[j][u], bh[j][u + 2]);
#pragma unroll
                for (int j = 0; j < 2; j++)
#pragma unroll
                    for (int u = 0; u < 2; u++)
                        MMA_BF16v(S[(tpp + j) * 2 + u], qh[c],
                                  bl[j][u], bl[j][u + 2]);
#pragma unroll
                for (int j = 0; j < 2; j++)
#pragma unroll
                    for (int u = 0; u < 2; u++)
                        MMA_BF16v(S[(tpp + j) * 2 + u], ql[c],
                                  bh[j][u], bh[j][u + 2]);
            }
        }

        float rm0 = -1e30f, rm1 = -1e30f;
#pragma unroll
        for (int t = 0; t < 8; t++) {
            rm0 = fmaxf(rm0, fmaxf(S[t][0], S[t][1]));
            rm1 = fmaxf(rm1, fmaxf(S[t][2], S[t][3]));
        }
        rm0 = fmaxf(rm0, __shfl_xor_sync(0xffffffffu, rm0, 1));
        rm0 = fmaxf(rm0, __shfl_xor_sync(0xffffffffu, rm0, 2));
        rm1 = fmaxf(rm1, __shfl_xor_sync(0xffffffffu, rm1, 1));
        rm1 = fmaxf(rm1, __shfl_xor_sync(0xffffffffu, rm1, 2));
        float mn0 = fmaxf(m0, rm0), mn1 = fmaxf(m1, rm1);
        float c0 = __expf(m0 - mn0), c1 = __expf(m1 - mn1);
        m0 = mn0; m1 = mn1;
        float ps0 = 0.f, ps1 = 0.f;
#pragma unroll
        for (int t = 0; t < 8; t++) {
            S[t][0] = __expf(S[t][0] - mn0);
            S[t][1] = __expf(S[t][1] - mn0);
            S[t][2] = __expf(S[t][2] - mn1);
            S[t][3] = __expf(S[t][3] - mn1);
            ps0 += S[t][0] + S[t][1];
            ps1 += S[t][2] + S[t][3];
        }
        ps0 += __shfl_xor_sync(0xffffffffu, ps0, 1);
        ps0 += __shfl_xor_sync(0xffffffffu, ps0, 2);
        ps1 += __shfl_xor_sync(0xffffffffu, ps1, 1);
        ps1 += __shfl_xor_sync(0xffffffffu, ps1, 2);
        l0 = l0 * c0 + ps0;
        l1 = l1 * c1 + ps1;
#pragma unroll
        for (int t = 0; t < 8; t++) {
            O[t][0] *= c0; O[t][1] *= c0; O[t][2] *= c1; O[t][3] *= c1;
        }

        unsigned ph[4][4], pl[4][4];
#pragma unroll
        for (int c = 0; c < 4; c++) {
            int t0 = 2 * c, t1 = 2 * c + 1;
            ph[c][0] = pk2(S[t0][0], S[t0][1]);
            ph[c][1] = pk2(S[t0][2], S[t0][3]);
            ph[c][2] = pk2(S[t1][0], S[t1][1]);
            ph[c][3] = pk2(S[t1][2], S[t1][3]);
            pl[c][0] = pk2(lores(S[t0][0]), lores(S[t0][1]));
            pl[c][1] = pk2(lores(S[t0][2]), lores(S[t0][3]));
            pl[c][2] = pk2(lores(S[t1][0]), lores(S[t1][1]));
            pl[c][3] = pk2(lores(S[t1][2]), lores(S[t1][3]));
        }

#pragma unroll
        for (int c = 0; c < 4; c++) {
#pragma unroll
            for (int tpp = 0; tpp < 4; tpp += 2) {
                unsigned bh[2][4], bl[2][4];
#pragma unroll
                for (int j = 0; j < 2; j++) {
                    unsigned off = base + 18432u
                        + ((c * 16 + vr) * 72 + (tpp + j) * 16 + vc8) * 2;
                    LDSM4T(bh[j], off);
                    LDSM4T(bl[j], off + 9216u);
                }
#pragma unroll
                for (int j = 0; j < 2; j++)
#pragma unroll
                    for (int u = 0; u < 2; u++)
                        MMA_BF16v(O[(tpp + j) * 2 + u], ph[c],
                                  bh[j][u], bh[j][u + 2]);
#pragma unroll
                for (int j = 0; j < 2; j++)
#pragma unroll
                    for (int u = 0; u < 2; u++)
                        MMA_BF16v(O[(tpp + j) * 2 + u], ph[c],
                                  bl[j][u], bl[j][u + 2]);
#pragma unroll
                for (int j = 0; j < 2; j++)
#pragma unroll
                    for (int u = 0; u < 2; u++)
                        MMA_BF16v(O[(tpp + j) * 2 + u], pl[c],
                                  bh[j][u], bh[j][u + 2]);
            }
        }
        if (kb + 2 < 16) {
            int nb = buf + 2; if (nb >= 3) nb -= 3;
            issue_kv(kb + 2, nb);
        }
        if (++buf == 3) buf = 0;
    }

    float inv0 = 1.f / l0, inv1 = 1.f / l1;
#pragma unroll
    for (int t = 0; t < 8; t++) {
        int col = h * 64 + 8 * t + 2 * tg;
        size_t o0 = (size_t)qrow * 1024 + col;
        size_t o1 = o0 + 8 * 1024;
        float2 gg0 = *(const float2*)(g_g + o0);
        float2 gg1 = *(const float2*)(g_g + o1);
        float v0 = O[t][0] * inv0 * gg0.x;
        float v1 = O[t][1] * inv0 * gg0.y;
        float v2 = O[t][2] * inv1 * gg1.x;
        float v3 = O[t][3] * inv1 * gg1.y;
        *(unsigned*)(g_oh + o0) = pkh2(v0, v1);
        *(unsigned*)(g_oh + o1) = pkh2(v2, v3);
    }
}

// ---------------------------------------------------------------------------
extern "C" void kernel_launch(void* const* d_in, const int* in_sizes, int n_in,
                              void* d_out, int out_size)
{
    const float* single = (const float*)d_in[0];
    const float* pw     = (const float*)d_in[1];
    const float* gamma  = (const float*)d_in[2];
    const float* beta   = (const float*)d_in[3];
    const float* Wb     = (const float*)d_in[4];
    const float* Wq     = (const float*)d_in[5];
    const float* Wk     = (const float*)d_in[6];
    const float* Wv     = (const float*)d_in[7];
    const float* Wg     = (const float*)d_in[8];
    const float* bg     = (const float*)d_in[9];
    const float* Wo     = (const float*)d_in[10];
    float* out = (float*)d_out;

    const int QKVG_SMEM = 3 * 44032;   // 132096
    const int OUT_SMEM  = 3 * 19456;   // 58368
    const int ATTN_SMEM = 3 * 36864;   // 110592
    cudaFuncSetAttribute(gemm_qkvg,
        cudaFuncAttributeMaxDynamicSharedMemorySize, QKVG_SMEM);
    cudaFuncSetAttribute(gemm_out,
        cudaFuncAttributeMaxDynamicSharedMemorySize, OUT_SMEM);
    cudaFuncSetAttribute(attn_kernel,
        cudaFuncAttributeMaxDynamicSharedMemorySize, ATTN_SMEM);

    bias_setup<<<1, 128>>>(gamma, beta, Wb);
    dim3 bgrid(16, 1024);
    bias_kernel<<<bgrid, 256>>>(pw);

    dim3 cgrid(1024, 6);
    conv_all<<<cgrid, 256>>>(single, Wq, Wk, Wv, Wg, Wo);

    dim3 ggrid(4, 8, 4);   // 128 CTAs
    gemm_qkvg<<<ggrid, 512, QKVG_SMEM>>>(bg);

    dim3 agrid(8, 16);
    attn_kernel<<<agrid, 256, ATTN_SMEM>>>();

    dim3 ogrid(16, 8);     // 128 CTAs
    gemm_out<<<ogrid, 256, OUT_SMEM>>>(out);
}

// round 16
// speedup vs baseline: 1.7347x; 1.0572x over previous
#include <cuda_runtime.h>
#include <cuda_bf16.h>
#include <cuda_fp16.h>
#include <cstdint>

#define NN (1024u*1024u)

// scratch (device globals: allocation-free)
__device__ float g_bias[16u*1024u*1024u]; // [h][i][j]
__device__ float g_g [NN];                // gates fp32 [token][dim_inner]
__device__ __half g_sh[NN];               // single_repr fp16 (hi only) [m][k]
__device__ __half g_wfh[5][NN], g_wfl[5][NN]; // W [k][n] fp16 hi/lo (natural)
__device__ __half g_oh[NN];               // gated attn out fp16 (hi only)
__device__ __half g_qf[NN];               // Q fp16 hi only [tok][d] *0.125
__device__ __half g_kfh[NN], g_kfl[NN];   // K fp16 hi/lo
__device__ __half g_vfh[NN], g_vfl[NN];   // V fp16 hi/lo
__device__ __nv_bfloat16 g_wbth[16*128], g_wbtl[16*128]; // (gamma*Wb)^T [h][p]
__device__ float g_binit[16];                            // beta @ Wb

__device__ __forceinline__ unsigned pk2(float a, float b) {
    __nv_bfloat162 t = __floats2bfloat162_rn(a, b);
    return *reinterpret_cast<unsigned*>(&t);
}
__device__ __forceinline__ float lores(float a) {
    return a - __bfloat162float(__float2bfloat16(a));
}
__device__ __forceinline__ unsigned pkh2(float a, float b) {
    __half2 t = __floats2half2_rn(a, b);
    return *reinterpret_cast<unsigned*>(&t);
}
__device__ __forceinline__ float loresh(float a) {
    return a - __half2float(__float2half_rn(a));
}
__device__ __forceinline__ unsigned cvta_s(const void* p) {
    return (unsigned)__cvta_generic_to_shared(p);
}

#define MMA_BF16v(c, a, b0, b1) asm volatile( \
    "mma.sync.aligned.m16n8k16.row.col.f32.bf16.bf16.f32 " \
    "{%0,%1,%2,%3},{%4,%5,%6,%7},{%8,%9},{%0,%1,%2,%3};" \
    : "+f"((c)[0]), "+f"((c)[1]), "+f"((c)[2]), "+f"((c)[3]) \
    : "r"((a)[0]), "r"((a)[1]), "r"((a)[2]), "r"((a)[3]), \
      "r"(b0), "r"(b1))
#define MMA_F16v(c, a, b0, b1) asm volatile( \
    "mma.sync.aligned.m16n8k16.row.col.f32.f16.f16.f32 " \
    "{%0,%1,%2,%3},{%4,%5,%6,%7},{%8,%9},{%0,%1,%2,%3};" \
    : "+f"((c)[0]), "+f"((c)[1]), "+f"((c)[2]), "+f"((c)[3]) \
    : "r"((a)[0]), "r"((a)[1]), "r"((a)[2]), "r"((a)[3]), \
      "r"(b0), "r"(b1))
#define LDSM4(R, addr) asm volatile( \
    "ldmatrix.sync.aligned.m8n8.x4.shared.b16 {%0,%1,%2,%3}, [%4];" \
    : "=r"((R)[0]), "=r"((R)[1]), "=r"((R)[2]), "=r"((R)[3]) : "r"(addr))
#define LDSM4T(R, addr) asm volatile( \
    "ldmatrix.sync.aligned.m8n8.x4.trans.shared.b16 {%0,%1,%2,%3}, [%4];" \
    : "=r"((R)[0]), "=r"((R)[1]), "=r"((R)[2]), "=r"((R)[3]) : "r"(addr))
#define CP_ASYNC16(dst, src) asm volatile( \
    "cp.async.cg.shared.global [%0], [%1], 16;" :: "r"(dst), "l"(src) : "memory")
#define CP_COMMIT() asm volatile("cp.async.commit_group;" ::: "memory")
#define CP_WAIT1()  asm volatile("cp.async.wait_group 1;" ::: "memory")
#define CP_WAIT0()  asm volatile("cp.async.wait_group 0;" ::: "memory")

// ---------------------------------------------------------------------------
// One-time prep: (gamma*W_bias)^T as bf16 hi/lo, and beta@W_bias.
// ---------------------------------------------------------------------------
__global__ void bias_setup(const float* __restrict__ gamma,
                           const float* __restrict__ beta,
                           const float* __restrict__ Wb)
{
    int tid = threadIdx.x;
    for (int idx = tid; idx < 2048; idx += 128) {
        int p = idx >> 4, h = idx & 15;
        float w = gamma[p] * Wb[idx];
        __nv_bfloat16 hi = __float2bfloat16(w);
        g_wbth[h * 128 + p] = hi;
        g_wbtl[h * 128 + p] = __float2bfloat16(w - __bfloat162float(hi));
    }
    if (tid < 16) {
        float s = 0.f;
        for (int p = 0; p < 128; p++) s += beta[p] * Wb[p * 16 + tid];
        g_binit[tid] = s;
    }
}

// ---------------------------------------------------------------------------
// Bias kernel: LN (SIMT fp32 stats) + 128->16 projection on tensor cores.
// (unchanged numerics: bf16 3-pass)
// ---------------------------------------------------------------------------
__global__ __launch_bounds__(256) void bias_kernel(const float* __restrict__ pw)
{
    __shared__ __nv_bfloat16 sXh[64][136], sXl[64][136];
    __shared__ __nv_bfloat16 sWh[16][136], sWl[16][136];
    __shared__ float stage[16][64];
    __shared__ float sbin[16];

    int tid  = threadIdx.x;
    int lane = tid & 31, warp = tid >> 5;
    int i  = blockIdx.y;
    int j0 = blockIdx.x * 64;

    const float4* rowp = (const float4*)(pw
        + ((size_t)i * 1024 + j0 + warp * 8) * 128) + lane;
    float4 x[8];
#pragma unroll
    for (int rr = 0; rr < 8; rr++) x[rr] = rowp[rr * 32];

    for (int idx = tid; idx < 2048; idx += 256) {
        int h = idx >> 7, p = idx & 127;
        sWh[h][p] = g_wbth[idx];
        sWl[h][p] = g_wbtl[idx];
    }
    if (tid < 16) sbin[tid] = g_binit[tid];

#pragma unroll
    for (int rr = 0; rr < 8; rr++) {
        float s  = x[rr].x + x[rr].y + x[rr].z + x[rr].w;
        float ss = x[rr].x*x[rr].x + x[rr].y*x[rr].y
                 + x[rr].z*x[rr].z + x[rr].w*x[rr].w;
#pragma unroll
        for (int off = 16; off >= 1; off >>= 1) {
            s  += __shfl_xor_sync(0xffffffffu, s,  off);
            ss += __shfl_xor_sync(0xffffffffu, ss, off);
        }
        float mu  = s * 0.0078125f;
        float var = ss * 0.0078125f - mu * mu;
        float rs  = rsqrtf(var + 1e-5f);
        float y0 = (x[rr].x - mu) * rs, y1 = (x[rr].y - mu) * rs;
        float y2 = (x[rr].z - mu) * rs, y3 = (x[rr].w - mu) * rs;
        int r = warp * 8 + rr;
        *(uint2*)&sXh[r][lane * 4] = make_uint2(pk2(y0, y1), pk2(y2, y3));
        *(uint2*)&sXl[r][lane * 4] =
            make_uint2(pk2(lores(y0), lores(y1)), pk2(lores(y2), lores(y3)));
    }
    __syncthreads();

    if (warp < 4) {
        int gid  = lane >> 2, tg = lane & 3;
        float acc[2][4] = {};
        int warp_m = warp * 16;
        unsigned aXh = cvta_s(sXh), aXl = cvta_s(sXl);
        unsigned aWh = cvta_s(sWh), aWl = cvta_s(sWl);
        int fr = lane & 15, fc = lane >> 4;
#pragma unroll
        for (int c = 0; c < 8; c++) {
            int kk = c * 16;
            unsigned ah[4], al[4], bh[4], bl[4];
            LDSM4(ah, aXh + ((warp_m + fr) * 136 + kk + fc * 8) * 2);
            LDSM4(al, aXl + ((warp_m + fr) * 136 + kk + fc * 8) * 2);
            LDSM4(bh, aWh + ((fr) * 136 + kk + fc * 8) * 2);
            LDSM4(bl, aWl + ((fr) * 136 + kk + fc * 8) * 2);
#pragma unroll
            for (int t = 0; t < 2; t++)
                MMA_BF16v(acc[t], ah, bh[t], bh[t + 2]);
#pragma unroll
            for (int t = 0; t < 2; t++)
                MMA_BF16v(acc[t], ah, bl[t], bl[t + 2]);
#pragma unroll
            for (int t = 0; t < 2; t++)
                MMA_BF16v(acc[t], al, bh[t], bh[t + 2]);
        }
#pragma unroll
        for (int t = 0; t < 2; t++) {
            int hc = t * 8 + tg * 2;
            int r  = warp_m + gid;
            stage[hc][r]         = acc[t][0];
            stage[hc + 1][r]     = acc[t][1];
            stage[hc][r + 8]     = acc[t][2];
            stage[hc + 1][r + 8] = acc[t][3];
        }
    }
    __syncthreads();
    size_t obase = (size_t)i * 1024 + j0;
    for (int e = tid; e < 1024; e += 256) {
        int hh = e >> 6, j = e & 63;
        g_bias[(size_t)hh * NN + obase + j] = stage[hh][j] + sbin[hh];
    }
}

// ---------------------------------------------------------------------------
// Convert: single -> fp16 hi only; weights -> fp16 hi/lo.
// ---------------------------------------------------------------------------
__global__ __launch_bounds__(256) void conv_all(
    const float* __restrict__ s0, const float* __restrict__ s1,
    const float* __restrict__ s2, const float* __restrict__ s3,
    const float* __restrict__ s4, const float* __restrict__ s5)
{
    const float* srcs[6] = {s0, s1, s2, s3, s4, s5};
    const float* src = srcs[blockIdx.y];
    unsigned i = blockIdx.x * 256u + threadIdx.x;
    float4 v = ((const float4*)src)[i];
    if (blockIdx.y == 0) {
        *(unsigned*)(g_sh + 4u*i)     = pkh2(v.x, v.y);
        *(unsigned*)(g_sh + 4u*i + 2) = pkh2(v.z, v.w);
    } else {
        __half* Dh = g_wfh[blockIdx.y - 1];
        __half* Dl = g_wfl[blockIdx.y - 1];
        *(unsigned*)(Dh + 4u*i)     = pkh2(v.x, v.y);
        *(unsigned*)(Dh + 4u*i + 2) = pkh2(v.z, v.w);
        *(unsigned*)(Dl + 4u*i)     = pkh2(loresh(v.x), loresh(v.y));
        *(unsigned*)(Dl + 4u*i + 2) = pkh2(loresh(v.z), loresh(v.w));
    }
}

// ---------------------------------------------------------------------------
// QKVG GEMM: fp16 2-pass (A=hi only, B=hi+lo). 512 thr, tile 128x256, BK=32,
// depth-3 pipeline, one barrier/chunk. Grid (4, 8, 4) = 128 CTAs.
// ---------------------------------------------------------------------------
__global__ __launch_bounds__(512, 1) void gemm_qkvg(const float* __restrict__ aux)
{
    extern __shared__ __half dsm[];
    constexpr unsigned SZB   = 16896u;   // 32 * 264 * 2
    constexpr unsigned BUFSZ = 44032u;

    int widx = blockIdx.z;
    float scale = (widx == 0) ? 0.125f : 1.0f;
    const __half* gBh = g_wfh[widx];
    const __half* gBl = g_wfl[widx];

    int tid  = threadIdx.x;
    int lane = tid & 31, warp = tid >> 5;
    int gid  = lane >> 2, tg = lane & 3;
    int fr = lane & 15, fc8 = (lane >> 4) * 8;
    int vr = (lane >> 4) * 8 + (lane & 7);
    int vc8 = ((lane >> 3) & 1) * 8;
    int warp_m = (warp >> 2) * 32, warp_n = (warp & 3) * 64;
    int m0 = blockIdx.y * 128, n0 = blockIdx.x * 256;
    unsigned sb = cvta_s(dsm);

    int a_row = (tid & 511) >> 2, a_seg = tid & 3;
    int b_row = (tid & 1023) >> 5, b_seg = tid & 31;

    const __half* pA   = g_sh + (size_t)(m0 + a_row) * 1024 + a_seg * 8;
    const __half* pBh0 = gBh + (size_t)b_row * 1024 + n0 + b_seg * 8;
    const __half* pBl0 = gBl + (size_t)b_row * 1024 + n0 + b_seg * 8;
    const __half* pBh1 = pBh0 + 16 * 1024;
    const __half* pBl1 = pBl0 + 16 * 1024;
    unsigned dA  = a_row * 80u + a_seg * 16u;
    unsigned dB0 = 10240u + b_row * 528u + b_seg * 16u;
    unsigned dB1 = 10240u + (b_row + 16) * 528u + b_seg * 16u;

    auto issue = [&](int ch, int buf) {
        unsigned k0 = ch * 32u;
        size_t kq = ch * 32u * 1024u;
        unsigned bo = sb + buf * BUFSZ;
        CP_ASYNC16(bo + dA,        pA + k0);
        CP_ASYNC16(bo + dB0,       pBh0 + kq);
        CP_ASYNC16(bo + dB0 + SZB, pBl0 + kq);
        CP_ASYNC16(bo + dB1,       pBh1 + kq);
        CP_ASYNC16(bo + dB1 + SZB, pBl1 + kq);
        CP_COMMIT();
    };

    float acc[2][8][4];
#pragma unroll
    for (int a = 0; a < 2; a++)
#pragma unroll
        for (int b = 0; b < 8; b++)
#pragma unroll
            for (int q = 0; q < 4; q++) acc[a][b][q] = 0.f;

    issue(0, 0);
    issue(1, 1);

    int buf = 0;
#pragma unroll 1
    for (int ch = 0; ch < 32; ch++) {
        if (ch < 31) { CP_WAIT1(); } else { CP_WAIT0(); }
        __syncthreads();
        unsigned base = sb + buf * BUFSZ;
#pragma unroll
        for (int k16 = 0; k16 < 32; k16 += 16) {
            unsigned a_h[2][4], b_h[4][4], b_l[4][4];
#pragma unroll
            for (int mt = 0; mt < 2; mt++) {
                unsigned off = base + ((warp_m + mt * 16 + fr) * 40 + k16 + fc8) * 2;
                LDSM4(a_h[mt], off);
            }
#pragma unroll
            for (int tp = 0; tp < 4; tp++) {
                unsigned off = base + 10240u
                    + ((k16 + vr) * 264 + warp_n + tp * 16 + vc8) * 2;
                LDSM4T(b_h[tp], off);
                LDSM4T(b_l[tp], off + SZB);
            }
#pragma unroll
            for (int mt = 0; mt < 2; mt++)
#pragma unroll
                for (int tp = 0; tp < 4; tp++)
#pragma unroll
                    for (int u = 0; u < 2; u++)
                        MMA_F16v(acc[mt][tp * 2 + u], a_h[mt],
                                 b_h[tp][u], b_h[tp][u + 2]);
#pragma unroll
            for (int mt = 0; mt < 2; mt++)
#pragma unroll
                for (int tp = 0; tp < 4; tp++)
#pragma unroll
                    for (int u = 0; u < 2; u++)
                        MMA_F16v(acc[mt][tp * 2 + u], a_h[mt],
                                 b_l[tp][u], b_l[tp][u + 2]);
        }
        if (ch + 2 < 32) {
            int nb = buf + 2; if (nb >= 3) nb -= 3;
            issue(ch + 2, nb);
        }
        if (++buf == 3) buf = 0;
    }

    // epilogue: Q -> fp16 hi only; K,V -> fp16 hi/lo; gates -> fp32 sigmoid
#pragma unroll
    for (int mt = 0; mt < 2; mt++) {
#pragma unroll
        for (int j = 0; j < 8; j++) {
            int rg = m0 + warp_m + mt * 16 + gid;
            int cg = n0 + warp_n + j * 8 + tg * 2;
            float* a4 = acc[mt][j];
            if (widx == 3) {
                float b0 = aux[cg], b1 = aux[cg + 1];
                float v0 = 1.f / (1.f + __expf(-(a4[0] + b0)));
                float v1 = 1.f / (1.f + __expf(-(a4[1] + b1)));
                float v2 = 1.f / (1.f + __expf(-(a4[2] + b0)));
                float v3 = 1.f / (1.f + __expf(-(a4[3] + b1)));
                *(float2*)&g_g[(size_t)rg * 1024 + cg]       = make_float2(v0, v1);
                *(float2*)&g_g[(size_t)(rg + 8) * 1024 + cg] = make_float2(v2, v3);
            } else if (widx == 0) {
                float v0 = a4[0] * scale, v1 = a4[1] * scale;
                float v2 = a4[2] * scale, v3 = a4[3] * scale;
                *(unsigned*)&g_qf[(size_t)rg * 1024 + cg]       = pkh2(v0, v1);
                *(unsigned*)&g_qf[(size_t)(rg + 8) * 1024 + cg] = pkh2(v2, v3);
            } else {
                __half* Dh = (widx == 1) ? g_kfh : g_vfh;
                __half* Dl = (widx == 1) ? g_kfl : g_vfl;
                float v0 = a4[0], v1 = a4[1], v2 = a4[2], v3 = a4[3];
                *(unsigned*)&Dh[(size_t)rg * 1024 + cg]       = pkh2(v0, v1);
                *(unsigned*)&Dh[(size_t)(rg + 8) * 1024 + cg] = pkh2(v2, v3);
                *(unsigned*)&Dl[(size_t)rg * 1024 + cg]       =
                    pkh2(loresh(v0), loresh(v1));
                *(unsigned*)&Dl[(size_t)(rg + 8) * 1024 + cg] =
                    pkh2(loresh(v2), loresh(v3));
            }
        }
    }
}

// ---------------------------------------------------------------------------
// Output GEMM: fp16 2-pass. 256 thr, 128x64 tile, BK=32, depth-3. Grid (16,8).
// ---------------------------------------------------------------------------
__global__ __launch_bounds__(256) void gemm_out(float* __restrict__ Cext)
{
    extern __shared__ __half dsm[];
    constexpr unsigned SZB   = 32u * 72 * 2;          // 4608
    constexpr unsigned BUFSZ = 10240u + 2 * SZB;      // 19456

    const __half* gBh = g_wfh[4];
    const __half* gBl = g_wfl[4];

    int tid  = threadIdx.x;
    int lane = tid & 31, warp = tid >> 5;
    int gid  = lane >> 2, tg = lane & 3;
    int fr = lane & 15, fc8 = (lane >> 4) * 8;
    int vr = (lane >> 4) * 8 + (lane & 7);
    int vc8 = ((lane >> 3) & 1) * 8;
    int warp_m = (warp >> 1) * 32, warp_n = (warp & 1) * 32;
    int m0 = blockIdx.y * 128, n0 = blockIdx.x * 64;
    unsigned sb = cvta_s(dsm);

    auto issue = [&](int ch, int buf) {
        int k0 = ch * 32;
        unsigned bo = sb + buf * BUFSZ;
#pragma unroll
        for (int t = 0; t < 4; t++) {
            int s = tid + t * 256;
            unsigned dst;
            const __half* src;
            if (s < 512) {
                int row = s >> 2, seg = s & 3;
                dst = bo + row * 80u + seg * 16u;
                src = g_oh + (size_t)(m0 + row) * 1024 + k0 + seg * 8;
            } else {
                int ss = s - 512;
                int mt = ss >> 8, rem = ss & 255;
                int row = rem >> 3, seg = rem & 7;
                dst = bo + 10240u + mt * SZB + row * 144u + seg * 16u;
                src = (mt ? gBl : gBh) + (size_t)(k0 + row) * 1024 + n0 + seg * 8;
            }
            CP_ASYNC16(dst, src);
        }
        CP_COMMIT();
    };

    float acc[2][4][4];
#pragma unroll
    for (int a = 0; a < 2; a++)
#pragma unroll
        for (int b = 0; b < 4; b++)
#pragma unroll
            for (int q = 0; q < 4; q++) acc[a][b][q] = 0.f;

    issue(0, 0);
    issue(1, 1);

    int buf = 0;
#pragma unroll 1
    for (int ch = 0; ch < 32; ch++) {
        if (ch < 31) { CP_WAIT1(); } else { CP_WAIT0(); }
        __syncthreads();
        unsigned base = sb + buf * BUFSZ;
#pragma unroll
        for (int k16 = 0; k16 < 32; k16 += 16) {
            unsigned a_h[2][4], b_h[2][4], b_l[2][4];
#pragma unroll
            for (int mt = 0; mt < 2; mt++) {
                unsigned off = base + ((warp_m + mt * 16 + fr) * 40 + k16 + fc8) * 2;
                LDSM4(a_h[mt], off);
            }
#pragma unroll
            for (int tp = 0; tp < 2; tp++) {
                unsigned off = base + 10240u
                    + ((k16 + vr) * 72 + warp_n + tp * 16 + vc8) * 2;
                LDSM4T(b_h[tp], off);
                LDSM4T(b_l[tp], off + SZB);
            }
#pragma unroll
            for (int mt = 0; mt < 2; mt++)
#pragma unroll
                for (int tp = 0; tp < 2; tp++)
#pragma unroll
                    for (int u = 0; u < 2; u++)
                        MMA_F16v(acc[mt][tp * 2 + u], a_h[mt],
                                 b_h[tp][u], b_h[tp][u + 2]);
#pragma unroll
            for (int mt = 0; mt < 2; mt++)
#pragma unroll
                for (int tp = 0; tp < 2; tp++)
#pragma unroll
                    for (int u = 0; u < 2; u++)
                        MMA_F16v(acc[mt][tp * 2 + u], a_h[mt],
                                 b_l[tp][u], b_l[tp][u + 2]);
        }
        if (ch + 2 < 32) {
            int nb = buf + 2; if (nb >= 3) nb -= 3;
            issue(ch + 2, nb);
        }
        if (++buf == 3) buf = 0;
    }

#pragma unroll
    for (int mt = 0; mt < 2; mt++) {
#pragma unroll
        for (int j = 0; j < 4; j++) {
            int rg = m0 + warp_m + mt * 16 + gid;
            int cg = n0 + warp_n + j * 8 + tg * 2;
            float* a4 = acc[mt][j];
            *(float2*)&Cext[(size_t)rg * 1024 + cg]       = make_float2(a4[0], a4[1]);
            *(float2*)&Cext[(size_t)(rg + 8) * 1024 + cg] = make_float2(a4[2], a4[3]);
        }
    }
}

// ---------------------------------------------------------------------------
// Flash attention, fp16 2-pass: S = Qh (Kh + Kl),  O += Ph (Vh + Vl).
// depth-3 K/V pipeline, 256 thr, 128 queries/CTA. Grid (8, 16).
// ---------------------------------------------------------------------------
__global__ __launch_bounds__(256) void attn_kernel()
{
    extern __shared__ __half dsmh[];
    int tid  = threadIdx.x;
    int lane = tid & 31, warp = tid >> 5;
    int gid  = lane >> 2, tg = lane & 3;
    int h  = blockIdx.y;
    int q0 = blockIdx.x * 128;
    int warp_m = warp * 16;
    int qrow = q0 + warp_m + gid;
    unsigned sb = cvta_s(dsmh);

    int fr = lane & 15, fc8 = (lane >> 4) * 8;
    int vr = (lane >> 4) * 8 + (lane & 7);
    int vc8 = ((lane >> 3) & 1) * 8;

    auto issue_kv = [&](int kb, int buf) {
        int k0 = kb * 64;
        unsigned bo = buf * 36864u;
#pragma unroll
        for (int t = 0; t < 8; t++) {
            int s = tid + t * 256;
            int mt = s >> 9, rem = s & 511;
            int row = rem >> 3, seg = rem & 7;
            unsigned dst = sb + bo + mt * 9216u + row * 144u + seg * 16u;
            const __half* src;
            if      (mt == 0) src = g_kfh + (size_t)(k0 + row) * 1024 + h * 64 + seg * 8;
            else if (mt == 1) src = g_kfl + (size_t)(k0 + row) * 1024 + h * 64 + seg * 8;
            else if (mt == 2) src = g_vfh + (size_t)(k0 + row) * 1024 + h * 64 + seg * 8;
            else              src = g_vfl + (size_t)(k0 + row) * 1024 + h * 64 + seg * 8;
            CP_ASYNC16(dst, src);
        }
        CP_COMMIT();
    };

    unsigned qh[4][4];
    {
        const __half* Qf = g_qf + (size_t)qrow * 1024 + h * 64;
#pragma unroll
        for (int c = 0; c < 4; c++) {
            int kk = c * 16 + tg * 2;
            qh[c][0] = *(const unsigned*)(Qf + kk);
            qh[c][1] = *(const unsigned*)(Qf + 8 * 1024 + kk);
            qh[c][2] = *(const unsigned*)(Qf + kk + 8);
            qh[c][3] = *(const unsigned*)(Qf + 8 * 1024 + kk + 8);
        }
    }

    float m0 = -1e30f, m1 = -1e30f, l0 = 0.f, l1 = 0.f;
    float O[8][4] = {};

    issue_kv(0, 0);
    issue_kv(1, 1);

    int buf = 0;
#pragma unroll 1
    for (int kb = 0; kb < 16; kb++) {
        if (kb < 15) { CP_WAIT1(); } else { CP_WAIT0(); }
        __syncthreads();
        unsigned base = sb + buf * 36864u;
        int k0 = kb * 64;

        float S[8][4];
        {
            const float* bptr = g_bias + (size_t)h * NN + (size_t)qrow * 1024 + k0;
#pragma unroll
            for (int t = 0; t < 8; t++) {
                float2 b0 = *(const float2*)(bptr + 8 * t + 2 * tg);
                float2 b1 = *(const float2*)(bptr + 8 * 1024 + 8 * t + 2 * tg);
                S[t][0] = b0.x; S[t][1] = b0.y; S[t][2] = b1.x; S[t][3] = b1.y;
            }
        }
        // S += Q (Kh + Kl)  (2-pass fp16, tp-pairs)
#pragma unroll
        for (int c = 0; c < 4; c++) {
            int kk = c * 16;
#pragma unroll
            for (int tpp = 0; tpp < 4; tpp += 2) {
                unsigned bh[2][4], bl[2][4];
#pragma unroll
                for (int j = 0; j < 2; j++) {
                    unsigned off = base + (((tpp + j) * 16 + fr) * 72 + kk + fc8) * 2;
                    LDSM4(bh[j], off);
                    LDSM4(bl[j], off + 9216u);
                }
#pragma unroll
                for (int j = 0; j < 2; j++)
#pragma unroll
                    for (int u = 0; u < 2; u++)
                        MMA_F16v(S[(tpp + j) * 2 + u], qh[c],
                                 bh[j][u], bh[j][u + 2]);
#pragma unroll
                for (int j = 0; j < 2; j++)
#pragma unroll
                    for (int u = 0; u < 2; u++)
                        MMA_F16v(S[(tpp + j) * 2 + u], qh[c],
                                 bl[j][u], bl[j][u + 2]);
            }
        }

        float rm0 = -1e30f, rm1 = -1e30f;
#pragma unroll
        for (int t = 0; t < 8; t++) {
            rm0 = fmaxf(rm0, fmaxf(S[t][0], S[t][1]));
            rm1 = fmaxf(rm1, fmaxf(S[t][2], S[t][3]));
        }
        rm0 = fmaxf(rm0, __shfl_xor_sync(0xffffffffu, rm0, 1));
        rm0 = fmaxf(rm0, __shfl_xor_sync(0xffffffffu, rm0, 2));
        rm1 = fmaxf(rm1, __shfl_xor_sync(0xffffffffu, rm1, 1));
        rm1 = fmaxf(rm1, __shfl_xor_sync(0xffffffffu, rm1, 2));
        float mn0 = fmaxf(m0, rm0), mn1 = fmaxf(m1, rm1);
        float c0 = __expf(m0 - mn0), c1 = __expf(m1 - mn1);
        m0 = mn0; m1 = mn1;
        float ps0 = 0.f, ps1 = 0.f;
#pragma unroll
        for (int t = 0; t < 8; t++) {
            S[t][0] = __expf(S[t][0] - mn0);
            S[t][1] = __expf(S[t][1] - mn0);
            S[t][2] = __expf(S[t][2] - mn1);
            S[t][3] = __expf(S[t][3] - mn1);
            ps0 += S[t][0] + S[t][1];
            ps1 += S[t][2] + S[t][3];
        }
        ps0 += __shfl_xor_sync(0xffffffffu, ps0, 1);
        ps0 += __shfl_xor_sync(0xffffffffu, ps0, 2);
        ps1 += __shfl_xor_sync(0xffffffffu, ps1, 1);
        ps1 += __shfl_xor_sync(0xffffffffu, ps1, 2);
        l0 = l0 * c0 + ps0;
        l1 = l1 * c1 + ps1;
#pragma unroll
        for (int t = 0; t < 8; t++) {
            O[t][0] *= c0; O[t][1] *= c0; O[t][2] *= c1; O[t][3] *= c1;
        }

        // P as fp16 hi-only A-fragments
        unsigned ph[4][4];
#pragma unroll
        for (int c = 0; c < 4; c++) {
            int t0 = 2 * c, t1 = 2 * c + 1;
            ph[c][0] = pkh2(S[t0][0], S[t0][1]);
            ph[c][1] = pkh2(S[t0][2], S[t0][3]);
            ph[c][2] = pkh2(S[t1][0], S[t1][1]);
            ph[c][3] = pkh2(S[t1][2], S[t1][3]);
        }

        // O += P (Vh + Vl)  (2-pass fp16, tp-pairs)
#pragma unroll
        for (int c = 0; c < 4; c++) {
#pragma unroll
            for (int tpp = 0; tpp < 4; tpp += 2) {
                unsigned bh[2][4], bl[2][4];
#pragma unroll
                for (int j = 0; j < 2; j++) {
                    unsigned off = base + 18432u
                        + ((c * 16 + vr) * 72 + (tpp + j) * 16 + vc8) * 2;
                    LDSM4T(bh[j], off);
                    LDSM4T(bl[j], off + 9216u);
                }
#pragma unroll
                for (int j = 0; j < 2; j++)
#pragma unroll
                    for (int u = 0; u < 2; u++)
                        MMA_F16v(O[(tpp + j) * 2 + u], ph[c],
                                 bh[j][u], bh[j][u + 2]);
#pragma unroll
                for (int j = 0; j < 2; j++)
#pragma unroll
                    for (int u = 0; u < 2; u++)
                        MMA_F16v(O[(tpp + j) * 2 + u], ph[c],
                                 bl[j][u], bl[j][u + 2]);
            }
        }
        if (kb + 2 < 16) {
            int nb = buf + 2; if (nb >= 3) nb -= 3;
            issue_kv(kb + 2, nb);
        }
        if (++buf == 3) buf = 0;
    }

    float inv0 = 1.f / l0, inv1 = 1.f / l1;
#pragma unroll
    for (int t = 0; t < 8; t++) {
        int col = h * 64 + 8 * t + 2 * tg;
        size_t o0 = (size_t)qrow * 1024 + col;
        size_t o1 = o0 + 8 * 1024;
        float2 gg0 = *(const float2*)(g_g + o0);
        float2 gg1 = *(const float2*)(g_g + o1);
        float v0 = O[t][0] * inv0 * gg0.x;
        float v1 = O[t][1] * inv0 * gg0.y;
        float v2 = O[t][2] * inv1 * gg1.x;
        float v3 = O[t][3] * inv1 * gg1.y;
        *(unsigned*)(g_oh + o0) = pkh2(v0, v1);
        *(unsigned*)(g_oh + o1) = pkh2(v2, v3);
    }
}

// ---------------------------------------------------------------------------
extern "C" void kernel_launch(void* const* d_in, const int* in_sizes, int n_in,
                              void* d_out, int out_size)
{
    const float* single = (const float*)d_in[0];
    const float* pw     = (const float*)d_in[1];
    const float* gamma  = (const float*)d_in[2];
    const float* beta   = (const float*)d_in[3];
    const float* Wb     = (const float*)d_in[4];
    const float* Wq     = (const float*)d_in[5];
    const float* Wk     = (const float*)d_in[6];
    const float* Wv     = (const float*)d_in[7];
    const float* Wg     = (const float*)d_in[8];
    const float* bg     = (const float*)d_in[9];
    const float* Wo     = (const float*)d_in[10];
    float* out = (float*)d_out;

    const int QKVG_SMEM = 3 * 44032;   // 132096
    const int OUT_SMEM  = 3 * 19456;   // 58368
    const int ATTN_SMEM = 3 * 36864;   // 110592
    cudaFuncSetAttribute(gemm_qkvg,
        cudaFuncAttributeMaxDynamicSharedMemorySize, QKVG_SMEM);
    cudaFuncSetAttribute(gemm_out,
        cudaFuncAttributeMaxDynamicSharedMemorySize, OUT_SMEM);
    cudaFuncSetAttribute(attn_kernel,
        cudaFuncAttributeMaxDynamicSharedMemorySize, ATTN_SMEM);

    bias_setup<<<1, 128>>>(gamma, beta, Wb);
    dim3 bgrid(16, 1024);
    bias_kernel<<<bgrid, 256>>>(pw);

    dim3 cgrid(1024, 6);
    conv_all<<<cgrid, 256>>>(single, Wq, Wk, Wv, Wg, Wo);

    dim3 ggrid(4, 8, 4);   // 128 CTAs
    gemm_qkvg<<<ggrid, 512, QKVG_SMEM>>>(bg);

    dim3 agrid(8, 16);
    attn_kernel<<<agrid, 256, ATTN_SMEM>>>();

    dim3 ogrid(16, 8);     // 128 CTAs
    gemm_out<<<ogrid, 256, OUT_SMEM>>>(out);
}

// round 17
// speedup vs baseline: 1.8627x; 1.0738x over previous
#include <cuda_runtime.h>
#include <cuda_bf16.h>
#include <cuda_fp16.h>
#include <cstdint>

#define NN (1024u*1024u)

// scratch (device globals: allocation-free)
__device__ float g_bias[16u*1024u*1024u]; // [h][i][j]
__device__ float g_g [NN];                // gates fp32 [token][dim_inner]
__device__ __half g_sh[NN];               // single_repr fp16 (hi only) [m][k]
__device__ __half g_wfh[5][NN], g_wfl[5][NN]; // W [k][n] fp16 hi/lo (natural)
__device__ __half g_oh[NN];               // gated attn out fp16 (hi only)
__device__ __half g_qf[NN];               // Q fp16 hi only [tok][d] *0.125
__device__ __half g_kfh[NN], g_kfl[NN];   // K fp16 hi/lo
__device__ __half g_vfh[NN], g_vfl[NN];   // V fp16 hi/lo
__device__ __nv_bfloat16 g_wbth[16*128], g_wbtl[16*128]; // (gamma*Wb)^T [h][p]
__device__ float g_binit[16];                            // beta @ Wb

__device__ __forceinline__ unsigned pk2(float a, float b) {
    __nv_bfloat162 t = __floats2bfloat162_rn(a, b);
    return *reinterpret_cast<unsigned*>(&t);
}
__device__ __forceinline__ float lores(float a) {
    return a - __bfloat162float(__float2bfloat16(a));
}
__device__ __forceinline__ unsigned pkh2(float a, float b) {
    __half2 t = __floats2half2_rn(a, b);
    return *reinterpret_cast<unsigned*>(&t);
}
__device__ __forceinline__ float loresh(float a) {
    return a - __half2float(__float2half_rn(a));
}
__device__ __forceinline__ unsigned cvta_s(const void* p) {
    return (unsigned)__cvta_generic_to_shared(p);
}

#define MMA_BF16v(c, a, b0, b1) asm volatile( \
    "mma.sync.aligned.m16n8k16.row.col.f32.bf16.bf16.f32 " \
    "{%0,%1,%2,%3},{%4,%5,%6,%7},{%8,%9},{%0,%1,%2,%3};" \
    : "+f"((c)[0]), "+f"((c)[1]), "+f"((c)[2]), "+f"((c)[3]) \
    : "r"((a)[0]), "r"((a)[1]), "r"((a)[2]), "r"((a)[3]), \
      "r"(b0), "r"(b1))
#define MMA_F16v(c, a, b0, b1) asm volatile( \
    "mma.sync.aligned.m16n8k16.row.col.f32.f16.f16.f32 " \
    "{%0,%1,%2,%3},{%4,%5,%6,%7},{%8,%9},{%0,%1,%2,%3};" \
    : "+f"((c)[0]), "+f"((c)[1]), "+f"((c)[2]), "+f"((c)[3]) \
    : "r"((a)[0]), "r"((a)[1]), "r"((a)[2]), "r"((a)[3]), \
      "r"(b0), "r"(b1))
#define LDSM4(R, addr) asm volatile( \
    "ldmatrix.sync.aligned.m8n8.x4.shared.b16 {%0,%1,%2,%3}, [%4];" \
    : "=r"((R)[0]), "=r"((R)[1]), "=r"((R)[2]), "=r"((R)[3]) : "r"(addr))
#define LDSM4T(R, addr) asm volatile( \
    "ldmatrix.sync.aligned.m8n8.x4.trans.shared.b16 {%0,%1,%2,%3}, [%4];" \
    : "=r"((R)[0]), "=r"((R)[1]), "=r"((R)[2]), "=r"((R)[3]) : "r"(addr))
#define CP_ASYNC16(dst, src) asm volatile( \
    "cp.async.cg.shared.global [%0], [%1], 16;" :: "r"(dst), "l"(src) : "memory")
#define CP_COMMIT() asm volatile("cp.async.commit_group;" ::: "memory")
#define CP_WAIT1()  asm volatile("cp.async.wait_group 1;" ::: "memory")
#define CP_WAIT0()  asm volatile("cp.async.wait_group 0;" ::: "memory")

// ---------------------------------------------------------------------------
// One-time prep: (gamma*W_bias)^T as bf16 hi/lo, and beta@W_bias.
// ---------------------------------------------------------------------------
__global__ void bias_setup(const float* __restrict__ gamma,
                           const float* __restrict__ beta,
                           const float* __restrict__ Wb)
{
    int tid = threadIdx.x;
    for (int idx = tid; idx < 2048; idx += 128) {
        int p = idx >> 4, h = idx & 15;
        float w = gamma[p] * Wb[idx];
        __nv_bfloat16 hi = __float2bfloat16(w);
        g_wbth[h * 128 + p] = hi;
        g_wbtl[h * 128 + p] = __float2bfloat16(w - __bfloat162float(hi));
    }
    if (tid < 16) {
        float s = 0.f;
        for (int p = 0; p < 128; p++) s += beta[p] * Wb[p * 16 + tid];
        g_binit[tid] = s;
    }
}

// ---------------------------------------------------------------------------
// Bias kernel: LN (SIMT fp32 stats) + 128->16 projection on tensor cores.
// ---------------------------------------------------------------------------
__global__ __launch_bounds__(256) void bias_kernel(const float* __restrict__ pw)
{
    __shared__ __nv_bfloat16 sXh[64][136], sXl[64][136];
    __shared__ __nv_bfloat16 sWh[16][136], sWl[16][136];
    __shared__ float stage[16][64];
    __shared__ float sbin[16];

    int tid  = threadIdx.x;
    int lane = tid & 31, warp = tid >> 5;
    int i  = blockIdx.y;
    int j0 = blockIdx.x * 64;

    const float4* rowp = (const float4*)(pw
        + ((size_t)i * 1024 + j0 + warp * 8) * 128) + lane;
    float4 x[8];
#pragma unroll
    for (int rr = 0; rr < 8; rr++) x[rr] = rowp[rr * 32];

    for (int idx = tid; idx < 2048; idx += 256) {
        int h = idx >> 7, p = idx & 127;
        sWh[h][p] = g_wbth[idx];
        sWl[h][p] = g_wbtl[idx];
    }
    if (tid < 16) sbin[tid] = g_binit[tid];

#pragma unroll
    for (int rr = 0; rr < 8; rr++) {
        float s  = x[rr].x + x[rr].y + x[rr].z + x[rr].w;
        float ss = x[rr].x*x[rr].x + x[rr].y*x[rr].y
                 + x[rr].z*x[rr].z + x[rr].w*x[rr].w;
#pragma unroll
        for (int off = 16; off >= 1; off >>= 1) {
            s  += __shfl_xor_sync(0xffffffffu, s,  off);
            ss += __shfl_xor_sync(0xffffffffu, ss, off);
        }
        float mu  = s * 0.0078125f;
        float var = ss * 0.0078125f - mu * mu;
        float rs  = rsqrtf(var + 1e-5f);
        float y0 = (x[rr].x - mu) * rs, y1 = (x[rr].y - mu) * rs;
        float y2 = (x[rr].z - mu) * rs, y3 = (x[rr].w - mu) * rs;
        int r = warp * 8 + rr;
        *(uint2*)&sXh[r][lane * 4] = make_uint2(pk2(y0, y1), pk2(y2, y3));
        *(uint2*)&sXl[r][lane * 4] =
            make_uint2(pk2(lores(y0), lores(y1)), pk2(lores(y2), lores(y3)));
    }
    __syncthreads();

    if (warp < 4) {
        int gid  = lane >> 2, tg = lane & 3;
        float acc[2][4] = {};
        int warp_m = warp * 16;
        unsigned aXh = cvta_s(sXh), aXl = cvta_s(sXl);
        unsigned aWh = cvta_s(sWh), aWl = cvta_s(sWl);
        int fr = lane & 15, fc = lane >> 4;
#pragma unroll
        for (int c = 0; c < 8; c++) {
            int kk = c * 16;
            unsigned ah[4], al[4], bh[4], bl[4];
            LDSM4(ah, aXh + ((warp_m + fr) * 136 + kk + fc * 8) * 2);
            LDSM4(al, aXl + ((warp_m + fr) * 136 + kk + fc * 8) * 2);
            LDSM4(bh, aWh + ((fr) * 136 + kk + fc * 8) * 2);
            LDSM4(bl, aWl + ((fr) * 136 + kk + fc * 8) * 2);
#pragma unroll
            for (int t = 0; t < 2; t++)
                MMA_BF16v(acc[t], ah, bh[t], bh[t + 2]);
#pragma unroll
            for (int t = 0; t < 2; t++)
                MMA_BF16v(acc[t], ah, bl[t], bl[t + 2]);
#pragma unroll
            for (int t = 0; t < 2; t++)
                MMA_BF16v(acc[t], al, bh[t], bh[t + 2]);
        }
#pragma unroll
        for (int t = 0; t < 2; t++) {
            int hc = t * 8 + tg * 2;
            int r  = warp_m + gid;
            stage[hc][r]         = acc[t][0];
            stage[hc + 1][r]     = acc[t][1];
            stage[hc][r + 8]     = acc[t][2];
            stage[hc + 1][r + 8] = acc[t][3];
        }
    }
    __syncthreads();
    size_t obase = (size_t)i * 1024 + j0;
    for (int e = tid; e < 1024; e += 256) {
        int hh = e >> 6, j = e & 63;
        g_bias[(size_t)hh * NN + obase + j] = stage[hh][j] + sbin[hh];
    }
}

// ---------------------------------------------------------------------------
// Convert: single -> fp16 hi only; weights -> fp16 hi/lo.
// ---------------------------------------------------------------------------
__global__ __launch_bounds__(256) void conv_all(
    const float* __restrict__ s0, const float* __restrict__ s1,
    const float* __restrict__ s2, const float* __restrict__ s3,
    const float* __restrict__ s4, const float* __restrict__ s5)
{
    const float* srcs[6] = {s0, s1, s2, s3, s4, s5};
    const float* src = srcs[blockIdx.y];
    unsigned i = blockIdx.x * 256u + threadIdx.x;
    float4 v = ((const float4*)src)[i];
    if (blockIdx.y == 0) {
        *(unsigned*)(g_sh + 4u*i)     = pkh2(v.x, v.y);
        *(unsigned*)(g_sh + 4u*i + 2) = pkh2(v.z, v.w);
    } else {
        __half* Dh = g_wfh[blockIdx.y - 1];
        __half* Dl = g_wfl[blockIdx.y - 1];
        *(unsigned*)(Dh + 4u*i)     = pkh2(v.x, v.y);
        *(unsigned*)(Dh + 4u*i + 2) = pkh2(v.z, v.w);
        *(unsigned*)(Dl + 4u*i)     = pkh2(loresh(v.x), loresh(v.y));
        *(unsigned*)(Dl + 4u*i + 2) = pkh2(loresh(v.z), loresh(v.w));
    }
}

// ---------------------------------------------------------------------------
// QKVG GEMM: fp16 2-pass (A=hi only, B=hi+lo). 512 thr, tile 128x256, BK=32,
// depth-3 pipeline, one barrier/chunk. Grid (4, 8, 4) = 128 CTAs.
// ---------------------------------------------------------------------------
__global__ __launch_bounds__(512, 1) void gemm_qkvg(const float* __restrict__ aux)
{
    extern __shared__ __half dsm[];
    constexpr unsigned SZB   = 16896u;   // 32 * 264 * 2
    constexpr unsigned BUFSZ = 44032u;

    int widx = blockIdx.z;
    float scale = (widx == 0) ? 0.125f : 1.0f;
    const __half* gBh = g_wfh[widx];
    const __half* gBl = g_wfl[widx];

    int tid  = threadIdx.x;
    int lane = tid & 31, warp = tid >> 5;
    int gid  = lane >> 2, tg = lane & 3;
    int fr = lane & 15, fc8 = (lane >> 4) * 8;
    int vr = (lane >> 4) * 8 + (lane & 7);
    int vc8 = ((lane >> 3) & 1) * 8;
    int warp_m = (warp >> 2) * 32, warp_n = (warp & 3) * 64;
    int m0 = blockIdx.y * 128, n0 = blockIdx.x * 256;
    unsigned sb = cvta_s(dsm);

    int a_row = (tid & 511) >> 2, a_seg = tid & 3;
    int b_row = (tid & 1023) >> 5, b_seg = tid & 31;

    const __half* pA   = g_sh + (size_t)(m0 + a_row) * 1024 + a_seg * 8;
    const __half* pBh0 = gBh + (size_t)b_row * 1024 + n0 + b_seg * 8;
    const __half* pBl0 = gBl + (size_t)b_row * 1024 + n0 + b_seg * 8;
    const __half* pBh1 = pBh0 + 16 * 1024;
    const __half* pBl1 = pBl0 + 16 * 1024;
    unsigned dA  = a_row * 80u + a_seg * 16u;
    unsigned dB0 = 10240u + b_row * 528u + b_seg * 16u;
    unsigned dB1 = 10240u + (b_row + 16) * 528u + b_seg * 16u;

    auto issue = [&](int ch, int buf) {
        unsigned k0 = ch * 32u;
        size_t kq = ch * 32u * 1024u;
        unsigned bo = sb + buf * BUFSZ;
        CP_ASYNC16(bo + dA,        pA + k0);
        CP_ASYNC16(bo + dB0,       pBh0 + kq);
        CP_ASYNC16(bo + dB0 + SZB, pBl0 + kq);
        CP_ASYNC16(bo + dB1,       pBh1 + kq);
        CP_ASYNC16(bo + dB1 + SZB, pBl1 + kq);
        CP_COMMIT();
    };

    float acc[2][8][4];
#pragma unroll
    for (int a = 0; a < 2; a++)
#pragma unroll
        for (int b = 0; b < 8; b++)
#pragma unroll
            for (int q = 0; q < 4; q++) acc[a][b][q] = 0.f;

    issue(0, 0);
    issue(1, 1);

    int buf = 0;
#pragma unroll 1
    for (int ch = 0; ch < 32; ch++) {
        if (ch < 31) { CP_WAIT1(); } else { CP_WAIT0(); }
        __syncthreads();
        unsigned base = sb + buf * BUFSZ;
#pragma unroll
        for (int k16 = 0; k16 < 32; k16 += 16) {
            unsigned a_h[2][4], b_h[4][4], b_l[4][4];
#pragma unroll
            for (int mt = 0; mt < 2; mt++) {
                unsigned off = base + ((warp_m + mt * 16 + fr) * 40 + k16 + fc8) * 2;
                LDSM4(a_h[mt], off);
            }
#pragma unroll
            for (int tp = 0; tp < 4; tp++) {
                unsigned off = base + 10240u
                    + ((k16 + vr) * 264 + warp_n + tp * 16 + vc8) * 2;
                LDSM4T(b_h[tp], off);
                LDSM4T(b_l[tp], off + SZB);
            }
#pragma unroll
            for (int mt = 0; mt < 2; mt++)
#pragma unroll
                for (int tp = 0; tp < 4; tp++)
#pragma unroll
                    for (int u = 0; u < 2; u++)
                        MMA_F16v(acc[mt][tp * 2 + u], a_h[mt],
                                 b_h[tp][u], b_h[tp][u + 2]);
#pragma unroll
            for (int mt = 0; mt < 2; mt++)
#pragma unroll
                for (int tp = 0; tp < 4; tp++)
#pragma unroll
                    for (int u = 0; u < 2; u++)
                        MMA_F16v(acc[mt][tp * 2 + u], a_h[mt],
                                 b_l[tp][u], b_l[tp][u + 2]);
        }
        if (ch + 2 < 32) {
            int nb = buf + 2; if (nb >= 3) nb -= 3;
            issue(ch + 2, nb);
        }
        if (++buf == 3) buf = 0;
    }

    // epilogue: Q -> fp16 hi only; K,V -> fp16 hi/lo; gates -> fp32 sigmoid
#pragma unroll
    for (int mt = 0; mt < 2; mt++) {
#pragma unroll
        for (int j = 0; j < 8; j++) {
            int rg = m0 + warp_m + mt * 16 + gid;
            int cg = n0 + warp_n + j * 8 + tg * 2;
            float* a4 = acc[mt][j];
            if (widx == 3) {
                float b0 = aux[cg], b1 = aux[cg + 1];
                float v0 = 1.f / (1.f + __expf(-(a4[0] + b0)));
                float v1 = 1.f / (1.f + __expf(-(a4[1] + b1)));
                float v2 = 1.f / (1.f + __expf(-(a4[2] + b0)));
                float v3 = 1.f / (1.f + __expf(-(a4[3] + b1)));
                *(float2*)&g_g[(size_t)rg * 1024 + cg]       = make_float2(v0, v1);
                *(float2*)&g_g[(size_t)(rg + 8) * 1024 + cg] = make_float2(v2, v3);
            } else if (widx == 0) {
                float v0 = a4[0] * scale, v1 = a4[1] * scale;
                float v2 = a4[2] * scale, v3 = a4[3] * scale;
                *(unsigned*)&g_qf[(size_t)rg * 1024 + cg]       = pkh2(v0, v1);
                *(unsigned*)&g_qf[(size_t)(rg + 8) * 1024 + cg] = pkh2(v2, v3);
            } else {
                __half* Dh = (widx == 1) ? g_kfh : g_vfh;
                __half* Dl = (widx == 1) ? g_kfl : g_vfl;
                float v0 = a4[0], v1 = a4[1], v2 = a4[2], v3 = a4[3];
                *(unsigned*)&Dh[(size_t)rg * 1024 + cg]       = pkh2(v0, v1);
                *(unsigned*)&Dh[(size_t)(rg + 8) * 1024 + cg] = pkh2(v2, v3);
                *(unsigned*)&Dl[(size_t)rg * 1024 + cg]       =
                    pkh2(loresh(v0), loresh(v1));
                *(unsigned*)&Dl[(size_t)(rg + 8) * 1024 + cg] =
                    pkh2(loresh(v2), loresh(v3));
            }
        }
    }
}

// ---------------------------------------------------------------------------
// Output GEMM: fp16 2-pass. 256 thr, 128x64 tile, BK=32, depth-3. Grid (16,8).
// ---------------------------------------------------------------------------
__global__ __launch_bounds__(256) void gemm_out(float* __restrict__ Cext)
{
    extern __shared__ __half dsm[];
    constexpr unsigned SZB   = 32u * 72 * 2;          // 4608
    constexpr unsigned BUFSZ = 10240u + 2 * SZB;      // 19456

    const __half* gBh = g_wfh[4];
    const __half* gBl = g_wfl[4];

    int tid  = threadIdx.x;
    int lane = tid & 31, warp = tid >> 5;
    int gid  = lane >> 2, tg = lane & 3;
    int fr = lane & 15, fc8 = (lane >> 4) * 8;
    int vr = (lane >> 4) * 8 + (lane & 7);
    int vc8 = ((lane >> 3) & 1) * 8;
    int warp_m = (warp >> 1) * 32, warp_n = (warp & 1) * 32;
    int m0 = blockIdx.y * 128, n0 = blockIdx.x * 64;
    unsigned sb = cvta_s(dsm);

    auto issue = [&](int ch, int buf) {
        int k0 = ch * 32;
        unsigned bo = sb + buf * BUFSZ;
#pragma unroll
        for (int t = 0; t < 4; t++) {
            int s = tid + t * 256;
            unsigned dst;
            const __half* src;
            if (s < 512) {
                int row = s >> 2, seg = s & 3;
                dst = bo + row * 80u + seg * 16u;
                src = g_oh + (size_t)(m0 + row) * 1024 + k0 + seg * 8;
            } else {
                int ss = s - 512;
                int mt = ss >> 8, rem = ss & 255;
                int row = rem >> 3, seg = rem & 7;
                dst = bo + 10240u + mt * SZB + row * 144u + seg * 16u;
                src = (mt ? gBl : gBh) + (size_t)(k0 + row) * 1024 + n0 + seg * 8;
            }
            CP_ASYNC16(dst, src);
        }
        CP_COMMIT();
    };

    float acc[2][4][4];
#pragma unroll
    for (int a = 0; a < 2; a++)
#pragma unroll
        for (int b = 0; b < 4; b++)
#pragma unroll
            for (int q = 0; q < 4; q++) acc[a][b][q] = 0.f;

    issue(0, 0);
    issue(1, 1);

    int buf = 0;
#pragma unroll 1
    for (int ch = 0; ch < 32; ch++) {
        if (ch < 31) { CP_WAIT1(); } else { CP_WAIT0(); }
        __syncthreads();
        unsigned base = sb + buf * BUFSZ;
#pragma unroll
        for (int k16 = 0; k16 < 32; k16 += 16) {
            unsigned a_h[2][4], b_h[2][4], b_l[2][4];
#pragma unroll
            for (int mt = 0; mt < 2; mt++) {
                unsigned off = base + ((warp_m + mt * 16 + fr) * 40 + k16 + fc8) * 2;
                LDSM4(a_h[mt], off);
            }
#pragma unroll
            for (int tp = 0; tp < 2; tp++) {
                unsigned off = base + 10240u
                    + ((k16 + vr) * 72 + warp_n + tp * 16 + vc8) * 2;
                LDSM4T(b_h[tp], off);
                LDSM4T(b_l[tp], off + SZB);
            }
#pragma unroll
            for (int mt = 0; mt < 2; mt++)
#pragma unroll
                for (int tp = 0; tp < 2; tp++)
#pragma unroll
                    for (int u = 0; u < 2; u++)
                        MMA_F16v(acc[mt][tp * 2 + u], a_h[mt],
                                 b_h[tp][u], b_h[tp][u + 2]);
#pragma unroll
            for (int mt = 0; mt < 2; mt++)
#pragma unroll
                for (int tp = 0; tp < 2; tp++)
#pragma unroll
                    for (int u = 0; u < 2; u++)
                        MMA_F16v(acc[mt][tp * 2 + u], a_h[mt],
                                 b_l[tp][u], b_l[tp][u + 2]);
        }
        if (ch + 2 < 32) {
            int nb = buf + 2; if (nb >= 3) nb -= 3;
            issue(ch + 2, nb);
        }
        if (++buf == 3) buf = 0;
    }

#pragma unroll
    for (int mt = 0; mt < 2; mt++) {
#pragma unroll
        for (int j = 0; j < 4; j++) {
            int rg = m0 + warp_m + mt * 16 + gid;
            int cg = n0 + warp_n + j * 8 + tg * 2;
            float* a4 = acc[mt][j];
            *(float2*)&Cext[(size_t)rg * 1024 + cg]       = make_float2(a4[0], a4[1]);
            *(float2*)&Cext[(size_t)(rg + 8) * 1024 + cg] = make_float2(a4[2], a4[3]);
        }
    }
}

// ---------------------------------------------------------------------------
// Flash attention, fp16 2-pass: S = Qh (Kh + Kl),  O += Ph (Vh + Vl).
// depth-3 K/V pipeline, 256 thr, 128 queries/CTA. Grid (8, 16).
// ---------------------------------------------------------------------------
__global__ __launch_bounds__(256) void attn_kernel()
{
    extern __shared__ __half dsmh[];
    int tid  = threadIdx.x;
    int lane = tid & 31, warp = tid >> 5;
    int gid  = lane >> 2, tg = lane & 3;
    int h  = blockIdx.y;
    int q0 = blockIdx.x * 128;
    int warp_m = warp * 16;
    int qrow = q0 + warp_m + gid;
    unsigned sb = cvta_s(dsmh);

    int fr = lane & 15, fc8 = (lane >> 4) * 8;
    int vr = (lane >> 4) * 8 + (lane & 7);
    int vc8 = ((lane >> 3) & 1) * 8;

    auto issue_kv = [&](int kb, int buf) {
        int k0 = kb * 64;
        unsigned bo = buf * 36864u;
#pragma unroll
        for (int t = 0; t < 8; t++) {
            int s = tid + t * 256;
            int mt = s >> 9, rem = s & 511;
            int row = rem >> 3, seg = rem & 7;
            unsigned dst = sb + bo + mt * 9216u + row * 144u + seg * 16u;
            const __half* src;
            if      (mt == 0) src = g_kfh + (size_t)(k0 + row) * 1024 + h * 64 + seg * 8;
            else if (mt == 1) src = g_kfl + (size_t)(k0 + row) * 1024 + h * 64 + seg * 8;
            else if (mt == 2) src = g_vfh + (size_t)(k0 + row) * 1024 + h * 64 + seg * 8;
            else              src = g_vfl + (size_t)(k0 + row) * 1024 + h * 64 + seg * 8;
            CP_ASYNC16(dst, src);
        }
        CP_COMMIT();
    };

    unsigned qh[4][4];
    {
        const __half* Qf = g_qf + (size_t)qrow * 1024 + h * 64;
#pragma unroll
        for (int c = 0; c < 4; c++) {
            int kk = c * 16 + tg * 2;
            qh[c][0] = *(const unsigned*)(Qf + kk);
            qh[c][1] = *(const unsigned*)(Qf + 8 * 1024 + kk);
            qh[c][2] = *(const unsigned*)(Qf + kk + 8);
            qh[c][3] = *(const unsigned*)(Qf + 8 * 1024 + kk + 8);
        }
    }

    float m0 = -1e30f, m1 = -1e30f, l0 = 0.f, l1 = 0.f;
    float O[8][4] = {};

    issue_kv(0, 0);
    issue_kv(1, 1);

    int buf = 0;
#pragma unroll 1
    for (int kb = 0; kb < 16; kb++) {
        if (kb < 15) { CP_WAIT1(); } else { CP_WAIT0(); }
        __syncthreads();
        unsigned base = sb + buf * 36864u;
        int k0 = kb * 64;

        float S[8][4];
        {
            const float* bptr = g_bias + (size_t)h * NN + (size_t)qrow * 1024 + k0;
#pragma unroll
            for (int t = 0; t < 8; t++) {
                float2 b0 = *(const float2*)(bptr + 8 * t + 2 * tg);
                float2 b1 = *(const float2*)(bptr + 8 * 1024 + 8 * t + 2 * tg);
                S[t][0] = b0.x; S[t][1] = b0.y; S[t][2] = b1.x; S[t][3] = b1.y;
            }
        }
        // S += Q (Kh + Kl)  (2-pass fp16, tp-pairs)
#pragma unroll
        for (int c = 0; c < 4; c++) {
            int kk = c * 16;
#pragma unroll
            for (int tpp = 0; tpp < 4; tpp += 2) {
                unsigned bh[2][4], bl[2][4];
#pragma unroll
                for (int j = 0; j < 2; j++) {
                    unsigned off = base + (((tpp + j) * 16 + fr) * 72 + kk + fc8) * 2;
                    LDSM4(bh[j], off);
                    LDSM4(bl[j], off + 9216u);
                }
#pragma unroll
                for (int j = 0; j < 2; j++)
#pragma unroll
                    for (int u = 0; u < 2; u++)
                        MMA_F16v(S[(tpp + j) * 2 + u], qh[c],
                                 bh[j][u], bh[j][u + 2]);
#pragma unroll
                for (int j = 0; j < 2; j++)
#pragma unroll
                    for (int u = 0; u < 2; u++)
                        MMA_F16v(S[(tpp + j) * 2 + u], qh[c],
                                 bl[j][u], bl[j][u + 2]);
            }
        }

        float rm0 = -1e30f, rm1 = -1e30f;
#pragma unroll
        for (int t = 0; t < 8; t++) {
            rm0 = fmaxf(rm0, fmaxf(S[t][0], S[t][1]));
            rm1 = fmaxf(rm1, fmaxf(S[t][2], S[t][3]));
        }
        rm0 = fmaxf(rm0, __shfl_xor_sync(0xffffffffu, rm0, 1));
        rm0 = fmaxf(rm0, __shfl_xor_sync(0xffffffffu, rm0, 2));
        rm1 = fmaxf(rm1, __shfl_xor_sync(0xffffffffu, rm1, 1));
        rm1 = fmaxf(rm1, __shfl_xor_sync(0xffffffffu, rm1, 2));
        float mn0 = fmaxf(m0, rm0), mn1 = fmaxf(m1, rm1);
        float c0 = __expf(m0 - mn0), c1 = __expf(m1 - mn1);
        m0 = mn0; m1 = mn1;
        float ps0 = 0.f, ps1 = 0.f;
#pragma unroll
        for (int t = 0; t < 8; t++) {
            S[t][0] = __expf(S[t][0] - mn0);
            S[t][1] = __expf(S[t][1] - mn0);
            S[t][2] = __expf(S[t][2] - mn1);
            S[t][3] = __expf(S[t][3] - mn1);
            ps0 += S[t][0] + S[t][1];
            ps1 += S[t][2] + S[t][3];
        }
        ps0 += __shfl_xor_sync(0xffffffffu, ps0, 1);
        ps0 += __shfl_xor_sync(0xffffffffu, ps0, 2);
        ps1 += __shfl_xor_sync(0xffffffffu, ps1, 1);
        ps1 += __shfl_xor_sync(0xffffffffu, ps1, 2);
        l0 = l0 * c0 + ps0;
        l1 = l1 * c1 + ps1;
#pragma unroll
        for (int t = 0; t < 8; t++) {
            O[t][0] *= c0; O[t][1] *= c0; O[t][2] *= c1; O[t][3] *= c1;
        }

        unsigned ph[4][4];
#pragma unroll
        for (int c = 0; c < 4; c++) {
            int t0 = 2 * c, t1 = 2 * c + 1;
            ph[c][0] = pkh2(S[t0][0], S[t0][1]);
            ph[c][1] = pkh2(S[t0][2], S[t0][3]);
            ph[c][2] = pkh2(S[t1][0], S[t1][1]);
            ph[c][3] = pkh2(S[t1][2], S[t1][3]);
        }

        // O += P (Vh + Vl)  (2-pass fp16, tp-pairs)
#pragma unroll
        for (int c = 0; c < 4; c++) {
#pragma unroll
            for (int tpp = 0; tpp < 4; tpp += 2) {
                unsigned bh[2][4], bl[2][4];
#pragma unroll
                for (int j = 0; j < 2; j++) {
                    unsigned off = base + 18432u
                        + ((c * 16 + vr) * 72 + (tpp + j) * 16 + vc8) * 2;
                    LDSM4T(bh[j], off);
                    LDSM4T(bl[j], off + 9216u);
                }
#pragma unroll
                for (int j = 0; j < 2; j++)
#pragma unroll
                    for (int u = 0; u < 2; u++)
                        MMA_F16v(O[(tpp + j) * 2 + u], ph[c],
                                 bh[j][u], bh[j][u + 2]);
#pragma unroll
                for (int j = 0; j < 2; j++)
#pragma unroll
                    for (int u = 0; u < 2; u++)
                        MMA_F16v(O[(tpp + j) * 2 + u], ph[c],
                                 bl[j][u], bl[j][u + 2]);
            }
        }
        if (kb + 2 < 16) {
            int nb = buf + 2; if (nb >= 3) nb -= 3;
            issue_kv(kb + 2, nb);
        }
        if (++buf == 3) buf = 0;
    }

    float inv0 = 1.f / l0, inv1 = 1.f / l1;
#pragma unroll
    for (int t = 0; t < 8; t++) {
        int col = h * 64 + 8 * t + 2 * tg;
        size_t o0 = (size_t)qrow * 1024 + col;
        size_t o1 = o0 + 8 * 1024;
        float2 gg0 = *(const float2*)(g_g + o0);
        float2 gg1 = *(const float2*)(g_g + o1);
        float v0 = O[t][0] * inv0 * gg0.x;
        float v1 = O[t][1] * inv0 * gg0.y;
        float v2 = O[t][2] * inv1 * gg1.x;
        float v3 = O[t][3] * inv1 * gg1.y;
        *(unsigned*)(g_oh + o0) = pkh2(v0, v1);
        *(unsigned*)(g_oh + o1) = pkh2(v2, v3);
    }
}

// ---------------------------------------------------------------------------
extern "C" void kernel_launch(void* const* d_in, const int* in_sizes, int n_in,
                              void* d_out, int out_size)
{
    const float* single = (const float*)d_in[0];
    const float* pw     = (const float*)d_in[1];
    const float* gamma  = (const float*)d_in[2];
    const float* beta   = (const float*)d_in[3];
    const float* Wb     = (const float*)d_in[4];
    const float* Wq     = (const float*)d_in[5];
    const float* Wk     = (const float*)d_in[6];
    const float* Wv     = (const float*)d_in[7];
    const float* Wg     = (const float*)d_in[8];
    const float* bg     = (const float*)d_in[9];
    const float* Wo     = (const float*)d_in[10];
    float* out = (float*)d_out;

    const int QKVG_SMEM = 3 * 44032;   // 132096
    const int OUT_SMEM  = 3 * 19456;   // 58368
    const int ATTN_SMEM = 3 * 36864;   // 110592
    cudaFuncSetAttribute(gemm_qkvg,
        cudaFuncAttributeMaxDynamicSharedMemorySize, QKVG_SMEM);
    cudaFuncSetAttribute(gemm_out,
        cudaFuncAttributeMaxDynamicSharedMemorySize, OUT_SMEM);
    cudaFuncSetAttribute(attn_kernel,
        cudaFuncAttributeMaxDynamicSharedMemorySize, ATTN_SMEM);

    // Fork-join: bias chain (HBM-bound) runs concurrently with the
    // conversion + QKVG GEMM chain (compute-bound). Host-side stream/event
    // objects only (no device allocations); kernel_launch runs only for the
    // correctness call + the capture call, so creating them per call is fine.
    cudaStream_t s1;
    cudaStreamCreateWithFlags(&s1, cudaStreamNonBlocking);
    cudaEvent_t ef, ej;
    cudaEventCreateWithFlags(&ef, cudaEventDisableTiming);
    cudaEventCreateWithFlags(&ej, cudaEventDisableTiming);

    cudaEventRecord(ef, 0);
    cudaStreamWaitEvent(s1, ef, 0);

    // side stream: pair-bias pipeline
    bias_setup<<<1, 128, 0, s1>>>(gamma, beta, Wb);
    dim3 bgrid(16, 1024);
    bias_kernel<<<bgrid, 256, 0, s1>>>(pw);

    // main stream: conversions + QKVG projections
    dim3 cgrid(1024, 6);
    conv_all<<<cgrid, 256>>>(single, Wq, Wk, Wv, Wg, Wo);
    dim3 ggrid(4, 8, 4);   // 128 CTAs
    gemm_qkvg<<<ggrid, 512, QKVG_SMEM>>>(bg);

    // join: attention needs bias + QKV + gates
    cudaEventRecord(ej, s1);
    cudaStreamWaitEvent(0, ej, 0);

    dim3 agrid(8, 16);
    attn_kernel<<<agrid, 256, ATTN_SMEM>>>();

    dim3 ogrid(16, 8);     // 128 CTAs
    gemm_out<<<ogrid, 256, OUT_SMEM>>>(out);
}